// round 3
// baseline (speedup 1.0000x reference)
#include <cuda_runtime.h>
#include <math.h>

#define N_NODES 25000
#define N_EDGES 200000
#define HID     128
#define N_GRAPHS 64
#define DEPTH   5
#define NODE_F  16

// Scratch (static device globals; no allocation allowed)
__device__ float g_h[N_NODES * HID];
__device__ float g_agg[N_NODES * HID];
__device__ float g_dist[N_EDGES];
__device__ float g_pool[N_GRAPHS * HID];

// ---------------------------------------------------------------------------
__global__ void dist_kernel(const float* __restrict__ pos, const int* __restrict__ ei) {
    int e = blockIdx.x * blockDim.x + threadIdx.x;
    if (e >= N_EDGES) return;
    int s = ei[e];
    int d = ei[N_EDGES + e];
    float dx = pos[d * 3 + 0] - pos[s * 3 + 0];
    float dy = pos[d * 3 + 1] - pos[s * 3 + 1];
    float dz = pos[d * 3 + 2] - pos[s * 3 + 2];
    g_dist[e] = sqrtf(dx * dx + dy * dy + dz * dz);
}

// h = x @ emb_W + emb_b   (one node per block, 128 threads)
__global__ void embed_kernel(const float* __restrict__ x,
                             const float* __restrict__ W,
                             const float* __restrict__ b) {
    int n = blockIdx.x;
    int t = threadIdx.x;
    float acc = b[t];
#pragma unroll
    for (int k = 0; k < NODE_F; k++)
        acc = fmaf(x[n * NODE_F + k], W[k * HID + t], acc);
    g_h[n * HID + t] = acc;
}

__global__ void zero_agg_kernel() {
    int i = blockIdx.x * blockDim.x + threadIdx.x;
    if (i < N_NODES * HID) g_agg[i] = 0.f;
}
__global__ void zero_pool_kernel() {
    int i = blockIdx.x * blockDim.x + threadIdx.x;
    if (i < N_GRAPHS * HID) g_pool[i] = 0.f;
}

// ---------------------------------------------------------------------------
// Block-wide LayerNorm(+affine)+ReLU over the 128-column dimension.
// acc[EPB] lives per-thread (thread t holds column t for EPB rows).
// Result written to sOut[e][t] (stride 132). Ends with __syncthreads().
template <int EPB>
__device__ __forceinline__ void ln_relu_to_smem(float* acc,
                                                const float* __restrict__ g,
                                                const float* __restrict__ be,
                                                float (*sOut)[132],
                                                float (*sRed)[4][2],
                                                float (*sMV)[2],
                                                int tid) {
    int lane = tid & 31, warp = tid >> 5;
#pragma unroll
    for (int e = 0; e < EPB; e++) {
        float s = acc[e], s2 = acc[e] * acc[e];
#pragma unroll
        for (int o = 16; o > 0; o >>= 1) {
            s  += __shfl_xor_sync(0xffffffffu, s, o);
            s2 += __shfl_xor_sync(0xffffffffu, s2, o);
        }
        if (lane == 0) { sRed[e][warp][0] = s; sRed[e][warp][1] = s2; }
    }
    __syncthreads();
    if (tid < EPB) {
        float s = 0.f, s2 = 0.f;
#pragma unroll
        for (int w = 0; w < 4; w++) { s += sRed[tid][w][0]; s2 += sRed[tid][w][1]; }
        float mean = s * (1.0f / HID);
        float var  = s2 * (1.0f / HID) - mean * mean;
        var = fmaxf(var, 0.f);
        sMV[tid][0] = mean;
        sMV[tid][1] = rsqrtf(var + 1e-5f);
    }
    __syncthreads();
    float gg = g[tid], bb = be[tid];
#pragma unroll
    for (int e = 0; e < EPB; e++) {
        float v = fmaf((acc[e] - sMV[e][0]) * sMV[e][1], gg, bb);
        sOut[e][tid] = fmaxf(v, 0.f);
    }
    __syncthreads();
}

// ---------------------------------------------------------------------------
// Edge message kernel: 16 edges per block, 128 threads (thread = out column).
// m = relu(LN([h_dst, h_src, dist] @ W1 + b1)); m = relu(LN(m @ W2 + b2));
// agg[dst] += m  (atomic).
#define EPB_MSG 16
__global__ __launch_bounds__(128) void msg_kernel(
    const int* __restrict__ ei,
    const float* __restrict__ W1, const float* __restrict__ b1,
    const float* __restrict__ g1, const float* __restrict__ be1,
    const float* __restrict__ W2, const float* __restrict__ b2,
    const float* __restrict__ g2, const float* __restrict__ be2) {
    __shared__ __align__(16) float sIn[EPB_MSG][260];
    __shared__ __align__(16) float sM[EPB_MSG][132];
    __shared__ float sRed[EPB_MSG][4][2];
    __shared__ float sMV[EPB_MSG][2];
    __shared__ int sSrc[EPB_MSG], sDst[EPB_MSG];

    int tid = threadIdx.x;
    int e0 = blockIdx.x * EPB_MSG;  // E = 200000 = 12500 * 16 exactly

    if (tid < EPB_MSG) {
        sSrc[tid] = ei[e0 + tid];
        sDst[tid] = ei[N_EDGES + e0 + tid];
    }
    __syncthreads();
#pragma unroll
    for (int e = 0; e < EPB_MSG; e++) {
        sIn[e][tid]       = g_h[sDst[e] * HID + tid];
        sIn[e][HID + tid] = g_h[sSrc[e] * HID + tid];
    }
    if (tid < EPB_MSG) sIn[tid][256] = g_dist[e0 + tid];
    __syncthreads();

    float acc[EPB_MSG];
    // ---- MLP1: 257 -> 128 ----
    {
        float bv = b1[tid];
#pragma unroll
        for (int e = 0; e < EPB_MSG; e++) acc[e] = bv;
        for (int k4 = 0; k4 < 64; k4++) {
            const float* wp = W1 + (k4 * 4) * HID + tid;
            float w0 = wp[0], w1 = wp[HID], w2 = wp[2 * HID], w3 = wp[3 * HID];
#pragma unroll
            for (int e = 0; e < EPB_MSG; e++) {
                float4 v = *(const float4*)&sIn[e][k4 * 4];
                acc[e] = fmaf(v.x, w0, fmaf(v.y, w1, fmaf(v.z, w2, fmaf(v.w, w3, acc[e]))));
            }
        }
        float wd = W1[256 * HID + tid];
#pragma unroll
        for (int e = 0; e < EPB_MSG; e++) acc[e] = fmaf(sIn[e][256], wd, acc[e]);
    }
    ln_relu_to_smem<EPB_MSG>(acc, g1, be1, sM, sRed, sMV, tid);

    // ---- MLP2: 128 -> 128 ----
    {
        float bv = b2[tid];
#pragma unroll
        for (int e = 0; e < EPB_MSG; e++) acc[e] = bv;
        for (int k4 = 0; k4 < 32; k4++) {
            const float* wp = W2 + (k4 * 4) * HID + tid;
            float w0 = wp[0], w1 = wp[HID], w2 = wp[2 * HID], w3 = wp[3 * HID];
#pragma unroll
            for (int e = 0; e < EPB_MSG; e++) {
                float4 v = *(const float4*)&sM[e][k4 * 4];
                acc[e] = fmaf(v.x, w0, fmaf(v.y, w1, fmaf(v.z, w2, fmaf(v.w, w3, acc[e]))));
            }
        }
    }
    ln_relu_to_smem<EPB_MSG>(acc, g2, be2, sM, sRed, sMV, tid);

#pragma unroll
    for (int e = 0; e < EPB_MSG; e++)
        atomicAdd(&g_agg[sDst[e] * HID + tid], sM[e][tid]);
}

// ---------------------------------------------------------------------------
// Node update kernel: 8 nodes per block.
// u = relu(LN([h, agg] @ W1 + b1)); u = relu(LN(u @ W2 + b2)); h += u.
#define NPB 8
__global__ __launch_bounds__(128) void upd_kernel(
    const float* __restrict__ W1, const float* __restrict__ b1,
    const float* __restrict__ g1, const float* __restrict__ be1,
    const float* __restrict__ W2, const float* __restrict__ b2,
    const float* __restrict__ g2, const float* __restrict__ be2) {
    __shared__ __align__(16) float sIn[NPB][256];
    __shared__ __align__(16) float sM[NPB][132];
    __shared__ float sRed[NPB][4][2];
    __shared__ float sMV[NPB][2];

    int tid = threadIdx.x;
    int n0 = blockIdx.x * NPB;  // 25000 = 3125 * 8 exactly

#pragma unroll
    for (int e = 0; e < NPB; e++) {
        sIn[e][tid]       = g_h[(n0 + e) * HID + tid];
        sIn[e][HID + tid] = g_agg[(n0 + e) * HID + tid];
    }
    __syncthreads();

    float acc[NPB];
    {
        float bv = b1[tid];
#pragma unroll
        for (int e = 0; e < NPB; e++) acc[e] = bv;
        for (int k4 = 0; k4 < 64; k4++) {
            const float* wp = W1 + (k4 * 4) * HID + tid;
            float w0 = wp[0], w1 = wp[HID], w2 = wp[2 * HID], w3 = wp[3 * HID];
#pragma unroll
            for (int e = 0; e < NPB; e++) {
                float4 v = *(const float4*)&sIn[e][k4 * 4];
                acc[e] = fmaf(v.x, w0, fmaf(v.y, w1, fmaf(v.z, w2, fmaf(v.w, w3, acc[e]))));
            }
        }
    }
    ln_relu_to_smem<NPB>(acc, g1, be1, sM, sRed, sMV, tid);
    {
        float bv = b2[tid];
#pragma unroll
        for (int e = 0; e < NPB; e++) acc[e] = bv;
        for (int k4 = 0; k4 < 32; k4++) {
            const float* wp = W2 + (k4 * 4) * HID + tid;
            float w0 = wp[0], w1 = wp[HID], w2 = wp[2 * HID], w3 = wp[3 * HID];
#pragma unroll
            for (int e = 0; e < NPB; e++) {
                float4 v = *(const float4*)&sM[e][k4 * 4];
                acc[e] = fmaf(v.x, w0, fmaf(v.y, w1, fmaf(v.z, w2, fmaf(v.w, w3, acc[e]))));
            }
        }
    }
    ln_relu_to_smem<NPB>(acc, g2, be2, sM, sRed, sMV, tid);

#pragma unroll
    for (int e = 0; e < NPB; e++)
        g_h[(n0 + e) * HID + tid] += sM[e][tid];
}

// ---------------------------------------------------------------------------
__global__ void pool_kernel(const int* __restrict__ batch) {
    int n = blockIdx.x;
    int t = threadIdx.x;
    atomicAdd(&g_pool[batch[n] * HID + t], g_h[n * HID + t]);
}

// out[g] = relu(pool[g] @ W1 + b1) @ W2 + b2
__global__ void pred_kernel(const float* __restrict__ W1, const float* __restrict__ b1,
                            const float* __restrict__ W2, const float* __restrict__ b2,
                            float* __restrict__ out) {
    __shared__ float sred[128];
    int g = blockIdx.x;
    int t = threadIdx.x;
    float acc = b1[t];
    for (int k = 0; k < HID; k++)
        acc = fmaf(g_pool[g * HID + k], W1[k * HID + t], acc);
    acc = fmaxf(acc, 0.f) * W2[t];
    sred[t] = acc;
    __syncthreads();
    for (int o = 64; o > 0; o >>= 1) {
        if (t < o) sred[t] += sred[t + o];
        __syncthreads();
    }
    if (t == 0) out[g] = sred[0] + b2[0];
}

// ---------------------------------------------------------------------------
extern "C" void kernel_launch(void* const* d_in, const int* in_sizes, int n_in,
                              void* d_out, int out_size) {
    const float* x     = (const float*)d_in[0];
    const float* pos   = (const float*)d_in[1];
    const int*   ei    = (const int*)d_in[2];
    const int*   batch = (const int*)d_in[3];
    const float* emb_W = (const float*)d_in[4];
    const float* emb_b = (const float*)d_in[5];

    const float *mW1, *mb1, *mg1, *mbe1, *mW2, *mb2, *mg2, *mbe2;
    const float *uW1, *ub1, *ug1, *ube1, *uW2, *ub2, *ug2, *ube2;

    if (in_sizes[8] == 81920) {
        // setup_inputs dict-insertion order: W1,b1,W2,b2 (msg), W1,b1,W2,b2 (upd), then g/be
        mW1  = (const float*)d_in[6];  mb1  = (const float*)d_in[7];
        mW2  = (const float*)d_in[8];  mb2  = (const float*)d_in[9];
        uW1  = (const float*)d_in[10]; ub1  = (const float*)d_in[11];
        uW2  = (const float*)d_in[12]; ub2  = (const float*)d_in[13];
        mg1  = (const float*)d_in[14]; mbe1 = (const float*)d_in[15];
        mg2  = (const float*)d_in[16]; mbe2 = (const float*)d_in[17];
        ug1  = (const float*)d_in[18]; ube1 = (const float*)d_in[19];
        ug2  = (const float*)d_in[20]; ube2 = (const float*)d_in[21];
    } else {
        // reference() signature order: g/be interleaved
        mW1  = (const float*)d_in[6];  mb1  = (const float*)d_in[7];
        mg1  = (const float*)d_in[8];  mbe1 = (const float*)d_in[9];
        mW2  = (const float*)d_in[10]; mb2  = (const float*)d_in[11];
        mg2  = (const float*)d_in[12]; mbe2 = (const float*)d_in[13];
        uW1  = (const float*)d_in[14]; ub1  = (const float*)d_in[15];
        ug1  = (const float*)d_in[16]; ube1 = (const float*)d_in[17];
        uW2  = (const float*)d_in[18]; ub2  = (const float*)d_in[19];
        ug2  = (const float*)d_in[20]; ube2 = (const float*)d_in[21];
    }
    const float* pW1 = (const float*)d_in[22];
    const float* pb1 = (const float*)d_in[23];
    const float* pW2 = (const float*)d_in[24];
    const float* pb2 = (const float*)d_in[25];
    float* out = (float*)d_out;

    dist_kernel<<<(N_EDGES + 255) / 256, 256>>>(pos, ei);
    embed_kernel<<<N_NODES, 128>>>(x, emb_W, emb_b);

    for (int l = 0; l < DEPTH; l++) {
        zero_agg_kernel<<<(N_NODES * HID + 255) / 256, 256>>>();
        msg_kernel<<<N_EDGES / EPB_MSG, 128>>>(
            ei,
            mW1 + l * 257 * HID, mb1 + l * HID, mg1 + l * HID, mbe1 + l * HID,
            mW2 + l * HID * HID, mb2 + l * HID, mg2 + l * HID, mbe2 + l * HID);
        upd_kernel<<<N_NODES / NPB, 128>>>(
            uW1 + l * 256 * HID, ub1 + l * HID, ug1 + l * HID, ube1 + l * HID,
            uW2 + l * HID * HID, ub2 + l * HID, ug2 + l * HID, ube2 + l * HID);
    }

    zero_pool_kernel<<<(N_GRAPHS * HID + 255) / 256, 256>>>();
    pool_kernel<<<N_NODES, 128>>>(batch);
    pred_kernel<<<N_GRAPHS, 128>>>(pW1, pb1, pW2, pb2, out);
}

// round 5
// speedup vs baseline: 1.4208x; 1.4208x over previous
#include <cuda_runtime.h>
#include <math.h>

#define N_NODES 25000
#define N_EDGES 200000
#define HID     128
#define N_GRAPHS 64
#define DEPTH   5
#define NODE_F  16
#define EPB     32   // edges (or nodes) per block

typedef unsigned long long ull;

// Scratch (static device globals; no allocation allowed)
__device__ float g_h[N_NODES * HID];
__device__ float g_agg[N_NODES * HID];
__device__ float g_dist[N_EDGES];
__device__ float g_pool[N_GRAPHS * HID];

// Packed weights: Wp[k4][c][j] = W[4*k4+j][c]  (zero-padded past K)
__device__ float g_Wm1[DEPTH * 65 * 512];  // msg W1: K=257 -> K4=65
__device__ float g_Wm2[DEPTH * 32 * 512];  // msg W2: K=128 -> K4=32
__device__ float g_Wu1[DEPTH * 64 * 512];  // upd W1: K=256 -> K4=64
__device__ float g_Wu2[DEPTH * 32 * 512];  // upd W2: K=128 -> K4=32

// ---------------------------------------------------------------------------
__device__ __forceinline__ void fma2(ull& d, ull a, ull b) {
    asm("fma.rn.f32x2 %0, %1, %2, %0;" : "+l"(d) : "l"(a), "l"(b));
}
__device__ __forceinline__ float f2sum(ull v) {
    float lo, hi;
    asm("mov.b64 {%0, %1}, %2;" : "=f"(lo), "=f"(hi) : "l"(v));
    return lo + hi;
}

// ---------------------------------------------------------------------------
// Pack all DEPTH layers of one weight tensor into k4-packed layout.
__global__ void pack_w5(const float* __restrict__ W, float* __restrict__ Wp,
                        int K, int K4) {
    int idx = blockIdx.x * blockDim.x + threadIdx.x;
    int per_layer = K4 * 512;
    if (idx >= DEPTH * per_layer) return;
    int l = idx / per_layer;
    int r = idx - l * per_layer;
    int j = r & 3, c = (r >> 2) & 127, k4 = r >> 9;
    int k = k4 * 4 + j;
    Wp[idx] = (k < K) ? W[l * K * HID + k * HID + c] : 0.f;
}

// ---------------------------------------------------------------------------
__global__ void dist_kernel(const float* __restrict__ pos, const int* __restrict__ ei) {
    int e = blockIdx.x * blockDim.x + threadIdx.x;
    if (e >= N_EDGES) return;
    int s = ei[e];
    int d = ei[N_EDGES + e];
    float dx = pos[d * 3 + 0] - pos[s * 3 + 0];
    float dy = pos[d * 3 + 1] - pos[s * 3 + 1];
    float dz = pos[d * 3 + 2] - pos[s * 3 + 2];
    g_dist[e] = sqrtf(dx * dx + dy * dy + dz * dz);
}

__global__ void embed_kernel(const float* __restrict__ x,
                             const float* __restrict__ W,
                             const float* __restrict__ b) {
    int n = blockIdx.x;
    int t = threadIdx.x;
    float acc = b[t];
#pragma unroll
    for (int k = 0; k < NODE_F; k++)
        acc = fmaf(x[n * NODE_F + k], W[k * HID + t], acc);
    g_h[n * HID + t] = acc;
}

__global__ void zero_agg_kernel() {
    int i = blockIdx.x * blockDim.x + threadIdx.x;
    if (i < N_NODES * HID) g_agg[i] = 0.f;
}
__global__ void zero_pool_kernel() {
    int i = blockIdx.x * blockDim.x + threadIdx.x;
    if (i < N_GRAPHS * HID) g_pool[i] = 0.f;
}

// ---------------------------------------------------------------------------
// Packed-f32x2 MLP inner loop. Thread owns columns c2 and c2+64, 16 rows
// (its edge/node group). Partial sums packed as {k-even, k-odd}; cross-added
// at the end, bias included.
template <int K4, int STRIDE>
__device__ __forceinline__ void mlp2x(const float* __restrict__ sRow,
                                      const float* __restrict__ Wp, int c2,
                                      float m0[16], float m1[16],
                                      float bias0, float bias1) {
    ull a0[16], a1[16];
#pragma unroll
    for (int e = 0; e < 16; e++) { a0[e] = 0ull; a1[e] = 0ull; }
#pragma unroll 2
    for (int k4 = 0; k4 < K4; k4++) {
        ulonglong2 w0 = *(const ulonglong2*)(Wp + (k4 * 128 + c2) * 4);
        ulonglong2 w1 = *(const ulonglong2*)(Wp + (k4 * 128 + c2 + 64) * 4);
#pragma unroll
        for (int e = 0; e < 16; e++) {
            ulonglong2 v = *(const ulonglong2*)(sRow + e * STRIDE + k4 * 4);
            fma2(a0[e], v.x, w0.x);
            fma2(a0[e], v.y, w0.y);
            fma2(a1[e], v.x, w1.x);
            fma2(a1[e], v.y, w1.y);
        }
    }
#pragma unroll
    for (int e = 0; e < 16; e++) {
        m0[e] = f2sum(a0[e]) + bias0;
        m1[e] = f2sum(a1[e]) + bias1;
    }
}

// Block-wide LayerNorm(+affine)+ReLU over 128 cols; thread holds cols c2,
// c2+64 for 16 rows of its group. In-place on m0/m1.
__device__ __forceinline__ void ln_phase(float m0[16], float m1[16],
                                         const float* __restrict__ g,
                                         const float* __restrict__ be,
                                         float (*sRed)[2][2], float (*sMV)[2],
                                         int tid, int c2, int grp) {
    int lane = tid & 31;
    int wip = (tid >> 5) & 1;  // warp-in-pair
#pragma unroll
    for (int e = 0; e < 16; e++) {
        float s  = m0[e] + m1[e];
        float s2 = m0[e] * m0[e] + m1[e] * m1[e];
#pragma unroll
        for (int o = 16; o > 0; o >>= 1) {
            s  += __shfl_xor_sync(0xffffffffu, s, o);
            s2 += __shfl_xor_sync(0xffffffffu, s2, o);
        }
        if (lane == 0) { sRed[grp * 16 + e][wip][0] = s; sRed[grp * 16 + e][wip][1] = s2; }
    }
    __syncthreads();
    if (tid < EPB) {
        float s  = sRed[tid][0][0] + sRed[tid][1][0];
        float s2 = sRed[tid][0][1] + sRed[tid][1][1];
        float mean = s * (1.0f / HID);
        float var  = s2 * (1.0f / HID) - mean * mean;
        var = fmaxf(var, 0.f);
        sMV[tid][0] = mean;
        sMV[tid][1] = rsqrtf(var + 1e-5f);
    }
    __syncthreads();
    float ga = g[c2], gb = g[c2 + 64], ba = be[c2], bb = be[c2 + 64];
#pragma unroll
    for (int e = 0; e < 16; e++) {
        float mean = sMV[grp * 16 + e][0], r = sMV[grp * 16 + e][1];
        m0[e] = fmaxf(fmaf((m0[e] - mean) * r, ga, ba), 0.f);
        m1[e] = fmaxf(fmaf((m1[e] - mean) * r, gb, bb), 0.f);
    }
}

// ---------------------------------------------------------------------------
// Edge message kernel: 32 edges/block, 128 threads.
// thread: c2 = tid&63 -> cols {c2, c2+64}; grp = tid>>6 -> edges grp*16..+15
__global__ __launch_bounds__(128, 4) void msg_kernel(
    const int* __restrict__ ei,
    const float* __restrict__ Wp1, const float* __restrict__ b1,
    const float* __restrict__ g1, const float* __restrict__ be1,
    const float* __restrict__ Wp2, const float* __restrict__ b2,
    const float* __restrict__ g2, const float* __restrict__ be2) {
    __shared__ __align__(16) float sBuf[EPB * 260];  // MLP1 in (260) / MLP2 in (132, aliased)
    __shared__ float sRed[EPB][2][2];
    __shared__ float sMV[EPB][2];
    __shared__ int sSrc[EPB], sDst[EPB];

    int tid = threadIdx.x;
    int c2 = tid & 63;
    int grp = tid >> 6;
    int e0 = blockIdx.x * EPB;  // 200000 = 6250 * 32 exactly

    if (tid < EPB) {
        sSrc[tid] = ei[e0 + tid];
        sDst[tid] = ei[N_EDGES + e0 + tid];
        sBuf[tid * 260 + 256] = g_dist[e0 + tid];
        sBuf[tid * 260 + 257] = 0.f;
        sBuf[tid * 260 + 258] = 0.f;
        sBuf[tid * 260 + 259] = 0.f;
    }
    __syncthreads();
    // gather h_dst|h_src: half = tid>>6 (0 dst, 1 src), sub = edge parity,
    // q4 = float4 lane within the 128-float half. Fully coalesced, in-bounds.
    {
        int half = grp;
        int sub  = (tid >> 5) & 1;
        int q4   = (tid & 31) * 4;
#pragma unroll 4
        for (int e = 0; e < EPB; e += 2) {
            int ee = e + sub;
            int node = half ? sSrc[ee] : sDst[ee];
            float4 v = *(const float4*)&g_h[node * HID + q4];
            *(float4*)&sBuf[ee * 260 + half * 128 + q4] = v;
        }
    }
    __syncthreads();

    float m0[16], m1[16];
    // ---- MLP1: 257(+pad) -> 128 ----
    mlp2x<65, 260>(sBuf + grp * 16 * 260, Wp1, c2, m0, m1, b1[c2], b1[c2 + 64]);
    ln_phase(m0, m1, g1, be1, sRed, sMV, tid, c2, grp);
    // write LN output as MLP2 input (stride 132, aliases sBuf; all reads done)
#pragma unroll
    for (int e = 0; e < 16; e++) {
        sBuf[(grp * 16 + e) * 132 + c2]      = m0[e];
        sBuf[(grp * 16 + e) * 132 + c2 + 64] = m1[e];
    }
    __syncthreads();
    // ---- MLP2: 128 -> 128 ----
    mlp2x<32, 132>(sBuf + grp * 16 * 132, Wp2, c2, m0, m1, b2[c2], b2[c2 + 64]);
    ln_phase(m0, m1, g2, be2, sRed, sMV, tid, c2, grp);

#pragma unroll
    for (int e = 0; e < 16; e++) {
        int d = sDst[grp * 16 + e];
        atomicAdd(&g_agg[d * HID + c2],      m0[e]);
        atomicAdd(&g_agg[d * HID + c2 + 64], m1[e]);
    }
}

// ---------------------------------------------------------------------------
// Node update kernel: 32 nodes/block (tail guarded).
__global__ __launch_bounds__(128, 4) void upd_kernel(
    const float* __restrict__ Wp1, const float* __restrict__ b1,
    const float* __restrict__ g1, const float* __restrict__ be1,
    const float* __restrict__ Wp2, const float* __restrict__ b2,
    const float* __restrict__ g2, const float* __restrict__ be2) {
    __shared__ __align__(16) float sBuf[EPB * 260];
    __shared__ float sRed[EPB][2][2];
    __shared__ float sMV[EPB][2];

    int tid = threadIdx.x;
    int c2 = tid & 63;
    int grp = tid >> 6;
    int n0 = blockIdx.x * EPB;

    // gather [h | agg]: half = tid>>6 (0 h, 1 agg), sub = node parity,
    // q4 = float4 lane within the 128-float half.
    {
        int half = grp;
        int sub  = (tid >> 5) & 1;
        int q4   = (tid & 31) * 4;
        const float* srcp = half ? g_agg : g_h;
#pragma unroll 4
        for (int e = 0; e < EPB; e += 2) {
            int ee = e + sub;
            int n = n0 + ee;
            if (n >= N_NODES) n = N_NODES - 1;
            float4 v = *(const float4*)&srcp[n * HID + q4];
            *(float4*)&sBuf[ee * 260 + half * 128 + q4] = v;
        }
    }
    __syncthreads();

    float m0[16], m1[16];
    mlp2x<64, 260>(sBuf + grp * 16 * 260, Wp1, c2, m0, m1, b1[c2], b1[c2 + 64]);
    ln_phase(m0, m1, g1, be1, sRed, sMV, tid, c2, grp);
#pragma unroll
    for (int e = 0; e < 16; e++) {
        sBuf[(grp * 16 + e) * 132 + c2]      = m0[e];
        sBuf[(grp * 16 + e) * 132 + c2 + 64] = m1[e];
    }
    __syncthreads();
    mlp2x<32, 132>(sBuf + grp * 16 * 132, Wp2, c2, m0, m1, b2[c2], b2[c2 + 64]);
    ln_phase(m0, m1, g2, be2, sRed, sMV, tid, c2, grp);

#pragma unroll
    for (int e = 0; e < 16; e++) {
        int n = n0 + grp * 16 + e;
        if (n < N_NODES) {
            g_h[n * HID + c2]      += m0[e];
            g_h[n * HID + c2 + 64] += m1[e];
        }
    }
}

// ---------------------------------------------------------------------------
__global__ void pool_kernel(const int* __restrict__ batch) {
    int n = blockIdx.x;
    int t = threadIdx.x;
    atomicAdd(&g_pool[batch[n] * HID + t], g_h[n * HID + t]);
}

__global__ void pred_kernel(const float* __restrict__ W1, const float* __restrict__ b1,
                            const float* __restrict__ W2, const float* __restrict__ b2,
                            float* __restrict__ out) {
    __shared__ float sred[128];
    int g = blockIdx.x;
    int t = threadIdx.x;
    float acc = b1[t];
    for (int k = 0; k < HID; k++)
        acc = fmaf(g_pool[g * HID + k], W1[k * HID + t], acc);
    acc = fmaxf(acc, 0.f) * W2[t];
    sred[t] = acc;
    __syncthreads();
    for (int o = 64; o > 0; o >>= 1) {
        if (t < o) sred[t] += sred[t + o];
        __syncthreads();
    }
    if (t == 0) out[g] = sred[0] + b2[0];
}

// ---------------------------------------------------------------------------
extern "C" void kernel_launch(void* const* d_in, const int* in_sizes, int n_in,
                              void* d_out, int out_size) {
    const float* x     = (const float*)d_in[0];
    const float* pos   = (const float*)d_in[1];
    const int*   ei    = (const int*)d_in[2];
    const int*   batch = (const int*)d_in[3];
    const float* emb_W = (const float*)d_in[4];
    const float* emb_b = (const float*)d_in[5];

    const float *mW1, *mb1, *mg1, *mbe1, *mW2, *mb2, *mg2, *mbe2;
    const float *uW1, *ub1, *ug1, *ube1, *uW2, *ub2, *ug2, *ube2;

    if (in_sizes[8] == 81920) {
        mW1  = (const float*)d_in[6];  mb1  = (const float*)d_in[7];
        mW2  = (const float*)d_in[8];  mb2  = (const float*)d_in[9];
        uW1  = (const float*)d_in[10]; ub1  = (const float*)d_in[11];
        uW2  = (const float*)d_in[12]; ub2  = (const float*)d_in[13];
        mg1  = (const float*)d_in[14]; mbe1 = (const float*)d_in[15];
        mg2  = (const float*)d_in[16]; mbe2 = (const float*)d_in[17];
        ug1  = (const float*)d_in[18]; ube1 = (const float*)d_in[19];
        ug2  = (const float*)d_in[20]; ube2 = (const float*)d_in[21];
    } else {
        mW1  = (const float*)d_in[6];  mb1  = (const float*)d_in[7];
        mg1  = (const float*)d_in[8];  mbe1 = (const float*)d_in[9];
        mW2  = (const float*)d_in[10]; mb2  = (const float*)d_in[11];
        mg2  = (const float*)d_in[12]; mbe2 = (const float*)d_in[13];
        uW1  = (const float*)d_in[14]; ub1  = (const float*)d_in[15];
        ug1  = (const float*)d_in[16]; ube1 = (const float*)d_in[17];
        uW2  = (const float*)d_in[18]; ub2  = (const float*)d_in[19];
        ug2  = (const float*)d_in[20]; ube2 = (const float*)d_in[21];
    }
    const float* pW1 = (const float*)d_in[22];
    const float* pb1 = (const float*)d_in[23];
    const float* pW2 = (const float*)d_in[24];
    const float* pb2 = (const float*)d_in[25];
    float* out = (float*)d_out;

    float *wm1, *wm2, *wu1, *wu2;
    cudaGetSymbolAddress((void**)&wm1, g_Wm1);
    cudaGetSymbolAddress((void**)&wm2, g_Wm2);
    cudaGetSymbolAddress((void**)&wu1, g_Wu1);
    cudaGetSymbolAddress((void**)&wu2, g_Wu2);

    // Pack weights into k4-packed layout (tiny; in-graph each replay)
    pack_w5<<<(DEPTH * 65 * 512 + 255) / 256, 256>>>(mW1, wm1, 257, 65);
    pack_w5<<<(DEPTH * 32 * 512 + 255) / 256, 256>>>(mW2, wm2, 128, 32);
    pack_w5<<<(DEPTH * 64 * 512 + 255) / 256, 256>>>(uW1, wu1, 256, 64);
    pack_w5<<<(DEPTH * 32 * 512 + 255) / 256, 256>>>(uW2, wu2, 128, 32);

    dist_kernel<<<(N_EDGES + 255) / 256, 256>>>(pos, ei);
    embed_kernel<<<N_NODES, 128>>>(x, emb_W, emb_b);

    for (int l = 0; l < DEPTH; l++) {
        zero_agg_kernel<<<(N_NODES * HID + 255) / 256, 256>>>();
        msg_kernel<<<N_EDGES / EPB, 128>>>(
            ei,
            wm1 + l * 65 * 512, mb1 + l * HID, mg1 + l * HID, mbe1 + l * HID,
            wm2 + l * 32 * 512, mb2 + l * HID, mg2 + l * HID, mbe2 + l * HID);
        upd_kernel<<<(N_NODES + EPB - 1) / EPB, 128>>>(
            wu1 + l * 64 * 512, ub1 + l * HID, ug1 + l * HID, ube1 + l * HID,
            wu2 + l * 32 * 512, ub2 + l * HID, ug2 + l * HID, ube2 + l * HID);
    }

    zero_pool_kernel<<<(N_GRAPHS * HID + 255) / 256, 256>>>();
    pool_kernel<<<N_NODES, 128>>>(batch);
    pred_kernel<<<N_GRAPHS, 128>>>(pW1, pb1, pW2, pb2, out);
}

// round 10
// speedup vs baseline: 2.1912x; 1.5423x over previous
#include <cuda_runtime.h>
#include <cuda_bf16.h>
#include <math.h>
#include <stdint.h>

#define N_NODES 25000
#define N_EDGES 200000
#define HID     128
#define N_GRAPHS 64
#define DEPTH   5
#define NODE_F  16
#define EPB     32

typedef unsigned long long ull;

// ------------------------------ scratch globals ----------------------------
__device__ float g_h[N_NODES * HID];
__device__ float g_agg[N_NODES * HID];
__device__ float g_dist[N_EDGES];
__device__ float g_pool[N_GRAPHS * HID];
__device__ float g_Wu1[DEPTH * 64 * 512];
__device__ float g_Wu2[DEPTH * 32 * 512];
// bf16 hi/lo weight images for msg GEMMs:
// per chunk (16 k-rows x 128 n): 2048 hi + 2048 lo bf16, linear [k][n]
__device__ __nv_bfloat16 g_B1[DEPTH * 16 * 4096];  // W1 rows 0..255
__device__ __nv_bfloat16 g_B2[DEPTH * 8 * 4096];   // W2 rows 0..127

// ------------------------------ msg SMEM layout ----------------------------
#define OFF_A    0          // 2 bufs x (hi 6144 + lo 6144) : rows 128 x 24 bf16
#define OFF_B    24576      // 2 bufs x (hi 4352 + lo 4352) : 16 x 136 bf16
#define OFF_OUT  0          // 128 x 132 fp32 (aliases A/B after GEMMs)
#define OFF_PAR  67584      // 7 x 128 fp32: b1,g1,be1,b2,g2,be2,W1dist
#define OFF_DST  71168
#define OFF_SRC  71680
#define OFF_DIST 72192
#define SMEM_MSG 72704

// ------------------------------ helpers ------------------------------------
__device__ __forceinline__ uint32_t smem_u32(const void* p) {
    uint32_t a;
    asm("{ .reg .u64 t; cvta.to.shared.u64 t, %1; cvt.u32.u64 %0, t; }" : "=r"(a) : "l"(p));
    return a;
}
__device__ __forceinline__ void ldmA(uint32_t a[4], uint32_t addr) {
    asm volatile("ldmatrix.sync.aligned.m8n8.x4.shared.b16 {%0,%1,%2,%3}, [%4];"
                 : "=r"(a[0]), "=r"(a[1]), "=r"(a[2]), "=r"(a[3]) : "r"(addr));
}
__device__ __forceinline__ void ldmBT(uint32_t b[4], uint32_t addr) {
    asm volatile("ldmatrix.sync.aligned.m8n8.x4.trans.shared.b16 {%0,%1,%2,%3}, [%4];"
                 : "=r"(b[0]), "=r"(b[1]), "=r"(b[2]), "=r"(b[3]) : "r"(addr));
}
__device__ __forceinline__ void mma16816(float c[4], const uint32_t a[4],
                                         uint32_t b0, uint32_t b1) {
    asm volatile("mma.sync.aligned.m16n8k16.row.col.f32.bf16.bf16.f32 "
                 "{%0,%1,%2,%3}, {%4,%5,%6,%7}, {%8,%9}, {%0,%1,%2,%3};"
                 : "+f"(c[0]), "+f"(c[1]), "+f"(c[2]), "+f"(c[3])
                 : "r"(a[0]), "r"(a[1]), "r"(a[2]), "r"(a[3]), "r"(b0), "r"(b1));
}
__device__ __forceinline__ uint32_t pack_bf2(float a, float b) {
    __nv_bfloat162 h = __floats2bfloat162_rn(a, b);
    return *reinterpret_cast<uint32_t*>(&h);
}
__device__ __forceinline__ float bf16f(float v) {
    return __bfloat162float(__float2bfloat16(v));
}

// ------------------------------ pack kernels -------------------------------
__global__ void pack_w5(const float* __restrict__ W, float* __restrict__ Wp,
                        int K, int K4) {
    int idx = blockIdx.x * blockDim.x + threadIdx.x;
    int per_layer = K4 * 512;
    if (idx >= DEPTH * per_layer) return;
    int l = idx / per_layer;
    int r = idx - l * per_layer;
    int j = r & 3, c = (r >> 2) & 127, k4 = r >> 9;
    int k = k4 * 4 + j;
    Wp[idx] = (k < K) ? W[l * K * HID + k * HID + c] : 0.f;
}

// Pack msg weights into bf16 hi/lo chunk images (linear [k][n] per chunk).
__global__ void pack_msg(const float* __restrict__ W, __nv_bfloat16* __restrict__ B,
                         int rowStride, int Kuse, int nch) {
    int idx = blockIdx.x * blockDim.x + threadIdx.x;
    int per = nch * 4096;
    if (idx >= DEPTH * per) return;
    int lay = idx / per;
    int rem = idx - lay * per;
    int chunk = rem >> 12;
    int e = rem & 4095;
    int plane = e >> 11;
    int ke = e & 2047;
    int k = ke >> 7, n = ke & 127;
    int kg = chunk * 16 + k;
    float w = (kg < Kuse) ? W[lay * rowStride * HID + kg * HID + n] : 0.f;
    __nv_bfloat16 hi = __float2bfloat16(w);
    B[idx] = plane ? __float2bfloat16(w - __bfloat162float(hi)) : hi;
}

// ------------------------------ misc kernels -------------------------------
__global__ void dist_kernel(const float* __restrict__ pos, const int* __restrict__ ei) {
    int e = blockIdx.x * blockDim.x + threadIdx.x;
    if (e >= N_EDGES) return;
    int s = ei[e];
    int d = ei[N_EDGES + e];
    float dx = pos[d * 3 + 0] - pos[s * 3 + 0];
    float dy = pos[d * 3 + 1] - pos[s * 3 + 1];
    float dz = pos[d * 3 + 2] - pos[s * 3 + 2];
    g_dist[e] = sqrtf(dx * dx + dy * dy + dz * dz);
}

__global__ void embed_kernel(const float* __restrict__ x,
                             const float* __restrict__ W,
                             const float* __restrict__ b) {
    int n = blockIdx.x;
    int t = threadIdx.x;
    float acc = b[t];
#pragma unroll
    for (int k = 0; k < NODE_F; k++)
        acc = fmaf(x[n * NODE_F + k], W[k * HID + t], acc);
    g_h[n * HID + t] = acc;
}

__global__ void zero_agg_kernel() {
    int i = blockIdx.x * blockDim.x + threadIdx.x;
    if (i < N_NODES * HID) g_agg[i] = 0.f;
}
__global__ void zero_pool_kernel() {
    int i = blockIdx.x * blockDim.x + threadIdx.x;
    if (i < N_GRAPHS * HID) g_pool[i] = 0.f;
}

// ------------------------------ msg_mma kernel -----------------------------
// 128 edges/block, 256 threads (8 warps, warp w owns rows 16w..16w+15).
__global__ void __launch_bounds__(256, 1) msg_mma(
    const int* __restrict__ ei,
    const __nv_bfloat16* __restrict__ B1, const __nv_bfloat16* __restrict__ B2,
    const float* __restrict__ W1d,
    const float* __restrict__ b1, const float* __restrict__ g1, const float* __restrict__ be1,
    const float* __restrict__ b2, const float* __restrict__ g2, const float* __restrict__ be2) {
    extern __shared__ char sm[];
    uint32_t smb = smem_u32(sm);
    int tid = threadIdx.x;
    int w = tid >> 5, l = tid & 31;
    int e0 = blockIdx.x * 128;

    int* sDst = (int*)(sm + OFF_DST);
    int* sSrc = (int*)(sm + OFF_SRC);
    float* sDist = (float*)(sm + OFF_DIST);
    float* sPar = (float*)(sm + OFF_PAR);
    if (tid < 128) {
        sPar[tid]       = b1[tid];
        sPar[128 + tid] = g1[tid];
        sPar[256 + tid] = be1[tid];
        sPar[384 + tid] = b2[tid];
        sPar[512 + tid] = g2[tid];
        sPar[640 + tid] = be2[tid];
        sPar[768 + tid] = W1d[tid];
        int ec = min(e0 + tid, N_EDGES - 1);
        sSrc[tid] = ei[ec];
        sDst[tid] = ei[N_EDGES + ec];
        sDist[tid] = g_dist[ec];
    }
    __syncthreads();

    // ---- staging helpers ----
    auto stageA = [&](int kc, int buf) {
        int row = tid >> 1;
        int node = (kc < 8 ? sDst : sSrc)[row];
        const float* src = g_h + (size_t)node * HID + (kc & 7) * 16;
        char* hi = sm + OFF_A + buf * 12288;
        char* lo = hi + 6144;
#pragma unroll
        for (int jj = 0; jj < 2; jj++) {
            int i4 = (tid & 1) * 2 + jj;
            float4 v = *(const float4*)(src + i4 * 4);
            float h0 = bf16f(v.x), h1 = bf16f(v.y), h2 = bf16f(v.z), h3 = bf16f(v.w);
            uint2 H = make_uint2(pack_bf2(v.x, v.y), pack_bf2(v.z, v.w));
            uint2 L = make_uint2(pack_bf2(v.x - h0, v.y - h1), pack_bf2(v.z - h2, v.w - h3));
            int off = (row * 24 + i4 * 4) * 2;
            *(uint2*)(hi + off) = H;
            *(uint2*)(lo + off) = L;
        }
    };
    auto stageB = [&](const __nv_bfloat16* img, int buf) {
        char* dst = sm + OFF_B + buf * 8704;
#pragma unroll
        for (int jj = 0; jj < 2; jj++) {
            int e8 = tid * 2 + jj;          // 512 groups of 8 bf16
            int plane = e8 >> 8;
            int ge = e8 & 255;
            int k = ge >> 4, n = (ge & 15) * 8;
            float4 v = *(const float4*)(img + e8 * 8);
            *(float4*)(dst + plane * 4352 + (k * 136 + n) * 2) = v;
        }
    };

    // ---- GEMM1: [128 x 256] @ [256 x 128] over 16 K-chunks ----
    float C[16][4];
#pragma unroll
    for (int n = 0; n < 16; n++)
#pragma unroll
        for (int j = 0; j < 4; j++) C[n][j] = 0.f;

    stageA(0, 0);
    stageB(B1, 0);
    __syncthreads();
    uint32_t aoff = ((16 * w + (l & 15)) * 24 + (l >> 4) * 8) * 2;
    uint32_t boff = (((l & 7) + 8 * ((l >> 3) & 1)) * 136 + 8 * (l >> 4)) * 2;

#pragma unroll 1
    for (int kc = 0; kc < 16; kc++) {
        int buf = kc & 1;
        if (kc + 1 < 16) { stageA(kc + 1, buf ^ 1); stageB(B1 + (kc + 1) * 4096, buf ^ 1); }
        uint32_t Ah[4], Al[4];
        uint32_t abase = smb + OFF_A + buf * 12288 + aoff;
        ldmA(Ah, abase);
        ldmA(Al, abase + 6144);
        uint32_t bbase = smb + OFF_B + buf * 8704 + boff;
#pragma unroll
        for (int np = 0; np < 8; np++) {
            uint32_t Bh[4], Bl[4];
            uint32_t ba = bbase + np * 32;
            ldmBT(Bh, ba);
            ldmBT(Bl, ba + 4352);
            mma16816(C[2 * np],     Ah, Bh[0], Bh[1]);
            mma16816(C[2 * np],     Ah, Bl[0], Bl[1]);
            mma16816(C[2 * np],     Al, Bh[0], Bh[1]);
            mma16816(C[2 * np + 1], Ah, Bh[2], Bh[3]);
            mma16816(C[2 * np + 1], Ah, Bl[2], Bl[3]);
            mma16816(C[2 * np + 1], Al, Bh[2], Bh[3]);
        }
        __syncthreads();
    }

    // ---- epilogue1: dist rank-1 + bias + LN + ReLU -> A2 fragments ----
    int r0 = 16 * w + (l >> 2), r1 = r0 + 8;
    int q2 = 2 * (l & 3);
    float d0 = sDist[r0], d1 = sDist[r1];
    float s0 = 0.f, s20 = 0.f, s1 = 0.f, s21 = 0.f;
#pragma unroll
    for (int n = 0; n < 16; n++) {
        int col = n * 8 + q2;
        float wd0 = sPar[768 + col], wd1 = sPar[768 + col + 1];
        float bb0 = sPar[col], bb1 = sPar[col + 1];
        C[n][0] += d0 * wd0 + bb0;
        C[n][1] += d0 * wd1 + bb1;
        C[n][2] += d1 * wd0 + bb0;
        C[n][3] += d1 * wd1 + bb1;
        s0 += C[n][0] + C[n][1]; s20 += C[n][0] * C[n][0] + C[n][1] * C[n][1];
        s1 += C[n][2] + C[n][3]; s21 += C[n][2] * C[n][2] + C[n][3] * C[n][3];
    }
    s0 += __shfl_xor_sync(0xffffffffu, s0, 1); s0 += __shfl_xor_sync(0xffffffffu, s0, 2);
    s20 += __shfl_xor_sync(0xffffffffu, s20, 1); s20 += __shfl_xor_sync(0xffffffffu, s20, 2);
    s1 += __shfl_xor_sync(0xffffffffu, s1, 1); s1 += __shfl_xor_sync(0xffffffffu, s1, 2);
    s21 += __shfl_xor_sync(0xffffffffu, s21, 1); s21 += __shfl_xor_sync(0xffffffffu, s21, 2);
    float mn0 = s0 * (1.f / 128.f), vr0 = fmaxf(s20 * (1.f / 128.f) - mn0 * mn0, 0.f);
    float mn1 = s1 * (1.f / 128.f), vr1 = fmaxf(s21 * (1.f / 128.f) - mn1 * mn1, 0.f);
    float rs0 = rsqrtf(vr0 + 1e-5f), rs1 = rsqrtf(vr1 + 1e-5f);

    uint32_t A2h[8][4], A2l[8][4];
#pragma unroll
    for (int n = 0; n < 16; n++) {
        int col = n * 8 + q2;
        float ga = sPar[128 + col], gb = sPar[128 + col + 1];
        float ba = sPar[256 + col], bb = sPar[256 + col + 1];
        float v0 = fmaxf(fmaf((C[n][0] - mn0) * rs0, ga, ba), 0.f);
        float v1 = fmaxf(fmaf((C[n][1] - mn0) * rs0, gb, bb), 0.f);
        float v2 = fmaxf(fmaf((C[n][2] - mn1) * rs1, ga, ba), 0.f);
        float v3 = fmaxf(fmaf((C[n][3] - mn1) * rs1, gb, bb), 0.f);
        int kc = n >> 1, part = (n & 1) * 2;
        float h0 = bf16f(v0), h1 = bf16f(v1), h2 = bf16f(v2), h3 = bf16f(v3);
        A2h[kc][part]     = pack_bf2(v0, v1);
        A2h[kc][part + 1] = pack_bf2(v2, v3);
        A2l[kc][part]     = pack_bf2(v0 - h0, v1 - h1);
        A2l[kc][part + 1] = pack_bf2(v2 - h2, v3 - h3);
    }

    // ---- GEMM2: [128 x 128] @ [128 x 128], A in registers ----
    float C2[16][4];
#pragma unroll
    for (int n = 0; n < 16; n++)
#pragma unroll
        for (int j = 0; j < 4; j++) C2[n][j] = 0.f;

    stageB(B2, 0);
    __syncthreads();
#pragma unroll
    for (int kc = 0; kc < 8; kc++) {
        int buf = kc & 1;
        if (kc + 1 < 8) stageB(B2 + (kc + 1) * 4096, buf ^ 1);
        uint32_t bbase = smb + OFF_B + buf * 8704 + boff;
#pragma unroll
        for (int np = 0; np < 8; np++) {
            uint32_t Bh[4], Bl[4];
            uint32_t ba = bbase + np * 32;
            ldmBT(Bh, ba);
            ldmBT(Bl, ba + 4352);
            mma16816(C2[2 * np],     A2h[kc], Bh[0], Bh[1]);
            mma16816(C2[2 * np],     A2h[kc], Bl[0], Bl[1]);
            mma16816(C2[2 * np],     A2l[kc], Bh[0], Bh[1]);
            mma16816(C2[2 * np + 1], A2h[kc], Bh[2], Bh[3]);
            mma16816(C2[2 * np + 1], A2h[kc], Bl[2], Bl[3]);
            mma16816(C2[2 * np + 1], A2l[kc], Bh[2], Bh[3]);
        }
        __syncthreads();
    }

    // ---- epilogue2: bias + LN + ReLU -> SMEM -> coalesced atomic scatter ----
    s0 = 0.f; s20 = 0.f; s1 = 0.f; s21 = 0.f;
#pragma unroll
    for (int n = 0; n < 16; n++) {
        int col = n * 8 + q2;
        float bb0 = sPar[384 + col], bb1 = sPar[384 + col + 1];
        C2[n][0] += bb0; C2[n][1] += bb1; C2[n][2] += bb0; C2[n][3] += bb1;
        s0 += C2[n][0] + C2[n][1]; s20 += C2[n][0] * C2[n][0] + C2[n][1] * C2[n][1];
        s1 += C2[n][2] + C2[n][3]; s21 += C2[n][2] * C2[n][2] + C2[n][3] * C2[n][3];
    }
    s0 += __shfl_xor_sync(0xffffffffu, s0, 1); s0 += __shfl_xor_sync(0xffffffffu, s0, 2);
    s20 += __shfl_xor_sync(0xffffffffu, s20, 1); s20 += __shfl_xor_sync(0xffffffffu, s20, 2);
    s1 += __shfl_xor_sync(0xffffffffu, s1, 1); s1 += __shfl_xor_sync(0xffffffffu, s1, 2);
    s21 += __shfl_xor_sync(0xffffffffu, s21, 1); s21 += __shfl_xor_sync(0xffffffffu, s21, 2);
    mn0 = s0 * (1.f / 128.f); vr0 = fmaxf(s20 * (1.f / 128.f) - mn0 * mn0, 0.f);
    mn1 = s1 * (1.f / 128.f); vr1 = fmaxf(s21 * (1.f / 128.f) - mn1 * mn1, 0.f);
    rs0 = rsqrtf(vr0 + 1e-5f); rs1 = rsqrtf(vr1 + 1e-5f);

    float* sOut = (float*)(sm + OFF_OUT);
#pragma unroll
    for (int n = 0; n < 16; n++) {
        int col = n * 8 + q2;
        float ga = sPar[512 + col], gb = sPar[512 + col + 1];
        float ba = sPar[640 + col], bb = sPar[640 + col + 1];
        float v0 = fmaxf(fmaf((C2[n][0] - mn0) * rs0, ga, ba), 0.f);
        float v1 = fmaxf(fmaf((C2[n][1] - mn0) * rs0, gb, bb), 0.f);
        float v2 = fmaxf(fmaf((C2[n][2] - mn1) * rs1, ga, ba), 0.f);
        float v3 = fmaxf(fmaf((C2[n][3] - mn1) * rs1, gb, bb), 0.f);
        *(float2*)&sOut[r0 * 132 + col] = make_float2(v0, v1);
        *(float2*)&sOut[r1 * 132 + col] = make_float2(v2, v3);
    }
    __syncthreads();

    int col = tid & 127;
    int half = tid >> 7;
#pragma unroll 4
    for (int i = 0; i < 64; i++) {
        int row = half * 64 + i;
        if (e0 + row < N_EDGES)
            atomicAdd(&g_agg[sDst[row] * HID + col], sOut[row * 132 + col]);
    }
}

// --------------------------- scalar upd path (R4) --------------------------
__device__ __forceinline__ void fma2(ull& d, ull a, ull b) {
    asm("fma.rn.f32x2 %0, %1, %2, %0;" : "+l"(d) : "l"(a), "l"(b));
}
__device__ __forceinline__ float f2sum(ull v) {
    float lo, hi;
    asm("mov.b64 {%0, %1}, %2;" : "=f"(lo), "=f"(hi) : "l"(v));
    return lo + hi;
}

template <int K4, int STRIDE>
__device__ __forceinline__ void mlp2x(const float* __restrict__ sRow,
                                      const float* __restrict__ Wp, int c2,
                                      float m0[16], float m1[16],
                                      float bias0, float bias1) {
    ull a0[16], a1[16];
#pragma unroll
    for (int e = 0; e < 16; e++) { a0[e] = 0ull; a1[e] = 0ull; }
#pragma unroll 2
    for (int k4 = 0; k4 < K4; k4++) {
        ulonglong2 w0 = *(const ulonglong2*)(Wp + (k4 * 128 + c2) * 4);
        ulonglong2 w1 = *(const ulonglong2*)(Wp + (k4 * 128 + c2 + 64) * 4);
#pragma unroll
        for (int e = 0; e < 16; e++) {
            ulonglong2 v = *(const ulonglong2*)(sRow + e * STRIDE + k4 * 4);
            fma2(a0[e], v.x, w0.x);
            fma2(a0[e], v.y, w0.y);
            fma2(a1[e], v.x, w1.x);
            fma2(a1[e], v.y, w1.y);
        }
    }
#pragma unroll
    for (int e = 0; e < 16; e++) {
        m0[e] = f2sum(a0[e]) + bias0;
        m1[e] = f2sum(a1[e]) + bias1;
    }
}

__device__ __forceinline__ void ln_phase(float m0[16], float m1[16],
                                         const float* __restrict__ g,
                                         const float* __restrict__ be,
                                         float (*sRed)[2][2], float (*sMV)[2],
                                         int tid, int c2, int grp) {
    int lane = tid & 31;
    int wip = (tid >> 5) & 1;
#pragma unroll
    for (int e = 0; e < 16; e++) {
        float s  = m0[e] + m1[e];
        float s2 = m0[e] * m0[e] + m1[e] * m1[e];
#pragma unroll
        for (int o = 16; o > 0; o >>= 1) {
            s  += __shfl_xor_sync(0xffffffffu, s, o);
            s2 += __shfl_xor_sync(0xffffffffu, s2, o);
        }
        if (lane == 0) { sRed[grp * 16 + e][wip][0] = s; sRed[grp * 16 + e][wip][1] = s2; }
    }
    __syncthreads();
    if (tid < EPB) {
        float s  = sRed[tid][0][0] + sRed[tid][1][0];
        float s2 = sRed[tid][0][1] + sRed[tid][1][1];
        float mean = s * (1.0f / HID);
        float var  = s2 * (1.0f / HID) - mean * mean;
        var = fmaxf(var, 0.f);
        sMV[tid][0] = mean;
        sMV[tid][1] = rsqrtf(var + 1e-5f);
    }
    __syncthreads();
    float ga = g[c2], gb = g[c2 + 64], ba = be[c2], bb = be[c2 + 64];
#pragma unroll
    for (int e = 0; e < 16; e++) {
        float mean = sMV[grp * 16 + e][0], r = sMV[grp * 16 + e][1];
        m0[e] = fmaxf(fmaf((m0[e] - mean) * r, ga, ba), 0.f);
        m1[e] = fmaxf(fmaf((m1[e] - mean) * r, gb, bb), 0.f);
    }
}

__global__ __launch_bounds__(128, 4) void upd_kernel(
    const float* __restrict__ Wp1, const float* __restrict__ b1,
    const float* __restrict__ g1, const float* __restrict__ be1,
    const float* __restrict__ Wp2, const float* __restrict__ b2,
    const float* __restrict__ g2, const float* __restrict__ be2) {
    __shared__ __align__(16) float sBuf[EPB * 260];
    __shared__ float sRed[EPB][2][2];
    __shared__ float sMV[EPB][2];

    int tid = threadIdx.x;
    int c2 = tid & 63;
    int grp = tid >> 6;
    int n0 = blockIdx.x * EPB;

    {
        int half = grp;
        int sub  = (tid >> 5) & 1;
        int q4   = (tid & 31) * 4;
        const float* srcp = half ? g_agg : g_h;
#pragma unroll 4
        for (int e = 0; e < EPB; e += 2) {
            int ee = e + sub;
            int n = n0 + ee;
            if (n >= N_NODES) n = N_NODES - 1;
            float4 v = *(const float4*)&srcp[n * HID + q4];
            *(float4*)&sBuf[ee * 260 + half * 128 + q4] = v;
        }
    }
    __syncthreads();

    float m0[16], m1[16];
    mlp2x<64, 260>(sBuf + grp * 16 * 260, Wp1, c2, m0, m1, b1[c2], b1[c2 + 64]);
    ln_phase(m0, m1, g1, be1, sRed, sMV, tid, c2, grp);
#pragma unroll
    for (int e = 0; e < 16; e++) {
        sBuf[(grp * 16 + e) * 132 + c2]      = m0[e];
        sBuf[(grp * 16 + e) * 132 + c2 + 64] = m1[e];
    }
    __syncthreads();
    mlp2x<32, 132>(sBuf + grp * 16 * 132, Wp2, c2, m0, m1, b2[c2], b2[c2 + 64]);
    ln_phase(m0, m1, g2, be2, sRed, sMV, tid, c2, grp);

#pragma unroll
    for (int e = 0; e < 16; e++) {
        int n = n0 + grp * 16 + e;
        if (n < N_NODES) {
            g_h[n * HID + c2]      += m0[e];
            g_h[n * HID + c2 + 64] += m1[e];
        }
    }
}

// ------------------------------ pool / pred --------------------------------
__global__ void pool_kernel(const int* __restrict__ batch) {
    int n = blockIdx.x;
    int t = threadIdx.x;
    atomicAdd(&g_pool[batch[n] * HID + t], g_h[n * HID + t]);
}

__global__ void pred_kernel(const float* __restrict__ W1, const float* __restrict__ b1,
                            const float* __restrict__ W2, const float* __restrict__ b2,
                            float* __restrict__ out) {
    __shared__ float sred[128];
    int g = blockIdx.x;
    int t = threadIdx.x;
    float acc = b1[t];
    for (int k = 0; k < HID; k++)
        acc = fmaf(g_pool[g * HID + k], W1[k * HID + t], acc);
    acc = fmaxf(acc, 0.f) * W2[t];
    sred[t] = acc;
    __syncthreads();
    for (int o = 64; o > 0; o >>= 1) {
        if (t < o) sred[t] += sred[t + o];
        __syncthreads();
    }
    if (t == 0) out[g] = sred[0] + b2[0];
}

// ------------------------------ launch -------------------------------------
extern "C" void kernel_launch(void* const* d_in, const int* in_sizes, int n_in,
                              void* d_out, int out_size) {
    const float* x     = (const float*)d_in[0];
    const float* pos   = (const float*)d_in[1];
    const int*   ei    = (const int*)d_in[2];
    const int*   batch = (const int*)d_in[3];
    const float* emb_W = (const float*)d_in[4];
    const float* emb_b = (const float*)d_in[5];

    const float *mW1, *mb1, *mg1, *mbe1, *mW2, *mb2, *mg2, *mbe2;
    const float *uW1, *ub1, *ug1, *ube1, *uW2, *ub2, *ug2, *ube2;

    if (in_sizes[8] == 81920) {
        mW1  = (const float*)d_in[6];  mb1  = (const float*)d_in[7];
        mW2  = (const float*)d_in[8];  mb2  = (const float*)d_in[9];
        uW1  = (const float*)d_in[10]; ub1  = (const float*)d_in[11];
        uW2  = (const float*)d_in[12]; ub2  = (const float*)d_in[13];
        mg1  = (const float*)d_in[14]; mbe1 = (const float*)d_in[15];
        mg2  = (const float*)d_in[16]; mbe2 = (const float*)d_in[17];
        ug1  = (const float*)d_in[18]; ube1 = (const float*)d_in[19];
        ug2  = (const float*)d_in[20]; ube2 = (const float*)d_in[21];
    } else {
        mW1  = (const float*)d_in[6];  mb1  = (const float*)d_in[7];
        mg1  = (const float*)d_in[8];  mbe1 = (const float*)d_in[9];
        mW2  = (const float*)d_in[10]; mb2  = (const float*)d_in[11];
        mg2  = (const float*)d_in[12]; mbe2 = (const float*)d_in[13];
        uW1  = (const float*)d_in[14]; ub1  = (const float*)d_in[15];
        ug1  = (const float*)d_in[16]; ube1 = (const float*)d_in[17];
        uW2  = (const float*)d_in[18]; ub2  = (const float*)d_in[19];
        ug2  = (const float*)d_in[20]; ube2 = (const float*)d_in[21];
    }
    const float* pW1 = (const float*)d_in[22];
    const float* pb1 = (const float*)d_in[23];
    const float* pW2 = (const float*)d_in[24];
    const float* pb2 = (const float*)d_in[25];
    float* out = (float*)d_out;

    float *wu1, *wu2;
    __nv_bfloat16 *bm1, *bm2;
    cudaGetSymbolAddress((void**)&wu1, g_Wu1);
    cudaGetSymbolAddress((void**)&wu2, g_Wu2);
    cudaGetSymbolAddress((void**)&bm1, g_B1);
    cudaGetSymbolAddress((void**)&bm2, g_B2);

    cudaFuncSetAttribute(msg_mma, cudaFuncAttributeMaxDynamicSharedMemorySize, SMEM_MSG);

    pack_w5<<<(DEPTH * 64 * 512 + 255) / 256, 256>>>(uW1, wu1, 256, 64);
    pack_w5<<<(DEPTH * 32 * 512 + 255) / 256, 256>>>(uW2, wu2, 128, 32);
    pack_msg<<<(DEPTH * 16 * 4096 + 255) / 256, 256>>>(mW1, bm1, 257, 256, 16);
    pack_msg<<<(DEPTH * 8 * 4096 + 255) / 256, 256>>>(mW2, bm2, 128, 128, 8);

    dist_kernel<<<(N_EDGES + 255) / 256, 256>>>(pos, ei);
    embed_kernel<<<N_NODES, 128>>>(x, emb_W, emb_b);

    int msg_blocks = (N_EDGES + 127) / 128;
    for (int l = 0; l < DEPTH; l++) {
        zero_agg_kernel<<<(N_NODES * HID + 255) / 256, 256>>>();
        msg_mma<<<msg_blocks, 256, SMEM_MSG>>>(
            ei,
            bm1 + l * 16 * 4096, bm2 + l * 8 * 4096,
            mW1 + l * 257 * HID + 256 * HID,
            mb1 + l * HID, mg1 + l * HID, mbe1 + l * HID,
            mb2 + l * HID, mg2 + l * HID, mbe2 + l * HID);
        upd_kernel<<<(N_NODES + EPB - 1) / EPB, 128>>>(
            wu1 + l * 64 * 512, ub1 + l * HID, ug1 + l * HID, ube1 + l * HID,
            wu2 + l * 32 * 512, ub2 + l * HID, ug2 + l * HID, ube2 + l * HID);
    }

    zero_pool_kernel<<<(N_GRAPHS * HID + 255) / 256, 256>>>();
    pool_kernel<<<N_NODES, 128>>>(batch);
    pred_kernel<<<N_GRAPHS, 128>>>(pW1, pb1, pW2, pb2, out);
}

// round 12
// speedup vs baseline: 2.2826x; 1.0417x over previous
#include <cuda_runtime.h>
#include <cuda_bf16.h>
#include <math.h>
#include <stdint.h>

#define N_NODES 25000
#define N_EDGES 200000
#define HID     128
#define N_GRAPHS 64
#define DEPTH   5
#define NODE_F  16

// ------------------------------ scratch globals ----------------------------
__device__ float g_h[N_NODES * HID];
__device__ float g_agg[N_NODES * HID];
__device__ float g_dist[N_EDGES];
__device__ float g_pool[N_GRAPHS * HID];
// bf16 hi/lo weight images, per chunk (16 k-rows x 128 n): 2048 hi + 2048 lo
__device__ __nv_bfloat16 g_B1[DEPTH * 16 * 4096];   // msg W1 rows 0..255
__device__ __nv_bfloat16 g_B2[DEPTH * 8 * 4096];    // msg W2
__device__ __nv_bfloat16 g_BU1[DEPTH * 16 * 4096];  // upd W1 (256 rows)
__device__ __nv_bfloat16 g_BU2[DEPTH * 8 * 4096];   // upd W2

// ------------------------------ SMEM layout --------------------------------
#define OFF_A    0          // 2 bufs x (hi 6144 + lo 6144) : rows 128 x 24 bf16
#define OFF_B    24576      // 2 bufs x (hi 4352 + lo 4352) : 16 x 136 bf16
#define OFF_OUT  0          // 128 x 132 fp32 (aliases A/B after GEMMs)
#define OFF_PAR  67584      // 7 x 128 fp32: b1,g1,be1,b2,g2,be2,W1dist
#define OFF_DST  71168
#define OFF_SRC  71680
#define OFF_DIST 72192
#define SMEM_MSG 72704

// ------------------------------ helpers ------------------------------------
__device__ __forceinline__ uint32_t smem_u32(const void* p) {
    uint32_t a;
    asm("{ .reg .u64 t; cvta.to.shared.u64 t, %1; cvt.u32.u64 %0, t; }" : "=r"(a) : "l"(p));
    return a;
}
__device__ __forceinline__ void ldmA(uint32_t a[4], uint32_t addr) {
    asm volatile("ldmatrix.sync.aligned.m8n8.x4.shared.b16 {%0,%1,%2,%3}, [%4];"
                 : "=r"(a[0]), "=r"(a[1]), "=r"(a[2]), "=r"(a[3]) : "r"(addr));
}
__device__ __forceinline__ void ldmBT(uint32_t b[4], uint32_t addr) {
    asm volatile("ldmatrix.sync.aligned.m8n8.x4.trans.shared.b16 {%0,%1,%2,%3}, [%4];"
                 : "=r"(b[0]), "=r"(b[1]), "=r"(b[2]), "=r"(b[3]) : "r"(addr));
}
__device__ __forceinline__ void mma16816(float c[4], const uint32_t a[4],
                                         uint32_t b0, uint32_t b1) {
    asm volatile("mma.sync.aligned.m16n8k16.row.col.f32.bf16.bf16.f32 "
                 "{%0,%1,%2,%3}, {%4,%5,%6,%7}, {%8,%9}, {%0,%1,%2,%3};"
                 : "+f"(c[0]), "+f"(c[1]), "+f"(c[2]), "+f"(c[3])
                 : "r"(a[0]), "r"(a[1]), "r"(a[2]), "r"(a[3]), "r"(b0), "r"(b1));
}
__device__ __forceinline__ uint32_t pack_bf2(float a, float b) {
    __nv_bfloat162 h = __floats2bfloat162_rn(a, b);
    return *reinterpret_cast<uint32_t*>(&h);
}
__device__ __forceinline__ float bf16f(float v) {
    return __bfloat162float(__float2bfloat16(v));
}

// ------------------------------ pack kernel --------------------------------
// Pack weights into bf16 hi/lo chunk images (linear [k][n] per chunk).
__global__ void pack_msg(const float* __restrict__ W, __nv_bfloat16* __restrict__ B,
                         int rowStride, int Kuse, int nch) {
    int idx = blockIdx.x * blockDim.x + threadIdx.x;
    int per = nch * 4096;
    if (idx >= DEPTH * per) return;
    int lay = idx / per;
    int rem = idx - lay * per;
    int chunk = rem >> 12;
    int e = rem & 4095;
    int plane = e >> 11;
    int ke = e & 2047;
    int k = ke >> 7, n = ke & 127;
    int kg = chunk * 16 + k;
    float w = (kg < Kuse) ? W[lay * rowStride * HID + kg * HID + n] : 0.f;
    __nv_bfloat16 hi = __float2bfloat16(w);
    B[idx] = plane ? __float2bfloat16(w - __bfloat162float(hi)) : hi;
}

// ------------------------------ misc kernels -------------------------------
__global__ void dist_kernel(const float* __restrict__ pos, const int* __restrict__ ei) {
    int e = blockIdx.x * blockDim.x + threadIdx.x;
    if (e >= N_EDGES) return;
    int s = ei[e];
    int d = ei[N_EDGES + e];
    float dx = pos[d * 3 + 0] - pos[s * 3 + 0];
    float dy = pos[d * 3 + 1] - pos[s * 3 + 1];
    float dz = pos[d * 3 + 2] - pos[s * 3 + 2];
    g_dist[e] = sqrtf(dx * dx + dy * dy + dz * dz);
}

__global__ void embed_kernel(const float* __restrict__ x,
                             const float* __restrict__ W,
                             const float* __restrict__ b) {
    int n = blockIdx.x;
    int t = threadIdx.x;
    float acc = b[t];
#pragma unroll
    for (int k = 0; k < NODE_F; k++)
        acc = fmaf(x[n * NODE_F + k], W[k * HID + t], acc);
    g_h[n * HID + t] = acc;
}

__global__ void zero_agg_kernel() {
    int i = blockIdx.x * blockDim.x + threadIdx.x;
    if (i < N_NODES * HID) g_agg[i] = 0.f;
}
__global__ void zero_pool_kernel() {
    int i = blockIdx.x * blockDim.x + threadIdx.x;
    if (i < N_GRAPHS * HID) g_pool[i] = 0.f;
}

// ---------------------- shared B staging (device fn) -----------------------
__device__ __forceinline__ void stageB_fn(char* sm, int tid,
                                          const __nv_bfloat16* __restrict__ img, int buf) {
    char* dst = sm + OFF_B + buf * 8704;
#pragma unroll
    for (int jj = 0; jj < 2; jj++) {
        int e8 = tid * 2 + jj;          // 512 groups of 8 bf16
        int plane = e8 >> 8;
        int ge = e8 & 255;
        int k = ge >> 4, n = (ge & 15) * 8;
        float4 v = *(const float4*)(img + e8 * 8);
        *(float4*)(dst + plane * 4352 + (k * 136 + n) * 2) = v;
    }
}

// write one thread's 2 float4 spans of A (hi/lo) for (row, 16-col seg)
__device__ __forceinline__ void stageA_write(char* sm, int buf, int row, int i4base,
                                             const float* __restrict__ src) {
    char* hi = sm + OFF_A + buf * 12288;
    char* lo = hi + 6144;
#pragma unroll
    for (int jj = 0; jj < 2; jj++) {
        int i4 = i4base + jj;
        float4 v = *(const float4*)(src + i4 * 4);
        float h0 = bf16f(v.x), h1 = bf16f(v.y), h2 = bf16f(v.z), h3 = bf16f(v.w);
        uint2 H = make_uint2(pack_bf2(v.x, v.y), pack_bf2(v.z, v.w));
        uint2 L = make_uint2(pack_bf2(v.x - h0, v.y - h1), pack_bf2(v.z - h2, v.w - h3));
        int off = (row * 24 + i4 * 4) * 2;
        *(uint2*)(hi + off) = H;
        *(uint2*)(lo + off) = L;
    }
}

// ------------------------------ msg_mma kernel -----------------------------
// 128 edges/block, 256 threads (8 warps, warp w owns rows 16w..16w+15).
__global__ void __launch_bounds__(256, 1) msg_mma(
    const int* __restrict__ ei,
    const __nv_bfloat16* __restrict__ B1, const __nv_bfloat16* __restrict__ B2,
    const float* __restrict__ W1d,
    const float* __restrict__ b1, const float* __restrict__ g1, const float* __restrict__ be1,
    const float* __restrict__ b2, const float* __restrict__ g2, const float* __restrict__ be2) {
    extern __shared__ char sm[];
    uint32_t smb = smem_u32(sm);
    int tid = threadIdx.x;
    int w = tid >> 5, l = tid & 31;
    int e0 = blockIdx.x * 128;

    int* sDst = (int*)(sm + OFF_DST);
    int* sSrc = (int*)(sm + OFF_SRC);
    float* sDist = (float*)(sm + OFF_DIST);
    float* sPar = (float*)(sm + OFF_PAR);
    if (tid < 128) {
        sPar[tid]       = b1[tid];
        sPar[128 + tid] = g1[tid];
        sPar[256 + tid] = be1[tid];
        sPar[384 + tid] = b2[tid];
        sPar[512 + tid] = g2[tid];
        sPar[640 + tid] = be2[tid];
        sPar[768 + tid] = W1d[tid];
        int ec = min(e0 + tid, N_EDGES - 1);
        sSrc[tid] = ei[ec];
        sDst[tid] = ei[N_EDGES + ec];
        sDist[tid] = g_dist[ec];
    }
    __syncthreads();

    auto stageA = [&](int kc, int buf) {
        int row = tid >> 1;
        int node = (kc < 8 ? sDst : sSrc)[row];
        stageA_write(sm, buf, row, (tid & 1) * 2,
                     g_h + (size_t)node * HID + (kc & 7) * 16);
    };

    // ---- GEMM1: [128 x 256] @ [256 x 128] over 16 K-chunks ----
    float C[16][4];
#pragma unroll
    for (int n = 0; n < 16; n++)
#pragma unroll
        for (int j = 0; j < 4; j++) C[n][j] = 0.f;

    stageA(0, 0);
    stageB_fn(sm, tid, B1, 0);
    __syncthreads();
    uint32_t aoff = ((16 * w + (l & 15)) * 24 + (l >> 4) * 8) * 2;
    uint32_t boff = (((l & 7) + 8 * ((l >> 3) & 1)) * 136 + 8 * (l >> 4)) * 2;

#pragma unroll 1
    for (int kc = 0; kc < 16; kc++) {
        int buf = kc & 1;
        if (kc + 1 < 16) { stageA(kc + 1, buf ^ 1); stageB_fn(sm, tid, B1 + (kc + 1) * 4096, buf ^ 1); }
        uint32_t Ah[4], Al[4];
        uint32_t abase = smb + OFF_A + buf * 12288 + aoff;
        ldmA(Ah, abase);
        ldmA(Al, abase + 6144);
        uint32_t bbase = smb + OFF_B + buf * 8704 + boff;
#pragma unroll
        for (int np = 0; np < 8; np++) {
            uint32_t Bh[4], Bl[4];
            uint32_t ba = bbase + np * 32;
            ldmBT(Bh, ba);
            ldmBT(Bl, ba + 4352);
            mma16816(C[2 * np],     Ah, Bh[0], Bh[1]);
            mma16816(C[2 * np],     Ah, Bl[0], Bl[1]);
            mma16816(C[2 * np],     Al, Bh[0], Bh[1]);
            mma16816(C[2 * np + 1], Ah, Bh[2], Bh[3]);
            mma16816(C[2 * np + 1], Ah, Bl[2], Bl[3]);
            mma16816(C[2 * np + 1], Al, Bh[2], Bh[3]);
        }
        __syncthreads();
    }

    // ---- epilogue1: dist rank-1 + bias + LN + ReLU -> A2 fragments ----
    int r0 = 16 * w + (l >> 2), r1 = r0 + 8;
    int q2 = 2 * (l & 3);
    float d0 = sDist[r0], d1 = sDist[r1];
    float s0 = 0.f, s20 = 0.f, s1 = 0.f, s21 = 0.f;
#pragma unroll
    for (int n = 0; n < 16; n++) {
        int col = n * 8 + q2;
        float wd0 = sPar[768 + col], wd1 = sPar[768 + col + 1];
        float bb0 = sPar[col], bb1 = sPar[col + 1];
        C[n][0] += d0 * wd0 + bb0;
        C[n][1] += d0 * wd1 + bb1;
        C[n][2] += d1 * wd0 + bb0;
        C[n][3] += d1 * wd1 + bb1;
        s0 += C[n][0] + C[n][1]; s20 += C[n][0] * C[n][0] + C[n][1] * C[n][1];
        s1 += C[n][2] + C[n][3]; s21 += C[n][2] * C[n][2] + C[n][3] * C[n][3];
    }
    s0 += __shfl_xor_sync(0xffffffffu, s0, 1); s0 += __shfl_xor_sync(0xffffffffu, s0, 2);
    s20 += __shfl_xor_sync(0xffffffffu, s20, 1); s20 += __shfl_xor_sync(0xffffffffu, s20, 2);
    s1 += __shfl_xor_sync(0xffffffffu, s1, 1); s1 += __shfl_xor_sync(0xffffffffu, s1, 2);
    s21 += __shfl_xor_sync(0xffffffffu, s21, 1); s21 += __shfl_xor_sync(0xffffffffu, s21, 2);
    float mn0 = s0 * (1.f / 128.f), vr0 = fmaxf(s20 * (1.f / 128.f) - mn0 * mn0, 0.f);
    float mn1 = s1 * (1.f / 128.f), vr1 = fmaxf(s21 * (1.f / 128.f) - mn1 * mn1, 0.f);
    float rs0 = rsqrtf(vr0 + 1e-5f), rs1 = rsqrtf(vr1 + 1e-5f);

    uint32_t A2h[8][4], A2l[8][4];
#pragma unroll
    for (int n = 0; n < 16; n++) {
        int col = n * 8 + q2;
        float ga = sPar[128 + col], gb = sPar[128 + col + 1];
        float ba = sPar[256 + col], bb = sPar[256 + col + 1];
        float v0 = fmaxf(fmaf((C[n][0] - mn0) * rs0, ga, ba), 0.f);
        float v1 = fmaxf(fmaf((C[n][1] - mn0) * rs0, gb, bb), 0.f);
        float v2 = fmaxf(fmaf((C[n][2] - mn1) * rs1, ga, ba), 0.f);
        float v3 = fmaxf(fmaf((C[n][3] - mn1) * rs1, gb, bb), 0.f);
        int kc = n >> 1, part = (n & 1) * 2;
        float h0 = bf16f(v0), h1 = bf16f(v1), h2 = bf16f(v2), h3 = bf16f(v3);
        A2h[kc][part]     = pack_bf2(v0, v1);
        A2h[kc][part + 1] = pack_bf2(v2, v3);
        A2l[kc][part]     = pack_bf2(v0 - h0, v1 - h1);
        A2l[kc][part + 1] = pack_bf2(v2 - h2, v3 - h3);
    }

    // ---- GEMM2: [128 x 128] @ [128 x 128], A in registers ----
    float C2[16][4];
#pragma unroll
    for (int n = 0; n < 16; n++)
#pragma unroll
        for (int j = 0; j < 4; j++) C2[n][j] = 0.f;

    stageB_fn(sm, tid, B2, 0);
    __syncthreads();
#pragma unroll
    for (int kc = 0; kc < 8; kc++) {
        int buf = kc & 1;
        if (kc + 1 < 8) stageB_fn(sm, tid, B2 + (kc + 1) * 4096, buf ^ 1);
        uint32_t bbase = smb + OFF_B + buf * 8704 + boff;
#pragma unroll
        for (int np = 0; np < 8; np++) {
            uint32_t Bh[4], Bl[4];
            uint32_t ba = bbase + np * 32;
            ldmBT(Bh, ba);
            ldmBT(Bl, ba + 4352);
            mma16816(C2[2 * np],     A2h[kc], Bh[0], Bh[1]);
            mma16816(C2[2 * np],     A2h[kc], Bl[0], Bl[1]);
            mma16816(C2[2 * np],     A2l[kc], Bh[0], Bh[1]);
            mma16816(C2[2 * np + 1], A2h[kc], Bh[2], Bh[3]);
            mma16816(C2[2 * np + 1], A2h[kc], Bl[2], Bl[3]);
            mma16816(C2[2 * np + 1], A2l[kc], Bh[2], Bh[3]);
        }
        __syncthreads();
    }

    // ---- epilogue2: bias + LN + ReLU -> SMEM -> coalesced atomic scatter ----
    s0 = 0.f; s20 = 0.f; s1 = 0.f; s21 = 0.f;
#pragma unroll
    for (int n = 0; n < 16; n++) {
        int col = n * 8 + q2;
        float bb0 = sPar[384 + col], bb1 = sPar[384 + col + 1];
        C2[n][0] += bb0; C2[n][1] += bb1; C2[n][2] += bb0; C2[n][3] += bb1;
        s0 += C2[n][0] + C2[n][1]; s20 += C2[n][0] * C2[n][0] + C2[n][1] * C2[n][1];
        s1 += C2[n][2] + C2[n][3]; s21 += C2[n][2] * C2[n][2] + C2[n][3] * C2[n][3];
    }
    s0 += __shfl_xor_sync(0xffffffffu, s0, 1); s0 += __shfl_xor_sync(0xffffffffu, s0, 2);
    s20 += __shfl_xor_sync(0xffffffffu, s20, 1); s20 += __shfl_xor_sync(0xffffffffu, s20, 2);
    s1 += __shfl_xor_sync(0xffffffffu, s1, 1); s1 += __shfl_xor_sync(0xffffffffu, s1, 2);
    s21 += __shfl_xor_sync(0xffffffffu, s21, 1); s21 += __shfl_xor_sync(0xffffffffu, s21, 2);
    mn0 = s0 * (1.f / 128.f); vr0 = fmaxf(s20 * (1.f / 128.f) - mn0 * mn0, 0.f);
    mn1 = s1 * (1.f / 128.f); vr1 = fmaxf(s21 * (1.f / 128.f) - mn1 * mn1, 0.f);
    rs0 = rsqrtf(vr0 + 1e-5f); rs1 = rsqrtf(vr1 + 1e-5f);

    float* sOut = (float*)(sm + OFF_OUT);
#pragma unroll
    for (int n = 0; n < 16; n++) {
        int col = n * 8 + q2;
        float ga = sPar[512 + col], gb = sPar[512 + col + 1];
        float ba = sPar[640 + col], bb = sPar[640 + col + 1];
        float v0 = fmaxf(fmaf((C2[n][0] - mn0) * rs0, ga, ba), 0.f);
        float v1 = fmaxf(fmaf((C2[n][1] - mn0) * rs0, gb, bb), 0.f);
        float v2 = fmaxf(fmaf((C2[n][2] - mn1) * rs1, ga, ba), 0.f);
        float v3 = fmaxf(fmaf((C2[n][3] - mn1) * rs1, gb, bb), 0.f);
        *(float2*)&sOut[r0 * 132 + col] = make_float2(v0, v1);
        *(float2*)&sOut[r1 * 132 + col] = make_float2(v2, v3);
    }
    __syncthreads();

    int col = tid & 127;
    int half = tid >> 7;
#pragma unroll 4
    for (int i = 0; i < 64; i++) {
        int row = half * 64 + i;
        if (e0 + row < N_EDGES)
            atomicAdd(&g_agg[sDst[row] * HID + col], sOut[row * 132 + col]);
    }
}

// ------------------------------ upd_mma kernel -----------------------------
// 128 nodes/block; K=256 = 8 chunks of h + 8 chunks of agg; residual output.
__global__ void __launch_bounds__(256, 1) upd_mma(
    const __nv_bfloat16* __restrict__ B1, const __nv_bfloat16* __restrict__ B2,
    const float* __restrict__ b1, const float* __restrict__ g1, const float* __restrict__ be1,
    const float* __restrict__ b2, const float* __restrict__ g2, const float* __restrict__ be2) {
    extern __shared__ char sm[];
    uint32_t smb = smem_u32(sm);
    int tid = threadIdx.x;
    int w = tid >> 5, l = tid & 31;
    int n0 = blockIdx.x * 128;

    float* sPar = (float*)(sm + OFF_PAR);
    if (tid < 128) {
        sPar[tid]       = b1[tid];
        sPar[128 + tid] = g1[tid];
        sPar[256 + tid] = be1[tid];
        sPar[384 + tid] = b2[tid];
        sPar[512 + tid] = g2[tid];
        sPar[640 + tid] = be2[tid];
    }
    __syncthreads();

    auto stageA = [&](int kc, int buf) {
        int row = tid >> 1;
        int n = min(n0 + row, N_NODES - 1);
        const float* base = (kc < 8) ? g_h : g_agg;
        stageA_write(sm, buf, row, (tid & 1) * 2,
                     base + (size_t)n * HID + (kc & 7) * 16);
    };

    // ---- GEMM1 ----
    float C[16][4];
#pragma unroll
    for (int n = 0; n < 16; n++)
#pragma unroll
        for (int j = 0; j < 4; j++) C[n][j] = 0.f;

    stageA(0, 0);
    stageB_fn(sm, tid, B1, 0);
    __syncthreads();
    uint32_t aoff = ((16 * w + (l & 15)) * 24 + (l >> 4) * 8) * 2;
    uint32_t boff = (((l & 7) + 8 * ((l >> 3) & 1)) * 136 + 8 * (l >> 4)) * 2;

#pragma unroll 1
    for (int kc = 0; kc < 16; kc++) {
        int buf = kc & 1;
        if (kc + 1 < 16) { stageA(kc + 1, buf ^ 1); stageB_fn(sm, tid, B1 + (kc + 1) * 4096, buf ^ 1); }
        uint32_t Ah[4], Al[4];
        uint32_t abase = smb + OFF_A + buf * 12288 + aoff;
        ldmA(Ah, abase);
        ldmA(Al, abase + 6144);
        uint32_t bbase = smb + OFF_B + buf * 8704 + boff;
#pragma unroll
        for (int np = 0; np < 8; np++) {
            uint32_t Bh[4], Bl[4];
            uint32_t ba = bbase + np * 32;
            ldmBT(Bh, ba);
            ldmBT(Bl, ba + 4352);
            mma16816(C[2 * np],     Ah, Bh[0], Bh[1]);
            mma16816(C[2 * np],     Ah, Bl[0], Bl[1]);
            mma16816(C[2 * np],     Al, Bh[0], Bh[1]);
            mma16816(C[2 * np + 1], Ah, Bh[2], Bh[3]);
            mma16816(C[2 * np + 1], Ah, Bl[2], Bl[3]);
            mma16816(C[2 * np + 1], Al, Bh[2], Bh[3]);
        }
        __syncthreads();
    }

    // ---- epilogue1: bias + LN + ReLU -> A2 fragments ----
    int r0 = 16 * w + (l >> 2), r1 = r0 + 8;
    int q2 = 2 * (l & 3);
    float s0 = 0.f, s20 = 0.f, s1 = 0.f, s21 = 0.f;
#pragma unroll
    for (int n = 0; n < 16; n++) {
        int col = n * 8 + q2;
        float bb0 = sPar[col], bb1 = sPar[col + 1];
        C[n][0] += bb0; C[n][1] += bb1; C[n][2] += bb0; C[n][3] += bb1;
        s0 += C[n][0] + C[n][1]; s20 += C[n][0] * C[n][0] + C[n][1] * C[n][1];
        s1 += C[n][2] + C[n][3]; s21 += C[n][2] * C[n][2] + C[n][3] * C[n][3];
    }
    s0 += __shfl_xor_sync(0xffffffffu, s0, 1); s0 += __shfl_xor_sync(0xffffffffu, s0, 2);
    s20 += __shfl_xor_sync(0xffffffffu, s20, 1); s20 += __shfl_xor_sync(0xffffffffu, s20, 2);
    s1 += __shfl_xor_sync(0xffffffffu, s1, 1); s1 += __shfl_xor_sync(0xffffffffu, s1, 2);
    s21 += __shfl_xor_sync(0xffffffffu, s21, 1); s21 += __shfl_xor_sync(0xffffffffu, s21, 2);
    float mn0 = s0 * (1.f / 128.f), vr0 = fmaxf(s20 * (1.f / 128.f) - mn0 * mn0, 0.f);
    float mn1 = s1 * (1.f / 128.f), vr1 = fmaxf(s21 * (1.f / 128.f) - mn1 * mn1, 0.f);
    float rs0 = rsqrtf(vr0 + 1e-5f), rs1 = rsqrtf(vr1 + 1e-5f);

    uint32_t A2h[8][4], A2l[8][4];
#pragma unroll
    for (int n = 0; n < 16; n++) {
        int col = n * 8 + q2;
        float ga = sPar[128 + col], gb = sPar[128 + col + 1];
        float ba = sPar[256 + col], bb = sPar[256 + col + 1];
        float v0 = fmaxf(fmaf((C[n][0] - mn0) * rs0, ga, ba), 0.f);
        float v1 = fmaxf(fmaf((C[n][1] - mn0) * rs0, gb, bb), 0.f);
        float v2 = fmaxf(fmaf((C[n][2] - mn1) * rs1, ga, ba), 0.f);
        float v3 = fmaxf(fmaf((C[n][3] - mn1) * rs1, gb, bb), 0.f);
        int kc = n >> 1, part = (n & 1) * 2;
        float h0 = bf16f(v0), h1 = bf16f(v1), h2 = bf16f(v2), h3 = bf16f(v3);
        A2h[kc][part]     = pack_bf2(v0, v1);
        A2h[kc][part + 1] = pack_bf2(v2, v3);
        A2l[kc][part]     = pack_bf2(v0 - h0, v1 - h1);
        A2l[kc][part + 1] = pack_bf2(v2 - h2, v3 - h3);
    }

    // ---- GEMM2 ----
    float C2[16][4];
#pragma unroll
    for (int n = 0; n < 16; n++)
#pragma unroll
        for (int j = 0; j < 4; j++) C2[n][j] = 0.f;

    stageB_fn(sm, tid, B2, 0);
    __syncthreads();
#pragma unroll
    for (int kc = 0; kc < 8; kc++) {
        int buf = kc & 1;
        if (kc + 1 < 8) stageB_fn(sm, tid, B2 + (kc + 1) * 4096, buf ^ 1);
        uint32_t bbase = smb + OFF_B + buf * 8704 + boff;
#pragma unroll
        for (int np = 0; np < 8; np++) {
            uint32_t Bh[4], Bl[4];
            uint32_t ba = bbase + np * 32;
            ldmBT(Bh, ba);
            ldmBT(Bl, ba + 4352);
            mma16816(C2[2 * np],     A2h[kc], Bh[0], Bh[1]);
            mma16816(C2[2 * np],     A2h[kc], Bl[0], Bl[1]);
            mma16816(C2[2 * np],     A2l[kc], Bh[0], Bh[1]);
            mma16816(C2[2 * np + 1], A2h[kc], Bh[2], Bh[3]);
            mma16816(C2[2 * np + 1], A2h[kc], Bl[2], Bl[3]);
            mma16816(C2[2 * np + 1], A2l[kc], Bh[2], Bh[3]);
        }
        __syncthreads();
    }

    // ---- epilogue2: bias + LN + ReLU + residual -> g_h ----
    s0 = 0.f; s20 = 0.f; s1 = 0.f; s21 = 0.f;
#pragma unroll
    for (int n = 0; n < 16; n++) {
        int col = n * 8 + q2;
        float bb0 = sPar[384 + col], bb1 = sPar[384 + col + 1];
        C2[n][0] += bb0; C2[n][1] += bb1; C2[n][2] += bb0; C2[n][3] += bb1;
        s0 += C2[n][0] + C2[n][1]; s20 += C2[n][0] * C2[n][0] + C2[n][1] * C2[n][1];
        s1 += C2[n][2] + C2[n][3]; s21 += C2[n][2] * C2[n][2] + C2[n][3] * C2[n][3];
    }
    s0 += __shfl_xor_sync(0xffffffffu, s0, 1); s0 += __shfl_xor_sync(0xffffffffu, s0, 2);
    s20 += __shfl_xor_sync(0xffffffffu, s20, 1); s20 += __shfl_xor_sync(0xffffffffu, s20, 2);
    s1 += __shfl_xor_sync(0xffffffffu, s1, 1); s1 += __shfl_xor_sync(0xffffffffu, s1, 2);
    s21 += __shfl_xor_sync(0xffffffffu, s21, 1); s21 += __shfl_xor_sync(0xffffffffu, s21, 2);
    mn0 = s0 * (1.f / 128.f); vr0 = fmaxf(s20 * (1.f / 128.f) - mn0 * mn0, 0.f);
    mn1 = s1 * (1.f / 128.f); vr1 = fmaxf(s21 * (1.f / 128.f) - mn1 * mn1, 0.f);
    rs0 = rsqrtf(vr0 + 1e-5f); rs1 = rsqrtf(vr1 + 1e-5f);

    int nrow0 = n0 + r0, nrow1 = n0 + r1;
#pragma unroll
    for (int n = 0; n < 16; n++) {
        int col = n * 8 + q2;
        float ga = sPar[512 + col], gb = sPar[512 + col + 1];
        float ba = sPar[640 + col], bb = sPar[640 + col + 1];
        if (nrow0 < N_NODES) {
            float v0 = fmaxf(fmaf((C2[n][0] - mn0) * rs0, ga, ba), 0.f);
            float v1 = fmaxf(fmaf((C2[n][1] - mn0) * rs0, gb, bb), 0.f);
            float2 old = *(float2*)&g_h[(size_t)nrow0 * HID + col];
            *(float2*)&g_h[(size_t)nrow0 * HID + col] = make_float2(old.x + v0, old.y + v1);
        }
        if (nrow1 < N_NODES) {
            float v2 = fmaxf(fmaf((C2[n][2] - mn1) * rs1, ga, ba), 0.f);
            float v3 = fmaxf(fmaf((C2[n][3] - mn1) * rs1, gb, bb), 0.f);
            float2 old = *(float2*)&g_h[(size_t)nrow1 * HID + col];
            *(float2*)&g_h[(size_t)nrow1 * HID + col] = make_float2(old.x + v2, old.y + v3);
        }
    }
}

// ------------------------------ pool / pred --------------------------------
__global__ void pool_kernel(const int* __restrict__ batch) {
    int n = blockIdx.x;
    int t = threadIdx.x;
    atomicAdd(&g_pool[batch[n] * HID + t], g_h[n * HID + t]);
}

__global__ void pred_kernel(const float* __restrict__ W1, const float* __restrict__ b1,
                            const float* __restrict__ W2, const float* __restrict__ b2,
                            float* __restrict__ out) {
    __shared__ float sred[128];
    int g = blockIdx.x;
    int t = threadIdx.x;
    float acc = b1[t];
    for (int k = 0; k < HID; k++)
        acc = fmaf(g_pool[g * HID + k], W1[k * HID + t], acc);
    acc = fmaxf(acc, 0.f) * W2[t];
    sred[t] = acc;
    __syncthreads();
    for (int o = 64; o > 0; o >>= 1) {
        if (t < o) sred[t] += sred[t + o];
        __syncthreads();
    }
    if (t == 0) out[g] = sred[0] + b2[0];
}

// ------------------------------ launch -------------------------------------
extern "C" void kernel_launch(void* const* d_in, const int* in_sizes, int n_in,
                              void* d_out, int out_size) {
    const float* x     = (const float*)d_in[0];
    const float* pos   = (const float*)d_in[1];
    const int*   ei    = (const int*)d_in[2];
    const int*   batch = (const int*)d_in[3];
    const float* emb_W = (const float*)d_in[4];
    const float* emb_b = (const float*)d_in[5];

    const float *mW1, *mb1, *mg1, *mbe1, *mW2, *mb2, *mg2, *mbe2;
    const float *uW1, *ub1, *ug1, *ube1, *uW2, *ub2, *ug2, *ube2;

    if (in_sizes[8] == 81920) {
        mW1  = (const float*)d_in[6];  mb1  = (const float*)d_in[7];
        mW2  = (const float*)d_in[8];  mb2  = (const float*)d_in[9];
        uW1  = (const float*)d_in[10]; ub1  = (const float*)d_in[11];
        uW2  = (const float*)d_in[12]; ub2  = (const float*)d_in[13];
        mg1  = (const float*)d_in[14]; mbe1 = (const float*)d_in[15];
        mg2  = (const float*)d_in[16]; mbe2 = (const float*)d_in[17];
        ug1  = (const float*)d_in[18]; ube1 = (const float*)d_in[19];
        ug2  = (const float*)d_in[20]; ube2 = (const float*)d_in[21];
    } else {
        mW1  = (const float*)d_in[6];  mb1  = (const float*)d_in[7];
        mg1  = (const float*)d_in[8];  mbe1 = (const float*)d_in[9];
        mW2  = (const float*)d_in[10]; mb2  = (const float*)d_in[11];
        mg2  = (const float*)d_in[12]; mbe2 = (const float*)d_in[13];
        uW1  = (const float*)d_in[14]; ub1  = (const float*)d_in[15];
        ug1  = (const float*)d_in[16]; ube1 = (const float*)d_in[17];
        uW2  = (const float*)d_in[18]; ub2  = (const float*)d_in[19];
        ug2  = (const float*)d_in[20]; ube2 = (const float*)d_in[21];
    }
    const float* pW1 = (const float*)d_in[22];
    const float* pb1 = (const float*)d_in[23];
    const float* pW2 = (const float*)d_in[24];
    const float* pb2 = (const float*)d_in[25];
    float* out = (float*)d_out;

    __nv_bfloat16 *bm1, *bm2, *bu1, *bu2;
    cudaGetSymbolAddress((void**)&bm1, g_B1);
    cudaGetSymbolAddress((void**)&bm2, g_B2);
    cudaGetSymbolAddress((void**)&bu1, g_BU1);
    cudaGetSymbolAddress((void**)&bu2, g_BU2);

    cudaFuncSetAttribute(msg_mma, cudaFuncAttributeMaxDynamicSharedMemorySize, SMEM_MSG);
    cudaFuncSetAttribute(upd_mma, cudaFuncAttributeMaxDynamicSharedMemorySize, SMEM_MSG);

    pack_msg<<<(DEPTH * 16 * 4096 + 255) / 256, 256>>>(mW1, bm1, 257, 256, 16);
    pack_msg<<<(DEPTH * 8 * 4096 + 255) / 256, 256>>>(mW2, bm2, 128, 128, 8);
    pack_msg<<<(DEPTH * 16 * 4096 + 255) / 256, 256>>>(uW1, bu1, 256, 256, 16);
    pack_msg<<<(DEPTH * 8 * 4096 + 255) / 256, 256>>>(uW2, bu2, 128, 128, 8);

    dist_kernel<<<(N_EDGES + 255) / 256, 256>>>(pos, ei);
    embed_kernel<<<N_NODES, 128>>>(x, emb_W, emb_b);

    int msg_blocks = (N_EDGES + 127) / 128;
    int upd_blocks = (N_NODES + 127) / 128;
    for (int l = 0; l < DEPTH; l++) {
        zero_agg_kernel<<<(N_NODES * HID + 255) / 256, 256>>>();
        msg_mma<<<msg_blocks, 256, SMEM_MSG>>>(
            ei,
            bm1 + l * 16 * 4096, bm2 + l * 8 * 4096,
            mW1 + l * 257 * HID + 256 * HID,
            mb1 + l * HID, mg1 + l * HID, mbe1 + l * HID,
            mb2 + l * HID, mg2 + l * HID, mbe2 + l * HID);
        upd_mma<<<upd_blocks, 256, SMEM_MSG>>>(
            bu1 + l * 16 * 4096, bu2 + l * 8 * 4096,
            ub1 + l * HID, ug1 + l * HID, ube1 + l * HID,
            ub2 + l * HID, ug2 + l * HID, ube2 + l * HID);
    }

    zero_pool_kernel<<<(N_GRAPHS * HID + 255) / 256, 256>>>();
    pool_kernel<<<N_NODES, 128>>>(batch);
    pred_kernel<<<N_GRAPHS, 128>>>(pW1, pb1, pW2, pb2, out);
}

// round 13
// speedup vs baseline: 2.8196x; 1.2352x over previous
#include <cuda_runtime.h>
#include <cuda_bf16.h>
#include <math.h>
#include <stdint.h>

#define N_NODES 25000
#define N_EDGES 200000
#define HID     128
#define N_GRAPHS 64
#define DEPTH   5
#define NODE_F  16

// ------------------------------ scratch globals ----------------------------
__device__ float g_h[N_NODES * HID];
__device__ float g_agg[N_NODES * HID];
__device__ float g_dist[N_EDGES];
__device__ float g_pool[N_GRAPHS * HID];
// bf16 hi/lo weight images, per chunk (16 k-rows x 128 n): 2048 hi + 2048 lo
__device__ __nv_bfloat16 g_B1[DEPTH * 16 * 4096];   // msg W1 rows 0..255
__device__ __nv_bfloat16 g_B2[DEPTH * 8 * 4096];    // msg W2
__device__ __nv_bfloat16 g_BU1[DEPTH * 16 * 4096];  // upd W1 (256 rows)
__device__ __nv_bfloat16 g_BU2[DEPTH * 8 * 4096];   // upd W2

// ------------------------------ SMEM layout --------------------------------
#define OFF_A    0          // 2 bufs x (hi 6144 + lo 6144) : rows 128 x 24 bf16
#define OFF_B    24576      // 2 bufs x (hi 4352 + lo 4352) : 16 x 136 bf16
#define OFF_OUT  0          // 128 x 132 fp32 (aliases A/B after GEMMs)
#define OFF_PAR  67584      // 7 x 128 fp32: b1,g1,be1,b2,g2,be2,W1dist
#define OFF_DST  71168
#define OFF_SRC  71680
#define OFF_DIST 72192
#define SMEM_MSG 72704

// ------------------------------ helpers ------------------------------------
__device__ __forceinline__ uint32_t smem_u32(const void* p) {
    uint32_t a;
    asm("{ .reg .u64 t; cvta.to.shared.u64 t, %1; cvt.u32.u64 %0, t; }" : "=r"(a) : "l"(p));
    return a;
}
__device__ __forceinline__ void ldmA(uint32_t a[4], uint32_t addr) {
    asm volatile("ldmatrix.sync.aligned.m8n8.x4.shared.b16 {%0,%1,%2,%3}, [%4];"
                 : "=r"(a[0]), "=r"(a[1]), "=r"(a[2]), "=r"(a[3]) : "r"(addr));
}
__device__ __forceinline__ void ldmBT(uint32_t b[4], uint32_t addr) {
    asm volatile("ldmatrix.sync.aligned.m8n8.x4.trans.shared.b16 {%0,%1,%2,%3}, [%4];"
                 : "=r"(b[0]), "=r"(b[1]), "=r"(b[2]), "=r"(b[3]) : "r"(addr));
}
__device__ __forceinline__ void mma16816(float c[4], const uint32_t a[4],
                                         uint32_t b0, uint32_t b1) {
    asm volatile("mma.sync.aligned.m16n8k16.row.col.f32.bf16.bf16.f32 "
                 "{%0,%1,%2,%3}, {%4,%5,%6,%7}, {%8,%9}, {%0,%1,%2,%3};"
                 : "+f"(c[0]), "+f"(c[1]), "+f"(c[2]), "+f"(c[3])
                 : "r"(a[0]), "r"(a[1]), "r"(a[2]), "r"(a[3]), "r"(b0), "r"(b1));
}
__device__ __forceinline__ uint32_t pack_bf2(float a, float b) {
    __nv_bfloat162 h = __floats2bfloat162_rn(a, b);
    return *reinterpret_cast<uint32_t*>(&h);
}
__device__ __forceinline__ float bf16f(float v) {
    return __bfloat162float(__float2bfloat16(v));
}

// ------------------------------ pack kernel --------------------------------
// Pack weights into bf16 hi/lo chunk images (linear [k][n] per chunk).
__global__ void pack_msg(const float* __restrict__ W, __nv_bfloat16* __restrict__ B,
                         int rowStride, int Kuse, int nch) {
    int idx = blockIdx.x * blockDim.x + threadIdx.x;
    int per = nch * 4096;
    if (idx >= DEPTH * per) return;
    int lay = idx / per;
    int rem = idx - lay * per;
    int chunk = rem >> 12;
    int e = rem & 4095;
    int plane = e >> 11;
    int ke = e & 2047;
    int k = ke >> 7, n = ke & 127;
    int kg = chunk * 16 + k;
    float w = (kg < Kuse) ? W[lay * rowStride * HID + kg * HID + n] : 0.f;
    __nv_bfloat16 hi = __float2bfloat16(w);
    B[idx] = plane ? __float2bfloat16(w - __bfloat162float(hi)) : hi;
}

// ------------------------------ misc kernels -------------------------------
__global__ void dist_kernel(const float* __restrict__ pos, const int* __restrict__ ei) {
    int e = blockIdx.x * blockDim.x + threadIdx.x;
    if (e >= N_EDGES) return;
    int s = ei[e];
    int d = ei[N_EDGES + e];
    float dx = pos[d * 3 + 0] - pos[s * 3 + 0];
    float dy = pos[d * 3 + 1] - pos[s * 3 + 1];
    float dz = pos[d * 3 + 2] - pos[s * 3 + 2];
    g_dist[e] = sqrtf(dx * dx + dy * dy + dz * dz);
}

__global__ void embed_kernel(const float* __restrict__ x,
                             const float* __restrict__ W,
                             const float* __restrict__ b) {
    int n = blockIdx.x;
    int t = threadIdx.x;
    float acc = b[t];
#pragma unroll
    for (int k = 0; k < NODE_F; k++)
        acc = fmaf(x[n * NODE_F + k], W[k * HID + t], acc);
    g_h[n * HID + t] = acc;
}

__global__ void zero_agg_kernel() {
    int i = blockIdx.x * blockDim.x + threadIdx.x;
    if (i < N_NODES * HID) g_agg[i] = 0.f;
}
__global__ void zero_pool_kernel() {
    int i = blockIdx.x * blockDim.x + threadIdx.x;
    if (i < N_GRAPHS * HID) g_pool[i] = 0.f;
}

// ---------------------- shared B staging (device fn) -----------------------
__device__ __forceinline__ void stageB_fn(char* sm, int tid,
                                          const __nv_bfloat16* __restrict__ img, int buf) {
    char* dst = sm + OFF_B + buf * 8704;
#pragma unroll
    for (int jj = 0; jj < 2; jj++) {
        int e8 = tid * 2 + jj;          // 512 groups of 8 bf16
        int plane = e8 >> 8;
        int ge = e8 & 255;
        int k = ge >> 4, n = (ge & 15) * 8;
        float4 v = *(const float4*)(img + e8 * 8);
        *(float4*)(dst + plane * 4352 + (k * 136 + n) * 2) = v;
    }
}

// write one thread's 2 float4 spans of A (hi/lo) for (row, 16-col seg)
__device__ __forceinline__ void stageA_write(char* sm, int buf, int row, int i4base,
                                             const float* __restrict__ src) {
    char* hi = sm + OFF_A + buf * 12288;
    char* lo = hi + 6144;
#pragma unroll
    for (int jj = 0; jj < 2; jj++) {
        int i4 = i4base + jj;
        float4 v = *(const float4*)(src + i4 * 4);
        float h0 = bf16f(v.x), h1 = bf16f(v.y), h2 = bf16f(v.z), h3 = bf16f(v.w);
        uint2 H = make_uint2(pack_bf2(v.x, v.y), pack_bf2(v.z, v.w));
        uint2 L = make_uint2(pack_bf2(v.x - h0, v.y - h1), pack_bf2(v.z - h2, v.w - h3));
        int off = (row * 24 + i4 * 4) * 2;
        *(uint2*)(hi + off) = H;
        *(uint2*)(lo + off) = L;
    }
}

// ------------------------------ msg_mma kernel -----------------------------
// 128 edges/block, 256 threads (8 warps, warp w owns rows 16w..16w+15).
// launch_bounds (256,2): cap at 128 regs so 2 CTAs fit per SM (latency hiding);
// modest local spills are L1-resident and cheaper than 1-CTA stalls.
__global__ void __launch_bounds__(256, 2) msg_mma(
    const int* __restrict__ ei,
    const __nv_bfloat16* __restrict__ B1, const __nv_bfloat16* __restrict__ B2,
    const float* __restrict__ W1d,
    const float* __restrict__ b1, const float* __restrict__ g1, const float* __restrict__ be1,
    const float* __restrict__ b2, const float* __restrict__ g2, const float* __restrict__ be2) {
    extern __shared__ char sm[];
    uint32_t smb = smem_u32(sm);
    int tid = threadIdx.x;
    int w = tid >> 5, l = tid & 31;
    int e0 = blockIdx.x * 128;

    int* sDst = (int*)(sm + OFF_DST);
    int* sSrc = (int*)(sm + OFF_SRC);
    float* sDist = (float*)(sm + OFF_DIST);
    float* sPar = (float*)(sm + OFF_PAR);
    if (tid < 128) {
        sPar[tid]       = b1[tid];
        sPar[128 + tid] = g1[tid];
        sPar[256 + tid] = be1[tid];
        sPar[384 + tid] = b2[tid];
        sPar[512 + tid] = g2[tid];
        sPar[640 + tid] = be2[tid];
        sPar[768 + tid] = W1d[tid];
        int ec = min(e0 + tid, N_EDGES - 1);
        sSrc[tid] = ei[ec];
        sDst[tid] = ei[N_EDGES + ec];
        sDist[tid] = g_dist[ec];
    }
    __syncthreads();

    auto stageA = [&](int kc, int buf) {
        int row = tid >> 1;
        int node = (kc < 8 ? sDst : sSrc)[row];
        stageA_write(sm, buf, row, (tid & 1) * 2,
                     g_h + (size_t)node * HID + (kc & 7) * 16);
    };

    // ---- GEMM1: [128 x 256] @ [256 x 128] over 16 K-chunks ----
    float C[16][4];
#pragma unroll
    for (int n = 0; n < 16; n++)
#pragma unroll
        for (int j = 0; j < 4; j++) C[n][j] = 0.f;

    stageA(0, 0);
    stageB_fn(sm, tid, B1, 0);
    __syncthreads();
    uint32_t aoff = ((16 * w + (l & 15)) * 24 + (l >> 4) * 8) * 2;
    uint32_t boff = (((l & 7) + 8 * ((l >> 3) & 1)) * 136 + 8 * (l >> 4)) * 2;

#pragma unroll 1
    for (int kc = 0; kc < 16; kc++) {
        int buf = kc & 1;
        if (kc + 1 < 16) { stageA(kc + 1, buf ^ 1); stageB_fn(sm, tid, B1 + (kc + 1) * 4096, buf ^ 1); }
        uint32_t Ah[4], Al[4];
        uint32_t abase = smb + OFF_A + buf * 12288 + aoff;
        ldmA(Ah, abase);
        ldmA(Al, abase + 6144);
        uint32_t bbase = smb + OFF_B + buf * 8704 + boff;
#pragma unroll
        for (int np = 0; np < 8; np++) {
            uint32_t Bh[4], Bl[4];
            uint32_t ba = bbase + np * 32;
            ldmBT(Bh, ba);
            ldmBT(Bl, ba + 4352);
            mma16816(C[2 * np],     Ah, Bh[0], Bh[1]);
            mma16816(C[2 * np],     Ah, Bl[0], Bl[1]);
            mma16816(C[2 * np],     Al, Bh[0], Bh[1]);
            mma16816(C[2 * np + 1], Ah, Bh[2], Bh[3]);
            mma16816(C[2 * np + 1], Ah, Bl[2], Bl[3]);
            mma16816(C[2 * np + 1], Al, Bh[2], Bh[3]);
        }
        __syncthreads();
    }

    // ---- epilogue1: dist rank-1 + bias + LN + ReLU -> A2 fragments ----
    int r0 = 16 * w + (l >> 2), r1 = r0 + 8;
    int q2 = 2 * (l & 3);
    float d0 = sDist[r0], d1 = sDist[r1];
    float s0 = 0.f, s20 = 0.f, s1 = 0.f, s21 = 0.f;
#pragma unroll
    for (int n = 0; n < 16; n++) {
        int col = n * 8 + q2;
        float wd0 = sPar[768 + col], wd1 = sPar[768 + col + 1];
        float bb0 = sPar[col], bb1 = sPar[col + 1];
        C[n][0] += d0 * wd0 + bb0;
        C[n][1] += d0 * wd1 + bb1;
        C[n][2] += d1 * wd0 + bb0;
        C[n][3] += d1 * wd1 + bb1;
        s0 += C[n][0] + C[n][1]; s20 += C[n][0] * C[n][0] + C[n][1] * C[n][1];
        s1 += C[n][2] + C[n][3]; s21 += C[n][2] * C[n][2] + C[n][3] * C[n][3];
    }
    s0 += __shfl_xor_sync(0xffffffffu, s0, 1); s0 += __shfl_xor_sync(0xffffffffu, s0, 2);
    s20 += __shfl_xor_sync(0xffffffffu, s20, 1); s20 += __shfl_xor_sync(0xffffffffu, s20, 2);
    s1 += __shfl_xor_sync(0xffffffffu, s1, 1); s1 += __shfl_xor_sync(0xffffffffu, s1, 2);
    s21 += __shfl_xor_sync(0xffffffffu, s21, 1); s21 += __shfl_xor_sync(0xffffffffu, s21, 2);
    float mn0 = s0 * (1.f / 128.f), vr0 = fmaxf(s20 * (1.f / 128.f) - mn0 * mn0, 0.f);
    float mn1 = s1 * (1.f / 128.f), vr1 = fmaxf(s21 * (1.f / 128.f) - mn1 * mn1, 0.f);
    float rs0 = rsqrtf(vr0 + 1e-5f), rs1 = rsqrtf(vr1 + 1e-5f);

    uint32_t A2h[8][4], A2l[8][4];
#pragma unroll
    for (int n = 0; n < 16; n++) {
        int col = n * 8 + q2;
        float ga = sPar[128 + col], gb = sPar[128 + col + 1];
        float ba = sPar[256 + col], bb = sPar[256 + col + 1];
        float v0 = fmaxf(fmaf((C[n][0] - mn0) * rs0, ga, ba), 0.f);
        float v1 = fmaxf(fmaf((C[n][1] - mn0) * rs0, gb, bb), 0.f);
        float v2 = fmaxf(fmaf((C[n][2] - mn1) * rs1, ga, ba), 0.f);
        float v3 = fmaxf(fmaf((C[n][3] - mn1) * rs1, gb, bb), 0.f);
        int kc = n >> 1, part = (n & 1) * 2;
        float h0 = bf16f(v0), h1 = bf16f(v1), h2 = bf16f(v2), h3 = bf16f(v3);
        A2h[kc][part]     = pack_bf2(v0, v1);
        A2h[kc][part + 1] = pack_bf2(v2, v3);
        A2l[kc][part]     = pack_bf2(v0 - h0, v1 - h1);
        A2l[kc][part + 1] = pack_bf2(v2 - h2, v3 - h3);
    }

    // ---- GEMM2: [128 x 128] @ [128 x 128], A in registers ----
    float C2[16][4];
#pragma unroll
    for (int n = 0; n < 16; n++)
#pragma unroll
        for (int j = 0; j < 4; j++) C2[n][j] = 0.f;

    stageB_fn(sm, tid, B2, 0);
    __syncthreads();
#pragma unroll
    for (int kc = 0; kc < 8; kc++) {
        int buf = kc & 1;
        if (kc + 1 < 8) stageB_fn(sm, tid, B2 + (kc + 1) * 4096, buf ^ 1);
        uint32_t bbase = smb + OFF_B + buf * 8704 + boff;
#pragma unroll
        for (int np = 0; np < 8; np++) {
            uint32_t Bh[4], Bl[4];
            uint32_t ba = bbase + np * 32;
            ldmBT(Bh, ba);
            ldmBT(Bl, ba + 4352);
            mma16816(C2[2 * np],     A2h[kc], Bh[0], Bh[1]);
            mma16816(C2[2 * np],     A2h[kc], Bl[0], Bl[1]);
            mma16816(C2[2 * np],     A2l[kc], Bh[0], Bh[1]);
            mma16816(C2[2 * np + 1], A2h[kc], Bh[2], Bh[3]);
            mma16816(C2[2 * np + 1], A2h[kc], Bl[2], Bl[3]);
            mma16816(C2[2 * np + 1], A2l[kc], Bh[2], Bh[3]);
        }
        __syncthreads();
    }

    // ---- epilogue2: bias + LN + ReLU -> SMEM -> coalesced atomic scatter ----
    s0 = 0.f; s20 = 0.f; s1 = 0.f; s21 = 0.f;
#pragma unroll
    for (int n = 0; n < 16; n++) {
        int col = n * 8 + q2;
        float bb0 = sPar[384 + col], bb1 = sPar[384 + col + 1];
        C2[n][0] += bb0; C2[n][1] += bb1; C2[n][2] += bb0; C2[n][3] += bb1;
        s0 += C2[n][0] + C2[n][1]; s20 += C2[n][0] * C2[n][0] + C2[n][1] * C2[n][1];
        s1 += C2[n][2] + C2[n][3]; s21 += C2[n][2] * C2[n][2] + C2[n][3] * C2[n][3];
    }
    s0 += __shfl_xor_sync(0xffffffffu, s0, 1); s0 += __shfl_xor_sync(0xffffffffu, s0, 2);
    s20 += __shfl_xor_sync(0xffffffffu, s20, 1); s20 += __shfl_xor_sync(0xffffffffu, s20, 2);
    s1 += __shfl_xor_sync(0xffffffffu, s1, 1); s1 += __shfl_xor_sync(0xffffffffu, s1, 2);
    s21 += __shfl_xor_sync(0xffffffffu, s21, 1); s21 += __shfl_xor_sync(0xffffffffu, s21, 2);
    mn0 = s0 * (1.f / 128.f); vr0 = fmaxf(s20 * (1.f / 128.f) - mn0 * mn0, 0.f);
    mn1 = s1 * (1.f / 128.f); vr1 = fmaxf(s21 * (1.f / 128.f) - mn1 * mn1, 0.f);
    rs0 = rsqrtf(vr0 + 1e-5f); rs1 = rsqrtf(vr1 + 1e-5f);

    float* sOut = (float*)(sm + OFF_OUT);
#pragma unroll
    for (int n = 0; n < 16; n++) {
        int col = n * 8 + q2;
        float ga = sPar[512 + col], gb = sPar[512 + col + 1];
        float ba = sPar[640 + col], bb = sPar[640 + col + 1];
        float v0 = fmaxf(fmaf((C2[n][0] - mn0) * rs0, ga, ba), 0.f);
        float v1 = fmaxf(fmaf((C2[n][1] - mn0) * rs0, gb, bb), 0.f);
        float v2 = fmaxf(fmaf((C2[n][2] - mn1) * rs1, ga, ba), 0.f);
        float v3 = fmaxf(fmaf((C2[n][3] - mn1) * rs1, gb, bb), 0.f);
        *(float2*)&sOut[r0 * 132 + col] = make_float2(v0, v1);
        *(float2*)&sOut[r1 * 132 + col] = make_float2(v2, v3);
    }
    __syncthreads();

    int col = tid & 127;
    int half = tid >> 7;
#pragma unroll 4
    for (int i = 0; i < 64; i++) {
        int row = half * 64 + i;
        if (e0 + row < N_EDGES)
            atomicAdd(&g_agg[sDst[row] * HID + col], sOut[row * 132 + col]);
    }
}

// ------------------------------ upd_mma kernel -----------------------------
// 128 nodes/block; K=256 = 8 chunks of h + 8 chunks of agg; residual output.
__global__ void __launch_bounds__(256, 2) upd_mma(
    const __nv_bfloat16* __restrict__ B1, const __nv_bfloat16* __restrict__ B2,
    const float* __restrict__ b1, const float* __restrict__ g1, const float* __restrict__ be1,
    const float* __restrict__ b2, const float* __restrict__ g2, const float* __restrict__ be2) {
    extern __shared__ char sm[];
    uint32_t smb = smem_u32(sm);
    int tid = threadIdx.x;
    int w = tid >> 5, l = tid & 31;
    int n0 = blockIdx.x * 128;

    float* sPar = (float*)(sm + OFF_PAR);
    if (tid < 128) {
        sPar[tid]       = b1[tid];
        sPar[128 + tid] = g1[tid];
        sPar[256 + tid] = be1[tid];
        sPar[384 + tid] = b2[tid];
        sPar[512 + tid] = g2[tid];
        sPar[640 + tid] = be2[tid];
    }
    __syncthreads();

    auto stageA = [&](int kc, int buf) {
        int row = tid >> 1;
        int n = min(n0 + row, N_NODES - 1);
        const float* base = (kc < 8) ? g_h : g_agg;
        stageA_write(sm, buf, row, (tid & 1) * 2,
                     base + (size_t)n * HID + (kc & 7) * 16);
    };

    // ---- GEMM1 ----
    float C[16][4];
#pragma unroll
    for (int n = 0; n < 16; n++)
#pragma unroll
        for (int j = 0; j < 4; j++) C[n][j] = 0.f;

    stageA(0, 0);
    stageB_fn(sm, tid, B1, 0);
    __syncthreads();
    uint32_t aoff = ((16 * w + (l & 15)) * 24 + (l >> 4) * 8) * 2;
    uint32_t boff = (((l & 7) + 8 * ((l >> 3) & 1)) * 136 + 8 * (l >> 4)) * 2;

#pragma unroll 1
    for (int kc = 0; kc < 16; kc++) {
        int buf = kc & 1;
        if (kc + 1 < 16) { stageA(kc + 1, buf ^ 1); stageB_fn(sm, tid, B1 + (kc + 1) * 4096, buf ^ 1); }
        uint32_t Ah[4], Al[4];
        uint32_t abase = smb + OFF_A + buf * 12288 + aoff;
        ldmA(Ah, abase);
        ldmA(Al, abase + 6144);
        uint32_t bbase = smb + OFF_B + buf * 8704 + boff;
#pragma unroll
        for (int np = 0; np < 8; np++) {
            uint32_t Bh[4], Bl[4];
            uint32_t ba = bbase + np * 32;
            ldmBT(Bh, ba);
            ldmBT(Bl, ba + 4352);
            mma16816(C[2 * np],     Ah, Bh[0], Bh[1]);
            mma16816(C[2 * np],     Ah, Bl[0], Bl[1]);
            mma16816(C[2 * np],     Al, Bh[0], Bh[1]);
            mma16816(C[2 * np + 1], Ah, Bh[2], Bh[3]);
            mma16816(C[2 * np + 1], Ah, Bl[2], Bl[3]);
            mma16816(C[2 * np + 1], Al, Bh[2], Bh[3]);
        }
        __syncthreads();
    }

    // ---- epilogue1: bias + LN + ReLU -> A2 fragments ----
    int r0 = 16 * w + (l >> 2), r1 = r0 + 8;
    int q2 = 2 * (l & 3);
    float s0 = 0.f, s20 = 0.f, s1 = 0.f, s21 = 0.f;
#pragma unroll
    for (int n = 0; n < 16; n++) {
        int col = n * 8 + q2;
        float bb0 = sPar[col], bb1 = sPar[col + 1];
        C[n][0] += bb0; C[n][1] += bb1; C[n][2] += bb0; C[n][3] += bb1;
        s0 += C[n][0] + C[n][1]; s20 += C[n][0] * C[n][0] + C[n][1] * C[n][1];
        s1 += C[n][2] + C[n][3]; s21 += C[n][2] * C[n][2] + C[n][3] * C[n][3];
    }
    s0 += __shfl_xor_sync(0xffffffffu, s0, 1); s0 += __shfl_xor_sync(0xffffffffu, s0, 2);
    s20 += __shfl_xor_sync(0xffffffffu, s20, 1); s20 += __shfl_xor_sync(0xffffffffu, s20, 2);
    s1 += __shfl_xor_sync(0xffffffffu, s1, 1); s1 += __shfl_xor_sync(0xffffffffu, s1, 2);
    s21 += __shfl_xor_sync(0xffffffffu, s21, 1); s21 += __shfl_xor_sync(0xffffffffu, s21, 2);
    float mn0 = s0 * (1.f / 128.f), vr0 = fmaxf(s20 * (1.f / 128.f) - mn0 * mn0, 0.f);
    float mn1 = s1 * (1.f / 128.f), vr1 = fmaxf(s21 * (1.f / 128.f) - mn1 * mn1, 0.f);
    float rs0 = rsqrtf(vr0 + 1e-5f), rs1 = rsqrtf(vr1 + 1e-5f);

    uint32_t A2h[8][4], A2l[8][4];
#pragma unroll
    for (int n = 0; n < 16; n++) {
        int col = n * 8 + q2;
        float ga = sPar[128 + col], gb = sPar[128 + col + 1];
        float ba = sPar[256 + col], bb = sPar[256 + col + 1];
        float v0 = fmaxf(fmaf((C[n][0] - mn0) * rs0, ga, ba), 0.f);
        float v1 = fmaxf(fmaf((C[n][1] - mn0) * rs0, gb, bb), 0.f);
        float v2 = fmaxf(fmaf((C[n][2] - mn1) * rs1, ga, ba), 0.f);
        float v3 = fmaxf(fmaf((C[n][3] - mn1) * rs1, gb, bb), 0.f);
        int kc = n >> 1, part = (n & 1) * 2;
        float h0 = bf16f(v0), h1 = bf16f(v1), h2 = bf16f(v2), h3 = bf16f(v3);
        A2h[kc][part]     = pack_bf2(v0, v1);
        A2h[kc][part + 1] = pack_bf2(v2, v3);
        A2l[kc][part]     = pack_bf2(v0 - h0, v1 - h1);
        A2l[kc][part + 1] = pack_bf2(v2 - h2, v3 - h3);
    }

    // ---- GEMM2 ----
    float C2[16][4];
#pragma unroll
    for (int n = 0; n < 16; n++)
#pragma unroll
        for (int j = 0; j < 4; j++) C2[n][j] = 0.f;

    stageB_fn(sm, tid, B2, 0);
    __syncthreads();
#pragma unroll
    for (int kc = 0; kc < 8; kc++) {
        int buf = kc & 1;
        if (kc + 1 < 8) stageB_fn(sm, tid, B2 + (kc + 1) * 4096, buf ^ 1);
        uint32_t bbase = smb + OFF_B + buf * 8704 + boff;
#pragma unroll
        for (int np = 0; np < 8; np++) {
            uint32_t Bh[4], Bl[4];
            uint32_t ba = bbase + np * 32;
            ldmBT(Bh, ba);
            ldmBT(Bl, ba + 4352);
            mma16816(C2[2 * np],     A2h[kc], Bh[0], Bh[1]);
            mma16816(C2[2 * np],     A2h[kc], Bl[0], Bl[1]);
            mma16816(C2[2 * np],     A2l[kc], Bh[0], Bh[1]);
            mma16816(C2[2 * np + 1], A2h[kc], Bh[2], Bh[3]);
            mma16816(C2[2 * np + 1], A2h[kc], Bl[2], Bl[3]);
            mma16816(C2[2 * np + 1], A2l[kc], Bh[2], Bh[3]);
        }
        __syncthreads();
    }

    // ---- epilogue2: bias + LN + ReLU + residual -> g_h ----
    s0 = 0.f; s20 = 0.f; s1 = 0.f; s21 = 0.f;
#pragma unroll
    for (int n = 0; n < 16; n++) {
        int col = n * 8 + q2;
        float bb0 = sPar[384 + col], bb1 = sPar[384 + col + 1];
        C2[n][0] += bb0; C2[n][1] += bb1; C2[n][2] += bb0; C2[n][3] += bb1;
        s0 += C2[n][0] + C2[n][1]; s20 += C2[n][0] * C2[n][0] + C2[n][1] * C2[n][1];
        s1 += C2[n][2] + C2[n][3]; s21 += C2[n][2] * C2[n][2] + C2[n][3] * C2[n][3];
    }
    s0 += __shfl_xor_sync(0xffffffffu, s0, 1); s0 += __shfl_xor_sync(0xffffffffu, s0, 2);
    s20 += __shfl_xor_sync(0xffffffffu, s20, 1); s20 += __shfl_xor_sync(0xffffffffu, s20, 2);
    s1 += __shfl_xor_sync(0xffffffffu, s1, 1); s1 += __shfl_xor_sync(0xffffffffu, s1, 2);
    s21 += __shfl_xor_sync(0xffffffffu, s21, 1); s21 += __shfl_xor_sync(0xffffffffu, s21, 2);
    mn0 = s0 * (1.f / 128.f); vr0 = fmaxf(s20 * (1.f / 128.f) - mn0 * mn0, 0.f);
    mn1 = s1 * (1.f / 128.f); vr1 = fmaxf(s21 * (1.f / 128.f) - mn1 * mn1, 0.f);
    rs0 = rsqrtf(vr0 + 1e-5f); rs1 = rsqrtf(vr1 + 1e-5f);

    int nrow0 = n0 + r0, nrow1 = n0 + r1;
#pragma unroll
    for (int n = 0; n < 16; n++) {
        int col = n * 8 + q2;
        float ga = sPar[512 + col], gb = sPar[512 + col + 1];
        float ba = sPar[640 + col], bb = sPar[640 + col + 1];
        if (nrow0 < N_NODES) {
            float v0 = fmaxf(fmaf((C2[n][0] - mn0) * rs0, ga, ba), 0.f);
            float v1 = fmaxf(fmaf((C2[n][1] - mn0) * rs0, gb, bb), 0.f);
            float2 old = *(float2*)&g_h[(size_t)nrow0 * HID + col];
            *(float2*)&g_h[(size_t)nrow0 * HID + col] = make_float2(old.x + v0, old.y + v1);
        }
        if (nrow1 < N_NODES) {
            float v2 = fmaxf(fmaf((C2[n][2] - mn1) * rs1, ga, ba), 0.f);
            float v3 = fmaxf(fmaf((C2[n][3] - mn1) * rs1, gb, bb), 0.f);
            float2 old = *(float2*)&g_h[(size_t)nrow1 * HID + col];
            *(float2*)&g_h[(size_t)nrow1 * HID + col] = make_float2(old.x + v2, old.y + v3);
        }
    }
}

// ------------------------------ pool / pred --------------------------------
__global__ void pool_kernel(const int* __restrict__ batch) {
    int n = blockIdx.x;
    int t = threadIdx.x;
    atomicAdd(&g_pool[batch[n] * HID + t], g_h[n * HID + t]);
}

__global__ void pred_kernel(const float* __restrict__ W1, const float* __restrict__ b1,
                            const float* __restrict__ W2, const float* __restrict__ b2,
                            float* __restrict__ out) {
    __shared__ float sred[128];
    int g = blockIdx.x;
    int t = threadIdx.x;
    float acc = b1[t];
    for (int k = 0; k < HID; k++)
        acc = fmaf(g_pool[g * HID + k], W1[k * HID + t], acc);
    acc = fmaxf(acc, 0.f) * W2[t];
    sred[t] = acc;
    __syncthreads();
    for (int o = 64; o > 0; o >>= 1) {
        if (t < o) sred[t] += sred[t + o];
        __syncthreads();
    }
    if (t == 0) out[g] = sred[0] + b2[0];
}

// ------------------------------ launch -------------------------------------
extern "C" void kernel_launch(void* const* d_in, const int* in_sizes, int n_in,
                              void* d_out, int out_size) {
    const float* x     = (const float*)d_in[0];
    const float* pos   = (const float*)d_in[1];
    const int*   ei    = (const int*)d_in[2];
    const int*   batch = (const int*)d_in[3];
    const float* emb_W = (const float*)d_in[4];
    const float* emb_b = (const float*)d_in[5];

    const float *mW1, *mb1, *mg1, *mbe1, *mW2, *mb2, *mg2, *mbe2;
    const float *uW1, *ub1, *ug1, *ube1, *uW2, *ub2, *ug2, *ube2;

    if (in_sizes[8] == 81920) {
        mW1  = (const float*)d_in[6];  mb1  = (const float*)d_in[7];
        mW2  = (const float*)d_in[8];  mb2  = (const float*)d_in[9];
        uW1  = (const float*)d_in[10]; ub1  = (const float*)d_in[11];
        uW2  = (const float*)d_in[12]; ub2  = (const float*)d_in[13];
        mg1  = (const float*)d_in[14]; mbe1 = (const float*)d_in[15];
        mg2  = (const float*)d_in[16]; mbe2 = (const float*)d_in[17];
        ug1  = (const float*)d_in[18]; ube1 = (const float*)d_in[19];
        ug2  = (const float*)d_in[20]; ube2 = (const float*)d_in[21];
    } else {
        mW1  = (const float*)d_in[6];  mb1  = (const float*)d_in[7];
        mg1  = (const float*)d_in[8];  mbe1 = (const float*)d_in[9];
        mW2  = (const float*)d_in[10]; mb2  = (const float*)d_in[11];
        mg2  = (const float*)d_in[12]; mbe2 = (const float*)d_in[13];
        uW1  = (const float*)d_in[14]; ub1  = (const float*)d_in[15];
        ug1  = (const float*)d_in[16]; ube1 = (const float*)d_in[17];
        uW2  = (const float*)d_in[18]; ub2  = (const float*)d_in[19];
        ug2  = (const float*)d_in[20]; ube2 = (const float*)d_in[21];
    }
    const float* pW1 = (const float*)d_in[22];
    const float* pb1 = (const float*)d_in[23];
    const float* pW2 = (const float*)d_in[24];
    const float* pb2 = (const float*)d_in[25];
    float* out = (float*)d_out;

    __nv_bfloat16 *bm1, *bm2, *bu1, *bu2;
    cudaGetSymbolAddress((void**)&bm1, g_B1);
    cudaGetSymbolAddress((void**)&bm2, g_B2);
    cudaGetSymbolAddress((void**)&bu1, g_BU1);
    cudaGetSymbolAddress((void**)&bu2, g_BU2);

    cudaFuncSetAttribute(msg_mma, cudaFuncAttributeMaxDynamicSharedMemorySize, SMEM_MSG);
    cudaFuncSetAttribute(upd_mma, cudaFuncAttributeMaxDynamicSharedMemorySize, SMEM_MSG);

    pack_msg<<<(DEPTH * 16 * 4096 + 255) / 256, 256>>>(mW1, bm1, 257, 256, 16);
    pack_msg<<<(DEPTH * 8 * 4096 + 255) / 256, 256>>>(mW2, bm2, 128, 128, 8);
    pack_msg<<<(DEPTH * 16 * 4096 + 255) / 256, 256>>>(uW1, bu1, 256, 256, 16);
    pack_msg<<<(DEPTH * 8 * 4096 + 255) / 256, 256>>>(uW2, bu2, 128, 128, 8);

    dist_kernel<<<(N_EDGES + 255) / 256, 256>>>(pos, ei);
    embed_kernel<<<N_NODES, 128>>>(x, emb_W, emb_b);

    int msg_blocks = (N_EDGES + 127) / 128;
    int upd_blocks = (N_NODES + 127) / 128;
    for (int l = 0; l < DEPTH; l++) {
        zero_agg_kernel<<<(N_NODES * HID + 255) / 256, 256>>>();
        msg_mma<<<msg_blocks, 256, SMEM_MSG>>>(
            ei,
            bm1 + l * 16 * 4096, bm2 + l * 8 * 4096,
            mW1 + l * 257 * HID + 256 * HID,
            mb1 + l * HID, mg1 + l * HID, mbe1 + l * HID,
            mb2 + l * HID, mg2 + l * HID, mbe2 + l * HID);
        upd_mma<<<upd_blocks, 256, SMEM_MSG>>>(
            bu1 + l * 16 * 4096, bu2 + l * 8 * 4096,
            ub1 + l * HID, ug1 + l * HID, ube1 + l * HID,
            ub2 + l * HID, ug2 + l * HID, ube2 + l * HID);
    }

    zero_pool_kernel<<<(N_GRAPHS * HID + 255) / 256, 256>>>();
    pool_kernel<<<N_NODES, 128>>>(batch);
    pred_kernel<<<N_GRAPHS, 128>>>(pW1, pb1, pW2, pb2, out);
}

// round 14
// speedup vs baseline: 2.9099x; 1.0320x over previous
#include <cuda_runtime.h>
#include <cuda_bf16.h>
#include <math.h>
#include <stdint.h>

#define N_NODES 25000
#define N_EDGES 200000
#define HID     128
#define N_GRAPHS 64
#define DEPTH   5
#define NODE_F  16

// ------------------------------ scratch globals ----------------------------
__device__ float g_h[N_NODES * HID];
__device__ float g_agg[N_NODES * HID];
__device__ float g_dist[N_EDGES];
__device__ float g_pool[N_GRAPHS * HID];
// bf16 hi/lo weight images, per chunk (16 k-rows x 128 n): 2048 hi + 2048 lo
__device__ __nv_bfloat16 g_B1[DEPTH * 16 * 4096];   // msg W1 rows 0..255
__device__ __nv_bfloat16 g_B2[DEPTH * 8 * 4096];    // msg W2
__device__ __nv_bfloat16 g_BU1[DEPTH * 16 * 4096];  // upd W1 (256 rows)
__device__ __nv_bfloat16 g_BU2[DEPTH * 8 * 4096];   // upd W2

// ------------------------------ SMEM layout (bytes) ------------------------
// GEMM1 A stage bufs live at [0, 24576); after GEMM1 the region is reused as
// the A2 image (LN output, bf16 hi/lo, 128 rows x 136 cols = 34816 B/plane),
// and after GEMM2 as sOut (128 x 132 fp32).
#define OFF_A    0          // 2 bufs x (hi 6144 + lo 6144)
#define OFF_A2   0          // hi plane 34816 + lo plane 34816 = 69632
#define OFF_OUT  0          // 128 x 132 fp32 = 67584
#define A2_LO    34816
#define OFF_B    69632      // 2 bufs x (hi 4352 + lo 4352) = 17408
#define OFF_PAR  87040      // 7 x 128 fp32
#define OFF_DST  90624
#define OFF_SRC  91136
#define OFF_DIST 91648
#define SMEM_MSG 92160      // 90 KB; 2 CTAs/SM = 180 KB <= 227 KB

// ------------------------------ helpers ------------------------------------
__device__ __forceinline__ uint32_t smem_u32(const void* p) {
    uint32_t a;
    asm("{ .reg .u64 t; cvta.to.shared.u64 t, %1; cvt.u32.u64 %0, t; }" : "=r"(a) : "l"(p));
    return a;
}
__device__ __forceinline__ void ldmA(uint32_t a[4], uint32_t addr) {
    asm volatile("ldmatrix.sync.aligned.m8n8.x4.shared.b16 {%0,%1,%2,%3}, [%4];"
                 : "=r"(a[0]), "=r"(a[1]), "=r"(a[2]), "=r"(a[3]) : "r"(addr));
}
__device__ __forceinline__ void ldmBT(uint32_t b[4], uint32_t addr) {
    asm volatile("ldmatrix.sync.aligned.m8n8.x4.trans.shared.b16 {%0,%1,%2,%3}, [%4];"
                 : "=r"(b[0]), "=r"(b[1]), "=r"(b[2]), "=r"(b[3]) : "r"(addr));
}
__device__ __forceinline__ void mma16816(float c[4], const uint32_t a[4],
                                         uint32_t b0, uint32_t b1) {
    asm volatile("mma.sync.aligned.m16n8k16.row.col.f32.bf16.bf16.f32 "
                 "{%0,%1,%2,%3}, {%4,%5,%6,%7}, {%8,%9}, {%0,%1,%2,%3};"
                 : "+f"(c[0]), "+f"(c[1]), "+f"(c[2]), "+f"(c[3])
                 : "r"(a[0]), "r"(a[1]), "r"(a[2]), "r"(a[3]), "r"(b0), "r"(b1));
}
__device__ __forceinline__ uint32_t pack_bf2(float a, float b) {
    __nv_bfloat162 h = __floats2bfloat162_rn(a, b);
    return *reinterpret_cast<uint32_t*>(&h);
}
__device__ __forceinline__ float bf16f(float v) {
    return __bfloat162float(__float2bfloat16(v));
}

// ------------------------------ pack kernel (merged) -----------------------
__device__ __forceinline__ void pack_one(const float* __restrict__ W,
                                         __nv_bfloat16* __restrict__ B,
                                         int idx, int rowStride, int Kuse, int nch) {
    int per = nch * 4096;
    int lay = idx / per;
    int rem = idx - lay * per;
    int chunk = rem >> 12;
    int e = rem & 4095;
    int plane = e >> 11;
    int ke = e & 2047;
    int k = ke >> 7, n = ke & 127;
    int kg = chunk * 16 + k;
    float w = (kg < Kuse) ? W[lay * rowStride * HID + kg * HID + n] : 0.f;
    __nv_bfloat16 hi = __float2bfloat16(w);
    B[idx] = plane ? __float2bfloat16(w - __bfloat162float(hi)) : hi;
}

#define PK16 (DEPTH * 16 * 4096)
#define PK8  (DEPTH * 8 * 4096)

__global__ void pack_all(const float* __restrict__ mW1, const float* __restrict__ mW2,
                         const float* __restrict__ uW1, const float* __restrict__ uW2,
                         __nv_bfloat16* __restrict__ B1, __nv_bfloat16* __restrict__ B2,
                         __nv_bfloat16* __restrict__ BU1, __nv_bfloat16* __restrict__ BU2) {
    int idx = blockIdx.x * blockDim.x + threadIdx.x;
    if (idx < PK16) { pack_one(mW1, B1, idx, 257, 256, 16); return; }
    idx -= PK16;
    if (idx < PK8)  { pack_one(mW2, B2, idx, 128, 128, 8); return; }
    idx -= PK8;
    if (idx < PK16) { pack_one(uW1, BU1, idx, 256, 256, 16); return; }
    idx -= PK16;
    if (idx < PK8)  { pack_one(uW2, BU2, idx, 128, 128, 8); }
}

// ------------------------------ misc kernels -------------------------------
__global__ void dist_kernel(const float* __restrict__ pos, const int* __restrict__ ei) {
    int e = blockIdx.x * blockDim.x + threadIdx.x;
    if (e >= N_EDGES) return;
    int s = ei[e];
    int d = ei[N_EDGES + e];
    float dx = pos[d * 3 + 0] - pos[s * 3 + 0];
    float dy = pos[d * 3 + 1] - pos[s * 3 + 1];
    float dz = pos[d * 3 + 2] - pos[s * 3 + 2];
    g_dist[e] = sqrtf(dx * dx + dy * dy + dz * dz);
}

__global__ void embed_kernel(const float* __restrict__ x,
                             const float* __restrict__ W,
                             const float* __restrict__ b) {
    int n = blockIdx.x;
    int t = threadIdx.x;
    float acc = b[t];
#pragma unroll
    for (int k = 0; k < NODE_F; k++)
        acc = fmaf(x[n * NODE_F + k], W[k * HID + t], acc);
    g_h[n * HID + t] = acc;
}

__global__ void zero_agg_kernel() {
    int i = blockIdx.x * blockDim.x + threadIdx.x;
    if (i < N_NODES * HID) g_agg[i] = 0.f;
}
__global__ void zero_pool_kernel() {
    int i = blockIdx.x * blockDim.x + threadIdx.x;
    if (i < N_GRAPHS * HID) g_pool[i] = 0.f;
}

// ---------------------- staging device fns ---------------------------------
__device__ __forceinline__ void stageB_fn(char* sm, int tid,
                                          const __nv_bfloat16* __restrict__ img, int buf) {
    char* dst = sm + OFF_B + buf * 8704;
#pragma unroll
    for (int jj = 0; jj < 2; jj++) {
        int e8 = tid * 2 + jj;          // 512 groups of 8 bf16
        int plane = e8 >> 8;
        int ge = e8 & 255;
        int k = ge >> 4, n = (ge & 15) * 8;
        float4 v = *(const float4*)(img + e8 * 8);
        *(float4*)(dst + plane * 4352 + (k * 136 + n) * 2) = v;
    }
}

// write one thread's 2 float4 spans of A (hi/lo) for (row, 16-col seg)
__device__ __forceinline__ void stageA_write(char* sm, int buf, int row, int i4base,
                                             const float* __restrict__ src) {
    char* hi = sm + OFF_A + buf * 12288;
    char* lo = hi + 6144;
#pragma unroll
    for (int jj = 0; jj < 2; jj++) {
        int i4 = i4base + jj;
        float4 v = *(const float4*)(src + i4 * 4);
        float h0 = bf16f(v.x), h1 = bf16f(v.y), h2 = bf16f(v.z), h3 = bf16f(v.w);
        uint2 H = make_uint2(pack_bf2(v.x, v.y), pack_bf2(v.z, v.w));
        uint2 L = make_uint2(pack_bf2(v.x - h0, v.y - h1), pack_bf2(v.z - h2, v.w - h3));
        int off = (row * 24 + i4 * 4) * 2;
        *(uint2*)(hi + off) = H;
        *(uint2*)(lo + off) = L;
    }
}

// epilogue LN result -> A2 SMEM image (bf16 hi/lo, row stride 272B)
__device__ __forceinline__ void a2_write(char* sm, int row, int col,
                                         float v0, float v1) {
    float h0 = bf16f(v0), h1 = bf16f(v1);
    int off = row * 272 + col * 2;
    *(uint32_t*)(sm + OFF_A2 + off)         = pack_bf2(v0, v1);
    *(uint32_t*)(sm + OFF_A2 + A2_LO + off) = pack_bf2(v0 - h0, v1 - h1);
}

// ------------------------------ msg_mma kernel -----------------------------
// 128 edges/block, 256 threads (8 warps, warp w owns rows 16w..16w+15).
// (256,2): two CTAs/SM; A2 lives in SMEM so register peak fits 128 w/o spills.
__global__ void __launch_bounds__(256, 2) msg_mma(
    const int* __restrict__ ei,
    const __nv_bfloat16* __restrict__ B1, const __nv_bfloat16* __restrict__ B2,
    const float* __restrict__ W1d,
    const float* __restrict__ b1, const float* __restrict__ g1, const float* __restrict__ be1,
    const float* __restrict__ b2, const float* __restrict__ g2, const float* __restrict__ be2) {
    extern __shared__ char sm[];
    uint32_t smb = smem_u32(sm);
    int tid = threadIdx.x;
    int w = tid >> 5, l = tid & 31;
    int e0 = blockIdx.x * 128;

    int* sDst = (int*)(sm + OFF_DST);
    int* sSrc = (int*)(sm + OFF_SRC);
    float* sDist = (float*)(sm + OFF_DIST);
    float* sPar = (float*)(sm + OFF_PAR);
    if (tid < 128) {
        sPar[tid]       = b1[tid];
        sPar[128 + tid] = g1[tid];
        sPar[256 + tid] = be1[tid];
        sPar[384 + tid] = b2[tid];
        sPar[512 + tid] = g2[tid];
        sPar[640 + tid] = be2[tid];
        sPar[768 + tid] = W1d[tid];
        int ec = min(e0 + tid, N_EDGES - 1);
        sSrc[tid] = ei[ec];
        sDst[tid] = ei[N_EDGES + ec];
        sDist[tid] = g_dist[ec];
    }
    __syncthreads();

    auto stageA = [&](int kc, int buf) {
        int row = tid >> 1;
        int node = (kc < 8 ? sDst : sSrc)[row];
        stageA_write(sm, buf, row, (tid & 1) * 2,
                     g_h + (size_t)node * HID + (kc & 7) * 16);
    };

    // ---- GEMM1: [128 x 256] @ [256 x 128] over 16 K-chunks ----
    float C[16][4];
#pragma unroll
    for (int n = 0; n < 16; n++)
#pragma unroll
        for (int j = 0; j < 4; j++) C[n][j] = 0.f;

    stageA(0, 0);
    stageB_fn(sm, tid, B1, 0);
    __syncthreads();
    uint32_t aoff = ((16 * w + (l & 15)) * 24 + (l >> 4) * 8) * 2;
    uint32_t boff = (((l & 7) + 8 * ((l >> 3) & 1)) * 136 + 8 * (l >> 4)) * 2;

#pragma unroll 1
    for (int kc = 0; kc < 16; kc++) {
        int buf = kc & 1;
        if (kc + 1 < 16) { stageA(kc + 1, buf ^ 1); stageB_fn(sm, tid, B1 + (kc + 1) * 4096, buf ^ 1); }
        uint32_t Ah[4], Al[4];
        uint32_t abase = smb + OFF_A + buf * 12288 + aoff;
        ldmA(Ah, abase);
        ldmA(Al, abase + 6144);
        uint32_t bbase = smb + OFF_B + buf * 8704 + boff;
#pragma unroll
        for (int np = 0; np < 8; np++) {
            uint32_t Bh[4], Bl[4];
            uint32_t ba = bbase + np * 32;
            ldmBT(Bh, ba);
            ldmBT(Bl, ba + 4352);
            mma16816(C[2 * np],     Ah, Bh[0], Bh[1]);
            mma16816(C[2 * np],     Ah, Bl[0], Bl[1]);
            mma16816(C[2 * np],     Al, Bh[0], Bh[1]);
            mma16816(C[2 * np + 1], Ah, Bh[2], Bh[3]);
            mma16816(C[2 * np + 1], Ah, Bl[2], Bl[3]);
            mma16816(C[2 * np + 1], Al, Bh[2], Bh[3]);
        }
        __syncthreads();
    }

    // ---- epilogue1: dist rank-1 + bias + LN + ReLU -> A2 SMEM image ----
    int r0 = 16 * w + (l >> 2), r1 = r0 + 8;
    int q2 = 2 * (l & 3);
    float d0 = sDist[r0], d1 = sDist[r1];
    float s0 = 0.f, s20 = 0.f, s1 = 0.f, s21 = 0.f;
#pragma unroll
    for (int n = 0; n < 16; n++) {
        int col = n * 8 + q2;
        float wd0 = sPar[768 + col], wd1 = sPar[768 + col + 1];
        float bb0 = sPar[col], bb1 = sPar[col + 1];
        C[n][0] += d0 * wd0 + bb0;
        C[n][1] += d0 * wd1 + bb1;
        C[n][2] += d1 * wd0 + bb0;
        C[n][3] += d1 * wd1 + bb1;
        s0 += C[n][0] + C[n][1]; s20 += C[n][0] * C[n][0] + C[n][1] * C[n][1];
        s1 += C[n][2] + C[n][3]; s21 += C[n][2] * C[n][2] + C[n][3] * C[n][3];
    }
    s0 += __shfl_xor_sync(0xffffffffu, s0, 1); s0 += __shfl_xor_sync(0xffffffffu, s0, 2);
    s20 += __shfl_xor_sync(0xffffffffu, s20, 1); s20 += __shfl_xor_sync(0xffffffffu, s20, 2);
    s1 += __shfl_xor_sync(0xffffffffu, s1, 1); s1 += __shfl_xor_sync(0xffffffffu, s1, 2);
    s21 += __shfl_xor_sync(0xffffffffu, s21, 1); s21 += __shfl_xor_sync(0xffffffffu, s21, 2);
    float mn0 = s0 * (1.f / 128.f), vr0 = fmaxf(s20 * (1.f / 128.f) - mn0 * mn0, 0.f);
    float mn1 = s1 * (1.f / 128.f), vr1 = fmaxf(s21 * (1.f / 128.f) - mn1 * mn1, 0.f);
    float rs0 = rsqrtf(vr0 + 1e-5f), rs1 = rsqrtf(vr1 + 1e-5f);

#pragma unroll
    for (int n = 0; n < 16; n++) {
        int col = n * 8 + q2;
        float ga = sPar[128 + col], gb = sPar[128 + col + 1];
        float ba = sPar[256 + col], bb = sPar[256 + col + 1];
        a2_write(sm, r0, col, fmaxf(fmaf((C[n][0] - mn0) * rs0, ga, ba), 0.f),
                              fmaxf(fmaf((C[n][1] - mn0) * rs0, gb, bb), 0.f));
        a2_write(sm, r1, col, fmaxf(fmaf((C[n][2] - mn1) * rs1, ga, ba), 0.f),
                              fmaxf(fmaf((C[n][3] - mn1) * rs1, gb, bb), 0.f));
    }

    // ---- GEMM2: [128 x 128] @ [128 x 128], A2 from SMEM ----
    float C2[16][4];
#pragma unroll
    for (int n = 0; n < 16; n++)
#pragma unroll
        for (int j = 0; j < 4; j++) C2[n][j] = 0.f;

    stageB_fn(sm, tid, B2, 0);
    __syncthreads();
    uint32_t a2row = smb + OFF_A2 + (16 * w + (l & 15)) * 272 + (l >> 4) * 16;
#pragma unroll
    for (int kc = 0; kc < 8; kc++) {
        int buf = kc & 1;
        if (kc + 1 < 8) stageB_fn(sm, tid, B2 + (kc + 1) * 4096, buf ^ 1);
        uint32_t A2h[4], A2l[4];
        uint32_t a2base = a2row + kc * 32;
        ldmA(A2h, a2base);
        ldmA(A2l, a2base + A2_LO);
        uint32_t bbase = smb + OFF_B + buf * 8704 + boff;
#pragma unroll
        for (int np = 0; np < 8; np++) {
            uint32_t Bh[4], Bl[4];
            uint32_t ba = bbase + np * 32;
            ldmBT(Bh, ba);
            ldmBT(Bl, ba + 4352);
            mma16816(C2[2 * np],     A2h, Bh[0], Bh[1]);
            mma16816(C2[2 * np],     A2h, Bl[0], Bl[1]);
            mma16816(C2[2 * np],     A2l, Bh[0], Bh[1]);
            mma16816(C2[2 * np + 1], A2h, Bh[2], Bh[3]);
            mma16816(C2[2 * np + 1], A2h, Bl[2], Bl[3]);
            mma16816(C2[2 * np + 1], A2l, Bh[2], Bh[3]);
        }
        __syncthreads();
    }

    // ---- epilogue2: bias + LN + ReLU -> SMEM -> coalesced atomic scatter ----
    s0 = 0.f; s20 = 0.f; s1 = 0.f; s21 = 0.f;
#pragma unroll
    for (int n = 0; n < 16; n++) {
        int col = n * 8 + q2;
        float bb0 = sPar[384 + col], bb1 = sPar[384 + col + 1];
        C2[n][0] += bb0; C2[n][1] += bb1; C2[n][2] += bb0; C2[n][3] += bb1;
        s0 += C2[n][0] + C2[n][1]; s20 += C2[n][0] * C2[n][0] + C2[n][1] * C2[n][1];
        s1 += C2[n][2] + C2[n][3]; s21 += C2[n][2] * C2[n][2] + C2[n][3] * C2[n][3];
    }
    s0 += __shfl_xor_sync(0xffffffffu, s0, 1); s0 += __shfl_xor_sync(0xffffffffu, s0, 2);
    s20 += __shfl_xor_sync(0xffffffffu, s20, 1); s20 += __shfl_xor_sync(0xffffffffu, s20, 2);
    s1 += __shfl_xor_sync(0xffffffffu, s1, 1); s1 += __shfl_xor_sync(0xffffffffu, s1, 2);
    s21 += __shfl_xor_sync(0xffffffffu, s21, 1); s21 += __shfl_xor_sync(0xffffffffu, s21, 2);
    mn0 = s0 * (1.f / 128.f); vr0 = fmaxf(s20 * (1.f / 128.f) - mn0 * mn0, 0.f);
    mn1 = s1 * (1.f / 128.f); vr1 = fmaxf(s21 * (1.f / 128.f) - mn1 * mn1, 0.f);
    rs0 = rsqrtf(vr0 + 1e-5f); rs1 = rsqrtf(vr1 + 1e-5f);

    float* sOut = (float*)(sm + OFF_OUT);
#pragma unroll
    for (int n = 0; n < 16; n++) {
        int col = n * 8 + q2;
        float ga = sPar[512 + col], gb = sPar[512 + col + 1];
        float ba = sPar[640 + col], bb = sPar[640 + col + 1];
        float v0 = fmaxf(fmaf((C2[n][0] - mn0) * rs0, ga, ba), 0.f);
        float v1 = fmaxf(fmaf((C2[n][1] - mn0) * rs0, gb, bb), 0.f);
        float v2 = fmaxf(fmaf((C2[n][2] - mn1) * rs1, ga, ba), 0.f);
        float v3 = fmaxf(fmaf((C2[n][3] - mn1) * rs1, gb, bb), 0.f);
        *(float2*)&sOut[r0 * 132 + col] = make_float2(v0, v1);
        *(float2*)&sOut[r1 * 132 + col] = make_float2(v2, v3);
    }
    __syncthreads();

    int col = tid & 127;
    int half = tid >> 7;
#pragma unroll 4
    for (int i = 0; i < 64; i++) {
        int row = half * 64 + i;
        if (e0 + row < N_EDGES)
            atomicAdd(&g_agg[sDst[row] * HID + col], sOut[row * 132 + col]);
    }
}

// ------------------------------ upd_mma kernel -----------------------------
// 128 nodes/block; K=256 = 8 chunks of h + 8 chunks of agg; residual output.
__global__ void __launch_bounds__(256, 2) upd_mma(
    const __nv_bfloat16* __restrict__ B1, const __nv_bfloat16* __restrict__ B2,
    const float* __restrict__ b1, const float* __restrict__ g1, const float* __restrict__ be1,
    const float* __restrict__ b2, const float* __restrict__ g2, const float* __restrict__ be2) {
    extern __shared__ char sm[];
    uint32_t smb = smem_u32(sm);
    int tid = threadIdx.x;
    int w = tid >> 5, l = tid & 31;
    int n0 = blockIdx.x * 128;

    float* sPar = (float*)(sm + OFF_PAR);
    if (tid < 128) {
        sPar[tid]       = b1[tid];
        sPar[128 + tid] = g1[tid];
        sPar[256 + tid] = be1[tid];
        sPar[384 + tid] = b2[tid];
        sPar[512 + tid] = g2[tid];
        sPar[640 + tid] = be2[tid];
    }
    __syncthreads();

    auto stageA = [&](int kc, int buf) {
        int row = tid >> 1;
        int n = min(n0 + row, N_NODES - 1);
        const float* base = (kc < 8) ? g_h : g_agg;
        stageA_write(sm, buf, row, (tid & 1) * 2,
                     base + (size_t)n * HID + (kc & 7) * 16);
    };

    // ---- GEMM1 ----
    float C[16][4];
#pragma unroll
    for (int n = 0; n < 16; n++)
#pragma unroll
        for (int j = 0; j < 4; j++) C[n][j] = 0.f;

    stageA(0, 0);
    stageB_fn(sm, tid, B1, 0);
    __syncthreads();
    uint32_t aoff = ((16 * w + (l & 15)) * 24 + (l >> 4) * 8) * 2;
    uint32_t boff = (((l & 7) + 8 * ((l >> 3) & 1)) * 136 + 8 * (l >> 4)) * 2;

#pragma unroll 1
    for (int kc = 0; kc < 16; kc++) {
        int buf = kc & 1;
        if (kc + 1 < 16) { stageA(kc + 1, buf ^ 1); stageB_fn(sm, tid, B1 + (kc + 1) * 4096, buf ^ 1); }
        uint32_t Ah[4], Al[4];
        uint32_t abase = smb + OFF_A + buf * 12288 + aoff;
        ldmA(Ah, abase);
        ldmA(Al, abase + 6144);
        uint32_t bbase = smb + OFF_B + buf * 8704 + boff;
#pragma unroll
        for (int np = 0; np < 8; np++) {
            uint32_t Bh[4], Bl[4];
            uint32_t ba = bbase + np * 32;
            ldmBT(Bh, ba);
            ldmBT(Bl, ba + 4352);
            mma16816(C[2 * np],     Ah, Bh[0], Bh[1]);
            mma16816(C[2 * np],     Ah, Bl[0], Bl[1]);
            mma16816(C[2 * np],     Al, Bh[0], Bh[1]);
            mma16816(C[2 * np + 1], Ah, Bh[2], Bh[3]);
            mma16816(C[2 * np + 1], Ah, Bl[2], Bl[3]);
            mma16816(C[2 * np + 1], Al, Bh[2], Bh[3]);
        }
        __syncthreads();
    }

    // ---- epilogue1: bias + LN + ReLU -> A2 SMEM image ----
    int r0 = 16 * w + (l >> 2), r1 = r0 + 8;
    int q2 = 2 * (l & 3);
    float s0 = 0.f, s20 = 0.f, s1 = 0.f, s21 = 0.f;
#pragma unroll
    for (int n = 0; n < 16; n++) {
        int col = n * 8 + q2;
        float bb0 = sPar[col], bb1 = sPar[col + 1];
        C[n][0] += bb0; C[n][1] += bb1; C[n][2] += bb0; C[n][3] += bb1;
        s0 += C[n][0] + C[n][1]; s20 += C[n][0] * C[n][0] + C[n][1] * C[n][1];
        s1 += C[n][2] + C[n][3]; s21 += C[n][2] * C[n][2] + C[n][3] * C[n][3];
    }
    s0 += __shfl_xor_sync(0xffffffffu, s0, 1); s0 += __shfl_xor_sync(0xffffffffu, s0, 2);
    s20 += __shfl_xor_sync(0xffffffffu, s20, 1); s20 += __shfl_xor_sync(0xffffffffu, s20, 2);
    s1 += __shfl_xor_sync(0xffffffffu, s1, 1); s1 += __shfl_xor_sync(0xffffffffu, s1, 2);
    s21 += __shfl_xor_sync(0xffffffffu, s21, 1); s21 += __shfl_xor_sync(0xffffffffu, s21, 2);
    float mn0 = s0 * (1.f / 128.f), vr0 = fmaxf(s20 * (1.f / 128.f) - mn0 * mn0, 0.f);
    float mn1 = s1 * (1.f / 128.f), vr1 = fmaxf(s21 * (1.f / 128.f) - mn1 * mn1, 0.f);
    float rs0 = rsqrtf(vr0 + 1e-5f), rs1 = rsqrtf(vr1 + 1e-5f);

#pragma unroll
    for (int n = 0; n < 16; n++) {
        int col = n * 8 + q2;
        float ga = sPar[128 + col], gb = sPar[128 + col + 1];
        float ba = sPar[256 + col], bb = sPar[256 + col + 1];
        a2_write(sm, r0, col, fmaxf(fmaf((C[n][0] - mn0) * rs0, ga, ba), 0.f),
                              fmaxf(fmaf((C[n][1] - mn0) * rs0, gb, bb), 0.f));
        a2_write(sm, r1, col, fmaxf(fmaf((C[n][2] - mn1) * rs1, ga, ba), 0.f),
                              fmaxf(fmaf((C[n][3] - mn1) * rs1, gb, bb), 0.f));
    }

    // ---- GEMM2 ----
    float C2[16][4];
#pragma unroll
    for (int n = 0; n < 16; n++)
#pragma unroll
        for (int j = 0; j < 4; j++) C2[n][j] = 0.f;

    stageB_fn(sm, tid, B2, 0);
    __syncthreads();
    uint32_t a2row = smb + OFF_A2 + (16 * w + (l & 15)) * 272 + (l >> 4) * 16;
#pragma unroll
    for (int kc = 0; kc < 8; kc++) {
        int buf = kc & 1;
        if (kc + 1 < 8) stageB_fn(sm, tid, B2 + (kc + 1) * 4096, buf ^ 1);
        uint32_t A2h[4], A2l[4];
        uint32_t a2base = a2row + kc * 32;
        ldmA(A2h, a2base);
        ldmA(A2l, a2base + A2_LO);
        uint32_t bbase = smb + OFF_B + buf * 8704 + boff;
#pragma unroll
        for (int np = 0; np < 8; np++) {
            uint32_t Bh[4], Bl[4];
            uint32_t ba = bbase + np * 32;
            ldmBT(Bh, ba);
            ldmBT(Bl, ba + 4352);
            mma16816(C2[2 * np],     A2h, Bh[0], Bh[1]);
            mma16816(C2[2 * np],     A2h, Bl[0], Bl[1]);
            mma16816(C2[2 * np],     A2l, Bh[0], Bh[1]);
            mma16816(C2[2 * np + 1], A2h, Bh[2], Bh[3]);
            mma16816(C2[2 * np + 1], A2h, Bl[2], Bl[3]);
            mma16816(C2[2 * np + 1], A2l, Bh[2], Bh[3]);
        }
        __syncthreads();
    }

    // ---- epilogue2: bias + LN + ReLU + residual -> g_h ----
    s0 = 0.f; s20 = 0.f; s1 = 0.f; s21 = 0.f;
#pragma unroll
    for (int n = 0; n < 16; n++) {
        int col = n * 8 + q2;
        float bb0 = sPar[384 + col], bb1 = sPar[384 + col + 1];
        C2[n][0] += bb0; C2[n][1] += bb1; C2[n][2] += bb0; C2[n][3] += bb1;
        s0 += C2[n][0] + C2[n][1]; s20 += C2[n][0] * C2[n][0] + C2[n][1] * C2[n][1];
        s1 += C2[n][2] + C2[n][3]; s21 += C2[n][2] * C2[n][2] + C2[n][3] * C2[n][3];
    }
    s0 += __shfl_xor_sync(0xffffffffu, s0, 1); s0 += __shfl_xor_sync(0xffffffffu, s0, 2);
    s20 += __shfl_xor_sync(0xffffffffu, s20, 1); s20 += __shfl_xor_sync(0xffffffffu, s20, 2);
    s1 += __shfl_xor_sync(0xffffffffu, s1, 1); s1 += __shfl_xor_sync(0xffffffffu, s1, 2);
    s21 += __shfl_xor_sync(0xffffffffu, s21, 1); s21 += __shfl_xor_sync(0xffffffffu, s21, 2);
    mn0 = s0 * (1.f / 128.f); vr0 = fmaxf(s20 * (1.f / 128.f) - mn0 * mn0, 0.f);
    mn1 = s1 * (1.f / 128.f); vr1 = fmaxf(s21 * (1.f / 128.f) - mn1 * mn1, 0.f);
    rs0 = rsqrtf(vr0 + 1e-5f); rs1 = rsqrtf(vr1 + 1e-5f);

    int nrow0 = n0 + r0, nrow1 = n0 + r1;
#pragma unroll
    for (int n = 0; n < 16; n++) {
        int col = n * 8 + q2;
        float ga = sPar[512 + col], gb = sPar[512 + col + 1];
        float ba = sPar[640 + col], bb = sPar[640 + col + 1];
        if (nrow0 < N_NODES) {
            float v0 = fmaxf(fmaf((C2[n][0] - mn0) * rs0, ga, ba), 0.f);
            float v1 = fmaxf(fmaf((C2[n][1] - mn0) * rs0, gb, bb), 0.f);
            float2 old = *(float2*)&g_h[(size_t)nrow0 * HID + col];
            *(float2*)&g_h[(size_t)nrow0 * HID + col] = make_float2(old.x + v0, old.y + v1);
        }
        if (nrow1 < N_NODES) {
            float v2 = fmaxf(fmaf((C2[n][2] - mn1) * rs1, ga, ba), 0.f);
            float v3 = fmaxf(fmaf((C2[n][3] - mn1) * rs1, gb, bb), 0.f);
            float2 old = *(float2*)&g_h[(size_t)nrow1 * HID + col];
            *(float2*)&g_h[(size_t)nrow1 * HID + col] = make_float2(old.x + v2, old.y + v3);
        }
    }
}

// ------------------------------ pool / pred --------------------------------
__global__ void pool_kernel(const int* __restrict__ batch) {
    int n = blockIdx.x;
    int t = threadIdx.x;
    atomicAdd(&g_pool[batch[n] * HID + t], g_h[n * HID + t]);
}

__global__ void pred_kernel(const float* __restrict__ W1, const float* __restrict__ b1,
                            const float* __restrict__ W2, const float* __restrict__ b2,
                            float* __restrict__ out) {
    __shared__ float sred[128];
    int g = blockIdx.x;
    int t = threadIdx.x;
    float acc = b1[t];
    for (int k = 0; k < HID; k++)
        acc = fmaf(g_pool[g * HID + k], W1[k * HID + t], acc);
    acc = fmaxf(acc, 0.f) * W2[t];
    sred[t] = acc;
    __syncthreads();
    for (int o = 64; o > 0; o >>= 1) {
        if (t < o) sred[t] += sred[t + o];
        __syncthreads();
    }
    if (t == 0) out[g] = sred[0] + b2[0];
}

// ------------------------------ launch -------------------------------------
extern "C" void kernel_launch(void* const* d_in, const int* in_sizes, int n_in,
                              void* d_out, int out_size) {
    const float* x     = (const float*)d_in[0];
    const float* pos   = (const float*)d_in[1];
    const int*   ei    = (const int*)d_in[2];
    const int*   batch = (const int*)d_in[3];
    const float* emb_W = (const float*)d_in[4];
    const float* emb_b = (const float*)d_in[5];

    const float *mW1, *mb1, *mg1, *mbe1, *mW2, *mb2, *mg2, *mbe2;
    const float *uW1, *ub1, *ug1, *ube1, *uW2, *ub2, *ug2, *ube2;

    if (in_sizes[8] == 81920) {
        mW1  = (const float*)d_in[6];  mb1  = (const float*)d_in[7];
        mW2  = (const float*)d_in[8];  mb2  = (const float*)d_in[9];
        uW1  = (const float*)d_in[10]; ub1  = (const float*)d_in[11];
        uW2  = (const float*)d_in[12]; ub2  = (const float*)d_in[13];
        mg1  = (const float*)d_in[14]; mbe1 = (const float*)d_in[15];
        mg2  = (const float*)d_in[16]; mbe2 = (const float*)d_in[17];
        ug1  = (const float*)d_in[18]; ube1 = (const float*)d_in[19];
        ug2  = (const float*)d_in[20]; ube2 = (const float*)d_in[21];
    } else {
        mW1  = (const float*)d_in[6];  mb1  = (const float*)d_in[7];
        mg1  = (const float*)d_in[8];  mbe1 = (const float*)d_in[9];
        mW2  = (const float*)d_in[10]; mb2  = (const float*)d_in[11];
        mg2  = (const float*)d_in[12]; mbe2 = (const float*)d_in[13];
        uW1  = (const float*)d_in[14]; ub1  = (const float*)d_in[15];
        ug1  = (const float*)d_in[16]; ube1 = (const float*)d_in[17];
        uW2  = (const float*)d_in[18]; ub2  = (const float*)d_in[19];
        ug2  = (const float*)d_in[20]; ube2 = (const float*)d_in[21];
    }
    const float* pW1 = (const float*)d_in[22];
    const float* pb1 = (const float*)d_in[23];
    const float* pW2 = (const float*)d_in[24];
    const float* pb2 = (const float*)d_in[25];
    float* out = (float*)d_out;

    __nv_bfloat16 *bm1, *bm2, *bu1, *bu2;
    cudaGetSymbolAddress((void**)&bm1, g_B1);
    cudaGetSymbolAddress((void**)&bm2, g_B2);
    cudaGetSymbolAddress((void**)&bu1, g_BU1);
    cudaGetSymbolAddress((void**)&bu2, g_BU2);

    cudaFuncSetAttribute(msg_mma, cudaFuncAttributeMaxDynamicSharedMemorySize, SMEM_MSG);
    cudaFuncSetAttribute(upd_mma, cudaFuncAttributeMaxDynamicSharedMemorySize, SMEM_MSG);

    // Launch order arranged so msg_mma is the 6th launch (ncu -s 5 -c 1).
    pack_all<<<(2 * (PK16 + PK8) + 255) / 256, 256>>>(mW1, mW2, uW1, uW2,
                                                      bm1, bm2, bu1, bu2);
    dist_kernel<<<(N_EDGES + 255) / 256, 256>>>(pos, ei);
    embed_kernel<<<N_NODES, 128>>>(x, emb_W, emb_b);
    zero_pool_kernel<<<(N_GRAPHS * HID + 255) / 256, 256>>>();

    int msg_blocks = (N_EDGES + 127) / 128;
    int upd_blocks = (N_NODES + 127) / 128;
    for (int l = 0; l < DEPTH; l++) {
        zero_agg_kernel<<<(N_NODES * HID + 255) / 256, 256>>>();
        msg_mma<<<msg_blocks, 256, SMEM_MSG>>>(
            ei,
            bm1 + l * 16 * 4096, bm2 + l * 8 * 4096,
            mW1 + l * 257 * HID + 256 * HID,
            mb1 + l * HID, mg1 + l * HID, mbe1 + l * HID,
            mb2 + l * HID, mg2 + l * HID, mbe2 + l * HID);
        upd_mma<<<upd_blocks, 256, SMEM_MSG>>>(
            bu1 + l * 16 * 4096, bu2 + l * 8 * 4096,
            ub1 + l * HID, ug1 + l * HID, ube1 + l * HID,
            ub2 + l * HID, ug2 + l * HID, ube2 + l * HID);
    }

    pool_kernel<<<N_NODES, 128>>>(batch);
    pred_kernel<<<N_GRAPHS, 128>>>(pW1, pb1, pW2, pb2, out);
}

// round 15
// speedup vs baseline: 2.9713x; 1.0211x over previous
#include <cuda_runtime.h>
#include <cuda_bf16.h>
#include <math.h>
#include <stdint.h>

#define N_NODES 25000
#define N_EDGES 200000
#define HID     128
#define N_GRAPHS 64
#define DEPTH   5
#define NODE_F  16

// ------------------------------ scratch globals ----------------------------
__device__ float g_h[N_NODES * HID];
__device__ float g_agg[N_NODES * HID];
__device__ float g_dist[N_EDGES];
__device__ float g_pool[N_GRAPHS * HID];
// bf16 hi/lo images of h and agg: [node][hi 128 | lo 128]
__device__ __nv_bfloat16 g_hbf[N_NODES * 256];
__device__ __nv_bfloat16 g_aggbf[N_NODES * 256];
// bf16 hi/lo weight images, per chunk (16 k-rows x 128 n): 2048 hi + 2048 lo
__device__ __nv_bfloat16 g_B1[DEPTH * 16 * 4096];   // msg W1 rows 0..255
__device__ __nv_bfloat16 g_B2[DEPTH * 8 * 4096];    // msg W2
__device__ __nv_bfloat16 g_BU1[DEPTH * 16 * 4096];  // upd W1 (256 rows)
__device__ __nv_bfloat16 g_BU2[DEPTH * 8 * 4096];   // upd W2

// ------------------------------ SMEM layout (bytes) ------------------------
#define OFF_A    0          // 2 bufs x (hi 6144 + lo 6144)
#define OFF_A2   0          // hi plane 34816 + lo plane 34816 = 69632
#define OFF_OUT  0          // 128 x 132 fp32 = 67584
#define A2_LO    34816
#define OFF_B    69632      // 2 bufs x (hi 4352 + lo 4352) = 17408
#define OFF_PAR  87040      // 7 x 128 fp32
#define OFF_DST  90624
#define OFF_SRC  91136
#define OFF_DIST 91648
#define SMEM_MSG 92160      // 90 KB; 2 CTAs/SM

// ------------------------------ helpers ------------------------------------
__device__ __forceinline__ uint32_t smem_u32(const void* p) {
    uint32_t a;
    asm("{ .reg .u64 t; cvta.to.shared.u64 t, %1; cvt.u32.u64 %0, t; }" : "=r"(a) : "l"(p));
    return a;
}
__device__ __forceinline__ void ldmA(uint32_t a[4], uint32_t addr) {
    asm volatile("ldmatrix.sync.aligned.m8n8.x4.shared.b16 {%0,%1,%2,%3}, [%4];"
                 : "=r"(a[0]), "=r"(a[1]), "=r"(a[2]), "=r"(a[3]) : "r"(addr));
}
__device__ __forceinline__ void ldmBT(uint32_t b[4], uint32_t addr) {
    asm volatile("ldmatrix.sync.aligned.m8n8.x4.trans.shared.b16 {%0,%1,%2,%3}, [%4];"
                 : "=r"(b[0]), "=r"(b[1]), "=r"(b[2]), "=r"(b[3]) : "r"(addr));
}
__device__ __forceinline__ void mma16816(float c[4], const uint32_t a[4],
                                         uint32_t b0, uint32_t b1) {
    asm volatile("mma.sync.aligned.m16n8k16.row.col.f32.bf16.bf16.f32 "
                 "{%0,%1,%2,%3}, {%4,%5,%6,%7}, {%8,%9}, {%0,%1,%2,%3};"
                 : "+f"(c[0]), "+f"(c[1]), "+f"(c[2]), "+f"(c[3])
                 : "r"(a[0]), "r"(a[1]), "r"(a[2]), "r"(a[3]), "r"(b0), "r"(b1));
}
__device__ __forceinline__ uint32_t pack_bf2(float a, float b) {
    __nv_bfloat162 h = __floats2bfloat162_rn(a, b);
    return *reinterpret_cast<uint32_t*>(&h);
}
__device__ __forceinline__ float bf16f(float v) {
    return __bfloat162float(__float2bfloat16(v));
}
__device__ __forceinline__ void cp16(uint32_t dst, const void* src) {
    asm volatile("cp.async.cg.shared.global [%0], [%1], 16;" :: "r"(dst), "l"(src) : "memory");
}
#define CP_COMMIT() asm volatile("cp.async.commit_group;" ::: "memory")
#define CP_WAIT0()  asm volatile("cp.async.wait_group 0;" ::: "memory")

// ------------------------------ pack kernel (merged) -----------------------
__device__ __forceinline__ void pack_one(const float* __restrict__ W,
                                         __nv_bfloat16* __restrict__ B,
                                         int idx, int rowStride, int Kuse, int nch) {
    int per = nch * 4096;
    int lay = idx / per;
    int rem = idx - lay * per;
    int chunk = rem >> 12;
    int e = rem & 4095;
    int plane = e >> 11;
    int ke = e & 2047;
    int k = ke >> 7, n = ke & 127;
    int kg = chunk * 16 + k;
    float w = (kg < Kuse) ? W[lay * rowStride * HID + kg * HID + n] : 0.f;
    __nv_bfloat16 hi = __float2bfloat16(w);
    B[idx] = plane ? __float2bfloat16(w - __bfloat162float(hi)) : hi;
}

#define PK16 (DEPTH * 16 * 4096)
#define PK8  (DEPTH * 8 * 4096)

__global__ void pack_all(const float* __restrict__ mW1, const float* __restrict__ mW2,
                         const float* __restrict__ uW1, const float* __restrict__ uW2,
                         __nv_bfloat16* __restrict__ B1, __nv_bfloat16* __restrict__ B2,
                         __nv_bfloat16* __restrict__ BU1, __nv_bfloat16* __restrict__ BU2) {
    int idx = blockIdx.x * blockDim.x + threadIdx.x;
    if (idx < PK16) { pack_one(mW1, B1, idx, 257, 256, 16); return; }
    idx -= PK16;
    if (idx < PK8)  { pack_one(mW2, B2, idx, 128, 128, 8); return; }
    idx -= PK8;
    if (idx < PK16) { pack_one(uW1, BU1, idx, 256, 256, 16); return; }
    idx -= PK16;
    if (idx < PK8)  { pack_one(uW2, BU2, idx, 128, 128, 8); }
}

// Convert an fp32 [N_NODES x 128] array into hi/lo bf16 image [node][hi|lo].
__global__ void tobf_kernel(const float* __restrict__ src,
                            __nv_bfloat16* __restrict__ dst) {
    int i = blockIdx.x * blockDim.x + threadIdx.x;
    if (i >= N_NODES * HID) return;
    int node = i >> 7, c = i & 127;
    float v = src[i];
    __nv_bfloat16 hi = __float2bfloat16(v);
    dst[node * 256 + c]       = hi;
    dst[node * 256 + 128 + c] = __float2bfloat16(v - __bfloat162float(hi));
}

// ------------------------------ misc kernels -------------------------------
__global__ void dist_kernel(const float* __restrict__ pos, const int* __restrict__ ei) {
    int e = blockIdx.x * blockDim.x + threadIdx.x;
    if (e >= N_EDGES) return;
    int s = ei[e];
    int d = ei[N_EDGES + e];
    float dx = pos[d * 3 + 0] - pos[s * 3 + 0];
    float dy = pos[d * 3 + 1] - pos[s * 3 + 1];
    float dz = pos[d * 3 + 2] - pos[s * 3 + 2];
    g_dist[e] = sqrtf(dx * dx + dy * dy + dz * dz);
}

__global__ void embed_kernel(const float* __restrict__ x,
                             const float* __restrict__ W,
                             const float* __restrict__ b) {
    int n = blockIdx.x;
    int t = threadIdx.x;
    float acc = b[t];
#pragma unroll
    for (int k = 0; k < NODE_F; k++)
        acc = fmaf(x[n * NODE_F + k], W[k * HID + t], acc);
    g_h[n * HID + t] = acc;
}

__global__ void zero_agg_kernel() {
    int i = blockIdx.x * blockDim.x + threadIdx.x;
    if (i < N_NODES * HID) g_agg[i] = 0.f;
}
__global__ void zero_pool_kernel() {
    int i = blockIdx.x * blockDim.x + threadIdx.x;
    if (i < N_GRAPHS * HID) g_pool[i] = 0.f;
}

// ---------------------- async staging device fns ---------------------------
// B chunk image (linear 4096 bf16) -> padded SMEM (k*136+n), via cp.async.
__device__ __forceinline__ void stageB_cp(uint32_t smb, int tid,
                                          const __nv_bfloat16* __restrict__ img, int buf) {
    uint32_t dst = smb + OFF_B + buf * 8704;
#pragma unroll
    for (int jj = 0; jj < 2; jj++) {
        int e8 = tid * 2 + jj;          // 512 groups of 8 bf16
        int plane = e8 >> 8;
        int ge = e8 & 255;
        int k = ge >> 4, n = (ge & 15) * 8;
        cp16(dst + plane * 4352 + k * 272 + n * 2, img + e8 * 8);
    }
}

// A chunk: 16 bf16 cols per row from a node's hi/lo image, via cp.async.
// 2 threads per row; thread handles 8 cols (16B) of both planes.
__device__ __forceinline__ void stageA_cp(uint32_t smb, int buf, int row, int half,
                                          const __nv_bfloat16* __restrict__ nodeimg,
                                          int kseg) {
    const __nv_bfloat16* src = nodeimg + kseg * 16 + half * 8;
    uint32_t dst = smb + OFF_A + buf * 12288 + row * 48 + half * 16;
    cp16(dst, src);                  // hi plane
    cp16(dst + 6144, src + 128);     // lo plane
}

// epilogue LN result -> A2 SMEM image (bf16 hi/lo, row stride 272B)
__device__ __forceinline__ void a2_write(char* sm, int row, int col,
                                         float v0, float v1) {
    float h0 = bf16f(v0), h1 = bf16f(v1);
    int off = row * 272 + col * 2;
    *(uint32_t*)(sm + OFF_A2 + off)         = pack_bf2(v0, v1);
    *(uint32_t*)(sm + OFF_A2 + A2_LO + off) = pack_bf2(v0 - h0, v1 - h1);
}

// ------------------------------ msg_mma kernel -----------------------------
// 128 edges/block, 256 threads (8 warps, warp w owns rows 16w..16w+15).
__global__ void __launch_bounds__(256, 2) msg_mma(
    const int* __restrict__ ei,
    const __nv_bfloat16* __restrict__ B1, const __nv_bfloat16* __restrict__ B2,
    const float* __restrict__ W1d,
    const float* __restrict__ b1, const float* __restrict__ g1, const float* __restrict__ be1,
    const float* __restrict__ b2, const float* __restrict__ g2, const float* __restrict__ be2) {
    extern __shared__ char sm[];
    uint32_t smb = smem_u32(sm);
    int tid = threadIdx.x;
    int w = tid >> 5, l = tid & 31;
    int e0 = blockIdx.x * 128;

    int* sDst = (int*)(sm + OFF_DST);
    int* sSrc = (int*)(sm + OFF_SRC);
    float* sDist = (float*)(sm + OFF_DIST);
    float* sPar = (float*)(sm + OFF_PAR);
    if (tid < 128) {
        sPar[tid]       = b1[tid];
        sPar[128 + tid] = g1[tid];
        sPar[256 + tid] = be1[tid];
        sPar[384 + tid] = b2[tid];
        sPar[512 + tid] = g2[tid];
        sPar[640 + tid] = be2[tid];
        sPar[768 + tid] = W1d[tid];
        int ec = min(e0 + tid, N_EDGES - 1);
        sSrc[tid] = ei[ec];
        sDst[tid] = ei[N_EDGES + ec];
        sDist[tid] = g_dist[ec];
    }
    __syncthreads();

    int rowS = tid >> 1, halfS = tid & 1;
    auto stageA = [&](int kc, int buf) {
        int node = (kc < 8 ? sDst : sSrc)[rowS];
        stageA_cp(smb, buf, rowS, halfS, g_hbf + (size_t)node * 256, kc & 7);
    };

    // ---- GEMM1: [128 x 256] @ [256 x 128] over 16 K-chunks ----
    float C[16][4];
#pragma unroll
    for (int n = 0; n < 16; n++)
#pragma unroll
        for (int j = 0; j < 4; j++) C[n][j] = 0.f;

    stageA(0, 0);
    stageB_cp(smb, tid, B1, 0);
    CP_COMMIT();
    CP_WAIT0();
    __syncthreads();
    uint32_t aoff = ((16 * w + (l & 15)) * 24 + (l >> 4) * 8) * 2;
    uint32_t boff = (((l & 7) + 8 * ((l >> 3) & 1)) * 136 + 8 * (l >> 4)) * 2;

#pragma unroll 1
    for (int kc = 0; kc < 16; kc++) {
        int buf = kc & 1;
        if (kc + 1 < 16) {
            stageA(kc + 1, buf ^ 1);
            stageB_cp(smb, tid, B1 + (kc + 1) * 4096, buf ^ 1);
            CP_COMMIT();
        }
        uint32_t Ah[4], Al[4];
        uint32_t abase = smb + OFF_A + buf * 12288 + aoff;
        ldmA(Ah, abase);
        ldmA(Al, abase + 6144);
        uint32_t bbase = smb + OFF_B + buf * 8704 + boff;
#pragma unroll
        for (int np = 0; np < 8; np++) {
            uint32_t Bh[4], Bl[4];
            uint32_t ba = bbase + np * 32;
            ldmBT(Bh, ba);
            ldmBT(Bl, ba + 4352);
            mma16816(C[2 * np],     Ah, Bh[0], Bh[1]);
            mma16816(C[2 * np],     Ah, Bl[0], Bl[1]);
            mma16816(C[2 * np],     Al, Bh[0], Bh[1]);
            mma16816(C[2 * np + 1], Ah, Bh[2], Bh[3]);
            mma16816(C[2 * np + 1], Ah, Bl[2], Bl[3]);
            mma16816(C[2 * np + 1], Al, Bh[2], Bh[3]);
        }
        CP_WAIT0();
        __syncthreads();
    }

    // ---- epilogue1: dist rank-1 + bias + LN + ReLU -> A2 SMEM image ----
    int r0 = 16 * w + (l >> 2), r1 = r0 + 8;
    int q2 = 2 * (l & 3);
    float d0 = sDist[r0], d1 = sDist[r1];
    float s0 = 0.f, s20 = 0.f, s1 = 0.f, s21 = 0.f;
#pragma unroll
    for (int n = 0; n < 16; n++) {
        int col = n * 8 + q2;
        float wd0 = sPar[768 + col], wd1 = sPar[768 + col + 1];
        float bb0 = sPar[col], bb1 = sPar[col + 1];
        C[n][0] += d0 * wd0 + bb0;
        C[n][1] += d0 * wd1 + bb1;
        C[n][2] += d1 * wd0 + bb0;
        C[n][3] += d1 * wd1 + bb1;
        s0 += C[n][0] + C[n][1]; s20 += C[n][0] * C[n][0] + C[n][1] * C[n][1];
        s1 += C[n][2] + C[n][3]; s21 += C[n][2] * C[n][2] + C[n][3] * C[n][3];
    }
    s0 += __shfl_xor_sync(0xffffffffu, s0, 1); s0 += __shfl_xor_sync(0xffffffffu, s0, 2);
    s20 += __shfl_xor_sync(0xffffffffu, s20, 1); s20 += __shfl_xor_sync(0xffffffffu, s20, 2);
    s1 += __shfl_xor_sync(0xffffffffu, s1, 1); s1 += __shfl_xor_sync(0xffffffffu, s1, 2);
    s21 += __shfl_xor_sync(0xffffffffu, s21, 1); s21 += __shfl_xor_sync(0xffffffffu, s21, 2);
    float mn0 = s0 * (1.f / 128.f), vr0 = fmaxf(s20 * (1.f / 128.f) - mn0 * mn0, 0.f);
    float mn1 = s1 * (1.f / 128.f), vr1 = fmaxf(s21 * (1.f / 128.f) - mn1 * mn1, 0.f);
    float rs0 = rsqrtf(vr0 + 1e-5f), rs1 = rsqrtf(vr1 + 1e-5f);

#pragma unroll
    for (int n = 0; n < 16; n++) {
        int col = n * 8 + q2;
        float ga = sPar[128 + col], gb = sPar[128 + col + 1];
        float ba = sPar[256 + col], bb = sPar[256 + col + 1];
        a2_write(sm, r0, col, fmaxf(fmaf((C[n][0] - mn0) * rs0, ga, ba), 0.f),
                              fmaxf(fmaf((C[n][1] - mn0) * rs0, gb, bb), 0.f));
        a2_write(sm, r1, col, fmaxf(fmaf((C[n][2] - mn1) * rs1, ga, ba), 0.f),
                              fmaxf(fmaf((C[n][3] - mn1) * rs1, gb, bb), 0.f));
    }

    // ---- GEMM2: [128 x 128] @ [128 x 128], A2 from SMEM ----
    float C2[16][4];
#pragma unroll
    for (int n = 0; n < 16; n++)
#pragma unroll
        for (int j = 0; j < 4; j++) C2[n][j] = 0.f;

    stageB_cp(smb, tid, B2, 0);
    CP_COMMIT();
    CP_WAIT0();
    __syncthreads();
    uint32_t a2row = smb + OFF_A2 + (16 * w + (l & 15)) * 272 + (l >> 4) * 16;
#pragma unroll
    for (int kc = 0; kc < 8; kc++) {
        int buf = kc & 1;
        if (kc + 1 < 8) { stageB_cp(smb, tid, B2 + (kc + 1) * 4096, buf ^ 1); CP_COMMIT(); }
        uint32_t A2h[4], A2l[4];
        uint32_t a2base = a2row + kc * 32;
        ldmA(A2h, a2base);
        ldmA(A2l, a2base + A2_LO);
        uint32_t bbase = smb + OFF_B + buf * 8704 + boff;
#pragma unroll
        for (int np = 0; np < 8; np++) {
            uint32_t Bh[4], Bl[4];
            uint32_t ba = bbase + np * 32;
            ldmBT(Bh, ba);
            ldmBT(Bl, ba + 4352);
            mma16816(C2[2 * np],     A2h, Bh[0], Bh[1]);
            mma16816(C2[2 * np],     A2h, Bl[0], Bl[1]);
            mma16816(C2[2 * np],     A2l, Bh[0], Bh[1]);
            mma16816(C2[2 * np + 1], A2h, Bh[2], Bh[3]);
            mma16816(C2[2 * np + 1], A2h, Bl[2], Bl[3]);
            mma16816(C2[2 * np + 1], A2l, Bh[2], Bh[3]);
        }
        CP_WAIT0();
        __syncthreads();
    }

    // ---- epilogue2: bias + LN + ReLU -> SMEM -> coalesced atomic scatter ----
    s0 = 0.f; s20 = 0.f; s1 = 0.f; s21 = 0.f;
#pragma unroll
    for (int n = 0; n < 16; n++) {
        int col = n * 8 + q2;
        float bb0 = sPar[384 + col], bb1 = sPar[384 + col + 1];
        C2[n][0] += bb0; C2[n][1] += bb1; C2[n][2] += bb0; C2[n][3] += bb1;
        s0 += C2[n][0] + C2[n][1]; s20 += C2[n][0] * C2[n][0] + C2[n][1] * C2[n][1];
        s1 += C2[n][2] + C2[n][3]; s21 += C2[n][2] * C2[n][2] + C2[n][3] * C2[n][3];
    }
    s0 += __shfl_xor_sync(0xffffffffu, s0, 1); s0 += __shfl_xor_sync(0xffffffffu, s0, 2);
    s20 += __shfl_xor_sync(0xffffffffu, s20, 1); s20 += __shfl_xor_sync(0xffffffffu, s20, 2);
    s1 += __shfl_xor_sync(0xffffffffu, s1, 1); s1 += __shfl_xor_sync(0xffffffffu, s1, 2);
    s21 += __shfl_xor_sync(0xffffffffu, s21, 1); s21 += __shfl_xor_sync(0xffffffffu, s21, 2);
    mn0 = s0 * (1.f / 128.f); vr0 = fmaxf(s20 * (1.f / 128.f) - mn0 * mn0, 0.f);
    mn1 = s1 * (1.f / 128.f); vr1 = fmaxf(s21 * (1.f / 128.f) - mn1 * mn1, 0.f);
    rs0 = rsqrtf(vr0 + 1e-5f); rs1 = rsqrtf(vr1 + 1e-5f);

    float* sOut = (float*)(sm + OFF_OUT);
#pragma unroll
    for (int n = 0; n < 16; n++) {
        int col = n * 8 + q2;
        float ga = sPar[512 + col], gb = sPar[512 + col + 1];
        float ba = sPar[640 + col], bb = sPar[640 + col + 1];
        float v0 = fmaxf(fmaf((C2[n][0] - mn0) * rs0, ga, ba), 0.f);
        float v1 = fmaxf(fmaf((C2[n][1] - mn0) * rs0, gb, bb), 0.f);
        float v2 = fmaxf(fmaf((C2[n][2] - mn1) * rs1, ga, ba), 0.f);
        float v3 = fmaxf(fmaf((C2[n][3] - mn1) * rs1, gb, bb), 0.f);
        *(float2*)&sOut[r0 * 132 + col] = make_float2(v0, v1);
        *(float2*)&sOut[r1 * 132 + col] = make_float2(v2, v3);
    }
    __syncthreads();

    int col = tid & 127;
    int half = tid >> 7;
#pragma unroll 4
    for (int i = 0; i < 64; i++) {
        int row = half * 64 + i;
        if (e0 + row < N_EDGES)
            atomicAdd(&g_agg[sDst[row] * HID + col], sOut[row * 132 + col]);
    }
}

// ------------------------------ upd_mma kernel -----------------------------
// 128 nodes/block; K=256 = 8 chunks of h + 8 chunks of agg; residual output.
__global__ void __launch_bounds__(256, 2) upd_mma(
    const __nv_bfloat16* __restrict__ B1, const __nv_bfloat16* __restrict__ B2,
    const float* __restrict__ b1, const float* __restrict__ g1, const float* __restrict__ be1,
    const float* __restrict__ b2, const float* __restrict__ g2, const float* __restrict__ be2) {
    extern __shared__ char sm[];
    uint32_t smb = smem_u32(sm);
    int tid = threadIdx.x;
    int w = tid >> 5, l = tid & 31;
    int n0 = blockIdx.x * 128;

    float* sPar = (float*)(sm + OFF_PAR);
    if (tid < 128) {
        sPar[tid]       = b1[tid];
        sPar[128 + tid] = g1[tid];
        sPar[256 + tid] = be1[tid];
        sPar[384 + tid] = b2[tid];
        sPar[512 + tid] = g2[tid];
        sPar[640 + tid] = be2[tid];
    }
    __syncthreads();

    int rowS = tid >> 1, halfS = tid & 1;
    int nodeS = min(n0 + rowS, N_NODES - 1);
    auto stageA = [&](int kc, int buf) {
        const __nv_bfloat16* base = (kc < 8) ? g_hbf : g_aggbf;
        stageA_cp(smb, buf, rowS, halfS, base + (size_t)nodeS * 256, kc & 7);
    };

    // ---- GEMM1 ----
    float C[16][4];
#pragma unroll
    for (int n = 0; n < 16; n++)
#pragma unroll
        for (int j = 0; j < 4; j++) C[n][j] = 0.f;

    stageA(0, 0);
    stageB_cp(smb, tid, B1, 0);
    CP_COMMIT();
    CP_WAIT0();
    __syncthreads();
    uint32_t aoff = ((16 * w + (l & 15)) * 24 + (l >> 4) * 8) * 2;
    uint32_t boff = (((l & 7) + 8 * ((l >> 3) & 1)) * 136 + 8 * (l >> 4)) * 2;

#pragma unroll 1
    for (int kc = 0; kc < 16; kc++) {
        int buf = kc & 1;
        if (kc + 1 < 16) {
            stageA(kc + 1, buf ^ 1);
            stageB_cp(smb, tid, B1 + (kc + 1) * 4096, buf ^ 1);
            CP_COMMIT();
        }
        uint32_t Ah[4], Al[4];
        uint32_t abase = smb + OFF_A + buf * 12288 + aoff;
        ldmA(Ah, abase);
        ldmA(Al, abase + 6144);
        uint32_t bbase = smb + OFF_B + buf * 8704 + boff;
#pragma unroll
        for (int np = 0; np < 8; np++) {
            uint32_t Bh[4], Bl[4];
            uint32_t ba = bbase + np * 32;
            ldmBT(Bh, ba);
            ldmBT(Bl, ba + 4352);
            mma16816(C[2 * np],     Ah, Bh[0], Bh[1]);
            mma16816(C[2 * np],     Ah, Bl[0], Bl[1]);
            mma16816(C[2 * np],     Al, Bh[0], Bh[1]);
            mma16816(C[2 * np + 1], Ah, Bh[2], Bh[3]);
            mma16816(C[2 * np + 1], Ah, Bl[2], Bl[3]);
            mma16816(C[2 * np + 1], Al, Bh[2], Bh[3]);
        }
        CP_WAIT0();
        __syncthreads();
    }

    // ---- epilogue1: bias + LN + ReLU -> A2 SMEM image ----
    int r0 = 16 * w + (l >> 2), r1 = r0 + 8;
    int q2 = 2 * (l & 3);
    float s0 = 0.f, s20 = 0.f, s1 = 0.f, s21 = 0.f;
#pragma unroll
    for (int n = 0; n < 16; n++) {
        int col = n * 8 + q2;
        float bb0 = sPar[col], bb1 = sPar[col + 1];
        C[n][0] += bb0; C[n][1] += bb1; C[n][2] += bb0; C[n][3] += bb1;
        s0 += C[n][0] + C[n][1]; s20 += C[n][0] * C[n][0] + C[n][1] * C[n][1];
        s1 += C[n][2] + C[n][3]; s21 += C[n][2] * C[n][2] + C[n][3] * C[n][3];
    }
    s0 += __shfl_xor_sync(0xffffffffu, s0, 1); s0 += __shfl_xor_sync(0xffffffffu, s0, 2);
    s20 += __shfl_xor_sync(0xffffffffu, s20, 1); s20 += __shfl_xor_sync(0xffffffffu, s20, 2);
    s1 += __shfl_xor_sync(0xffffffffu, s1, 1); s1 += __shfl_xor_sync(0xffffffffu, s1, 2);
    s21 += __shfl_xor_sync(0xffffffffu, s21, 1); s21 += __shfl_xor_sync(0xffffffffu, s21, 2);
    float mn0 = s0 * (1.f / 128.f), vr0 = fmaxf(s20 * (1.f / 128.f) - mn0 * mn0, 0.f);
    float mn1 = s1 * (1.f / 128.f), vr1 = fmaxf(s21 * (1.f / 128.f) - mn1 * mn1, 0.f);
    float rs0 = rsqrtf(vr0 + 1e-5f), rs1 = rsqrtf(vr1 + 1e-5f);

#pragma unroll
    for (int n = 0; n < 16; n++) {
        int col = n * 8 + q2;
        float ga = sPar[128 + col], gb = sPar[128 + col + 1];
        float ba = sPar[256 + col], bb = sPar[256 + col + 1];
        a2_write(sm, r0, col, fmaxf(fmaf((C[n][0] - mn0) * rs0, ga, ba), 0.f),
                              fmaxf(fmaf((C[n][1] - mn0) * rs0, gb, bb), 0.f));
        a2_write(sm, r1, col, fmaxf(fmaf((C[n][2] - mn1) * rs1, ga, ba), 0.f),
                              fmaxf(fmaf((C[n][3] - mn1) * rs1, gb, bb), 0.f));
    }

    // ---- GEMM2 ----
    float C2[16][4];
#pragma unroll
    for (int n = 0; n < 16; n++)
#pragma unroll
        for (int j = 0; j < 4; j++) C2[n][j] = 0.f;

    stageB_cp(smb, tid, B2, 0);
    CP_COMMIT();
    CP_WAIT0();
    __syncthreads();
    uint32_t a2row = smb + OFF_A2 + (16 * w + (l & 15)) * 272 + (l >> 4) * 16;
#pragma unroll
    for (int kc = 0; kc < 8; kc++) {
        int buf = kc & 1;
        if (kc + 1 < 8) { stageB_cp(smb, tid, B2 + (kc + 1) * 4096, buf ^ 1); CP_COMMIT(); }
        uint32_t A2h[4], A2l[4];
        uint32_t a2base = a2row + kc * 32;
        ldmA(A2h, a2base);
        ldmA(A2l, a2base + A2_LO);
        uint32_t bbase = smb + OFF_B + buf * 8704 + boff;
#pragma unroll
        for (int np = 0; np < 8; np++) {
            uint32_t Bh[4], Bl[4];
            uint32_t ba = bbase + np * 32;
            ldmBT(Bh, ba);
            ldmBT(Bl, ba + 4352);
            mma16816(C2[2 * np],     A2h, Bh[0], Bh[1]);
            mma16816(C2[2 * np],     A2h, Bl[0], Bl[1]);
            mma16816(C2[2 * np],     A2l, Bh[0], Bh[1]);
            mma16816(C2[2 * np + 1], A2h, Bh[2], Bh[3]);
            mma16816(C2[2 * np + 1], A2h, Bl[2], Bl[3]);
            mma16816(C2[2 * np + 1], A2l, Bh[2], Bh[3]);
        }
        CP_WAIT0();
        __syncthreads();
    }

    // ---- epilogue2: bias + LN + ReLU + residual -> g_h ----
    s0 = 0.f; s20 = 0.f; s1 = 0.f; s21 = 0.f;
#pragma unroll
    for (int n = 0; n < 16; n++) {
        int col = n * 8 + q2;
        float bb0 = sPar[384 + col], bb1 = sPar[384 + col + 1];
        C2[n][0] += bb0; C2[n][1] += bb1; C2[n][2] += bb0; C2[n][3] += bb1;
        s0 += C2[n][0] + C2[n][1]; s20 += C2[n][0] * C2[n][0] + C2[n][1] * C2[n][1];
        s1 += C2[n][2] + C2[n][3]; s21 += C2[n][2] * C2[n][2] + C2[n][3] * C2[n][3];
    }
    s0 += __shfl_xor_sync(0xffffffffu, s0, 1); s0 += __shfl_xor_sync(0xffffffffu, s0, 2);
    s20 += __shfl_xor_sync(0xffffffffu, s20, 1); s20 += __shfl_xor_sync(0xffffffffu, s20, 2);
    s1 += __shfl_xor_sync(0xffffffffu, s1, 1); s1 += __shfl_xor_sync(0xffffffffu, s1, 2);
    s21 += __shfl_xor_sync(0xffffffffu, s21, 1); s21 += __shfl_xor_sync(0xffffffffu, s21, 2);
    mn0 = s0 * (1.f / 128.f); vr0 = fmaxf(s20 * (1.f / 128.f) - mn0 * mn0, 0.f);
    mn1 = s1 * (1.f / 128.f); vr1 = fmaxf(s21 * (1.f / 128.f) - mn1 * mn1, 0.f);
    rs0 = rsqrtf(vr0 + 1e-5f); rs1 = rsqrtf(vr1 + 1e-5f);

    int nrow0 = n0 + r0, nrow1 = n0 + r1;
#pragma unroll
    for (int n = 0; n < 16; n++) {
        int col = n * 8 + q2;
        float ga = sPar[512 + col], gb = sPar[512 + col + 1];
        float ba = sPar[640 + col], bb = sPar[640 + col + 1];
        if (nrow0 < N_NODES) {
            float v0 = fmaxf(fmaf((C2[n][0] - mn0) * rs0, ga, ba), 0.f);
            float v1 = fmaxf(fmaf((C2[n][1] - mn0) * rs0, gb, bb), 0.f);
            float2 old = *(float2*)&g_h[(size_t)nrow0 * HID + col];
            *(float2*)&g_h[(size_t)nrow0 * HID + col] = make_float2(old.x + v0, old.y + v1);
        }
        if (nrow1 < N_NODES) {
            float v2 = fmaxf(fmaf((C2[n][2] - mn1) * rs1, ga, ba), 0.f);
            float v3 = fmaxf(fmaf((C2[n][3] - mn1) * rs1, gb, bb), 0.f);
            float2 old = *(float2*)&g_h[(size_t)nrow1 * HID + col];
            *(float2*)&g_h[(size_t)nrow1 * HID + col] = make_float2(old.x + v2, old.y + v3);
        }
    }
}

// ------------------------------ pool / pred --------------------------------
__global__ void pool_kernel(const int* __restrict__ batch) {
    int n = blockIdx.x;
    int t = threadIdx.x;
    atomicAdd(&g_pool[batch[n] * HID + t], g_h[n * HID + t]);
}

__global__ void pred_kernel(const float* __restrict__ W1, const float* __restrict__ b1,
                            const float* __restrict__ W2, const float* __restrict__ b2,
                            float* __restrict__ out) {
    __shared__ float sred[128];
    int g = blockIdx.x;
    int t = threadIdx.x;
    float acc = b1[t];
    for (int k = 0; k < HID; k++)
        acc = fmaf(g_pool[g * HID + k], W1[k * HID + t], acc);
    acc = fmaxf(acc, 0.f) * W2[t];
    sred[t] = acc;
    __syncthreads();
    for (int o = 64; o > 0; o >>= 1) {
        if (t < o) sred[t] += sred[t + o];
        __syncthreads();
    }
    if (t == 0) out[g] = sred[0] + b2[0];
}

// ------------------------------ launch -------------------------------------
extern "C" void kernel_launch(void* const* d_in, const int* in_sizes, int n_in,
                              void* d_out, int out_size) {
    const float* x     = (const float*)d_in[0];
    const float* pos   = (const float*)d_in[1];
    const int*   ei    = (const int*)d_in[2];
    const int*   batch = (const int*)d_in[3];
    const float* emb_W = (const float*)d_in[4];
    const float* emb_b = (const float*)d_in[5];

    const float *mW1, *mb1, *mg1, *mbe1, *mW2, *mb2, *mg2, *mbe2;
    const float *uW1, *ub1, *ug1, *ube1, *uW2, *ub2, *ug2, *ube2;

    if (in_sizes[8] == 81920) {
        mW1  = (const float*)d_in[6];  mb1  = (const float*)d_in[7];
        mW2  = (const float*)d_in[8];  mb2  = (const float*)d_in[9];
        uW1  = (const float*)d_in[10]; ub1  = (const float*)d_in[11];
        uW2  = (const float*)d_in[12]; ub2  = (const float*)d_in[13];
        mg1  = (const float*)d_in[14]; mbe1 = (const float*)d_in[15];
        mg2  = (const float*)d_in[16]; mbe2 = (const float*)d_in[17];
        ug1  = (const float*)d_in[18]; ube1 = (const float*)d_in[19];
        ug2  = (const float*)d_in[20]; ube2 = (const float*)d_in[21];
    } else {
        mW1  = (const float*)d_in[6];  mb1  = (const float*)d_in[7];
        mg1  = (const float*)d_in[8];  mbe1 = (const float*)d_in[9];
        mW2  = (const float*)d_in[10]; mb2  = (const float*)d_in[11];
        mg2  = (const float*)d_in[12]; mbe2 = (const float*)d_in[13];
        uW1  = (const float*)d_in[14]; ub1  = (const float*)d_in[15];
        ug1  = (const float*)d_in[16]; ube1 = (const float*)d_in[17];
        uW2  = (const float*)d_in[18]; ub2  = (const float*)d_in[19];
        ug2  = (const float*)d_in[20]; ube2 = (const float*)d_in[21];
    }
    const float* pW1 = (const float*)d_in[22];
    const float* pb1 = (const float*)d_in[23];
    const float* pW2 = (const float*)d_in[24];
    const float* pb2 = (const float*)d_in[25];
    float* out = (float*)d_out;

    __nv_bfloat16 *bm1, *bm2, *bu1, *bu2, *hbf, *aggbf;
    float *gh, *gagg;
    cudaGetSymbolAddress((void**)&bm1, g_B1);
    cudaGetSymbolAddress((void**)&bm2, g_B2);
    cudaGetSymbolAddress((void**)&bu1, g_BU1);
    cudaGetSymbolAddress((void**)&bu2, g_BU2);
    cudaGetSymbolAddress((void**)&hbf, g_hbf);
    cudaGetSymbolAddress((void**)&aggbf, g_aggbf);
    cudaGetSymbolAddress((void**)&gh, g_h);
    cudaGetSymbolAddress((void**)&gagg, g_agg);

    cudaFuncSetAttribute(msg_mma, cudaFuncAttributeMaxDynamicSharedMemorySize, SMEM_MSG);
    cudaFuncSetAttribute(upd_mma, cudaFuncAttributeMaxDynamicSharedMemorySize, SMEM_MSG);

    pack_all<<<(2 * (PK16 + PK8) + 255) / 256, 256>>>(mW1, mW2, uW1, uW2,
                                                      bm1, bm2, bu1, bu2);
    dist_kernel<<<(N_EDGES + 255) / 256, 256>>>(pos, ei);
    embed_kernel<<<N_NODES, 128>>>(x, emb_W, emb_b);
    zero_pool_kernel<<<(N_GRAPHS * HID + 255) / 256, 256>>>();

    int msg_blocks = (N_EDGES + 127) / 128;
    int upd_blocks = (N_NODES + 127) / 128;
    int conv_blocks = (N_NODES * HID + 255) / 256;
    for (int l = 0; l < DEPTH; l++) {
        zero_agg_kernel<<<conv_blocks, 256>>>();
        tobf_kernel<<<conv_blocks, 256>>>(gh, hbf);
        msg_mma<<<msg_blocks, 256, SMEM_MSG>>>(
            ei,
            bm1 + l * 16 * 4096, bm2 + l * 8 * 4096,
            mW1 + l * 257 * HID + 256 * HID,
            mb1 + l * HID, mg1 + l * HID, mbe1 + l * HID,
            mb2 + l * HID, mg2 + l * HID, mbe2 + l * HID);
        tobf_kernel<<<conv_blocks, 256>>>(gagg, aggbf);
        upd_mma<<<upd_blocks, 256, SMEM_MSG>>>(
            bu1 + l * 16 * 4096, bu2 + l * 8 * 4096,
            ub1 + l * HID, ug1 + l * HID, ube1 + l * HID,
            ub2 + l * HID, ug2 + l * HID, ube2 + l * HID);
    }

    pool_kernel<<<N_NODES, 128>>>(batch);
    pred_kernel<<<N_GRAPHS, 128>>>(pW1, pb1, pW2, pb2, out);
}

// round 16
// speedup vs baseline: 3.1282x; 1.0528x over previous
#include <cuda_runtime.h>
#include <cuda_bf16.h>
#include <math.h>
#include <stdint.h>

#define N_NODES 25000
#define N_EDGES 200000
#define HID     128
#define N_GRAPHS 64
#define DEPTH   5
#define NODE_F  16

// ------------------------------ scratch globals ----------------------------
__device__ float g_h[N_NODES * HID];
__device__ float g_agg[N_NODES * HID];
__device__ float g_dist[N_EDGES];
__device__ float g_pool[N_GRAPHS * HID];
__device__ __nv_bfloat16 g_hbf[N_NODES * 256];
__device__ __nv_bfloat16 g_aggbf[N_NODES * 256];
__device__ __nv_bfloat16 g_B1[DEPTH * 16 * 4096];
__device__ __nv_bfloat16 g_B2[DEPTH * 8 * 4096];
__device__ __nv_bfloat16 g_BU1[DEPTH * 16 * 4096];
__device__ __nv_bfloat16 g_BU2[DEPTH * 8 * 4096];

// ------------------------------ SMEM layout (bytes) ------------------------
#define OFF_A    0          // 2 bufs x (hi 6144 + lo 6144)
#define OFF_A2   0          // hi 34816 + lo 34816 = 69632 (after GEMM1)
#define OFF_OUT  0          // 128 x 132 fp32 (after GEMM2)
#define A2_LO    34816
#define OFF_B    69632      // 2 bufs x (hi 4352 + lo 4352)
#define OFF_PAR  87040      // 7 x 128 fp32
#define OFF_DST  90624
#define OFF_SRC  91136
#define OFF_DIST 91648
#define OFF_RED  92160      // 128 rows x 4 fp32 (cross-warp LN partials)
#define OFF_MV   94208      // 128 rows x 2 fp32 (mean, rstd)
#define SMEM_MSG 95232      // 93 KB; 2 CTAs/SM = 186 KB

// ------------------------------ helpers ------------------------------------
__device__ __forceinline__ uint32_t smem_u32(const void* p) {
    uint32_t a;
    asm("{ .reg .u64 t; cvta.to.shared.u64 t, %1; cvt.u32.u64 %0, t; }" : "=r"(a) : "l"(p));
    return a;
}
__device__ __forceinline__ void ldmA(uint32_t a[4], uint32_t addr) {
    asm volatile("ldmatrix.sync.aligned.m8n8.x4.shared.b16 {%0,%1,%2,%3}, [%4];"
                 : "=r"(a[0]), "=r"(a[1]), "=r"(a[2]), "=r"(a[3]) : "r"(addr));
}
__device__ __forceinline__ void ldmBT(uint32_t b[4], uint32_t addr) {
    asm volatile("ldmatrix.sync.aligned.m8n8.x4.trans.shared.b16 {%0,%1,%2,%3}, [%4];"
                 : "=r"(b[0]), "=r"(b[1]), "=r"(b[2]), "=r"(b[3]) : "r"(addr));
}
__device__ __forceinline__ void mma16816(float c[4], const uint32_t a[4],
                                         uint32_t b0, uint32_t b1) {
    asm volatile("mma.sync.aligned.m16n8k16.row.col.f32.bf16.bf16.f32 "
                 "{%0,%1,%2,%3}, {%4,%5,%6,%7}, {%8,%9}, {%0,%1,%2,%3};"
                 : "+f"(c[0]), "+f"(c[1]), "+f"(c[2]), "+f"(c[3])
                 : "r"(a[0]), "r"(a[1]), "r"(a[2]), "r"(a[3]), "r"(b0), "r"(b1));
}
__device__ __forceinline__ uint32_t pack_bf2(float a, float b) {
    __nv_bfloat162 h = __floats2bfloat162_rn(a, b);
    return *reinterpret_cast<uint32_t*>(&h);
}
__device__ __forceinline__ float bf16f(float v) {
    return __bfloat162float(__float2bfloat16(v));
}
__device__ __forceinline__ void cp16(uint32_t dst, const void* src) {
    asm volatile("cp.async.cg.shared.global [%0], [%1], 16;" :: "r"(dst), "l"(src) : "memory");
}
#define CP_COMMIT() asm volatile("cp.async.commit_group;" ::: "memory")
#define CP_WAIT0()  asm volatile("cp.async.wait_group 0;" ::: "memory")

// ------------------------------ pack kernel (merged) -----------------------
__device__ __forceinline__ void pack_one(const float* __restrict__ W,
                                         __nv_bfloat16* __restrict__ B,
                                         int idx, int rowStride, int Kuse, int nch) {
    int per = nch * 4096;
    int lay = idx / per;
    int rem = idx - lay * per;
    int chunk = rem >> 12;
    int e = rem & 4095;
    int plane = e >> 11;
    int ke = e & 2047;
    int k = ke >> 7, n = ke & 127;
    int kg = chunk * 16 + k;
    float w = (kg < Kuse) ? W[lay * rowStride * HID + kg * HID + n] : 0.f;
    __nv_bfloat16 hi = __float2bfloat16(w);
    B[idx] = plane ? __float2bfloat16(w - __bfloat162float(hi)) : hi;
}

#define PK16 (DEPTH * 16 * 4096)
#define PK8  (DEPTH * 8 * 4096)

__global__ void pack_all(const float* __restrict__ mW1, const float* __restrict__ mW2,
                         const float* __restrict__ uW1, const float* __restrict__ uW2,
                         __nv_bfloat16* __restrict__ B1, __nv_bfloat16* __restrict__ B2,
                         __nv_bfloat16* __restrict__ BU1, __nv_bfloat16* __restrict__ BU2) {
    int idx = blockIdx.x * blockDim.x + threadIdx.x;
    if (idx < PK16) { pack_one(mW1, B1, idx, 257, 256, 16); return; }
    idx -= PK16;
    if (idx < PK8)  { pack_one(mW2, B2, idx, 128, 128, 8); return; }
    idx -= PK8;
    if (idx < PK16) { pack_one(uW1, BU1, idx, 256, 256, 16); return; }
    idx -= PK16;
    if (idx < PK8)  { pack_one(uW2, BU2, idx, 128, 128, 8); }
}

// fp32 -> hi/lo bf16 image; optionally zero a second array (fused zero_agg).
__global__ void tobf_kernel(const float* __restrict__ src,
                            __nv_bfloat16* __restrict__ dst,
                            float* __restrict__ zeroarr) {
    int i = blockIdx.x * blockDim.x + threadIdx.x;
    if (i >= N_NODES * HID) return;
    int node = i >> 7, c = i & 127;
    float v = src[i];
    __nv_bfloat16 hi = __float2bfloat16(v);
    dst[node * 256 + c]       = hi;
    dst[node * 256 + 128 + c] = __float2bfloat16(v - __bfloat162float(hi));
    if (zeroarr) zeroarr[i] = 0.f;
}

// ------------------------------ misc kernels -------------------------------
__global__ void dist_kernel(const float* __restrict__ pos, const int* __restrict__ ei) {
    int e = blockIdx.x * blockDim.x + threadIdx.x;
    if (e >= N_EDGES) return;
    int s = ei[e];
    int d = ei[N_EDGES + e];
    float dx = pos[d * 3 + 0] - pos[s * 3 + 0];
    float dy = pos[d * 3 + 1] - pos[s * 3 + 1];
    float dz = pos[d * 3 + 2] - pos[s * 3 + 2];
    g_dist[e] = sqrtf(dx * dx + dy * dy + dz * dz);
}

__global__ void embed_kernel(const float* __restrict__ x,
                             const float* __restrict__ W,
                             const float* __restrict__ b) {
    int n = blockIdx.x;
    int t = threadIdx.x;
    float acc = b[t];
#pragma unroll
    for (int k = 0; k < NODE_F; k++)
        acc = fmaf(x[n * NODE_F + k], W[k * HID + t], acc);
    g_h[n * HID + t] = acc;
}

__global__ void zero_pool_kernel() {
    int i = blockIdx.x * blockDim.x + threadIdx.x;
    if (i < N_GRAPHS * HID) g_pool[i] = 0.f;
}

// ---------------------- async staging device fns ---------------------------
__device__ __forceinline__ void stageB_cp(uint32_t smb, int tid,
                                          const __nv_bfloat16* __restrict__ img, int buf) {
    uint32_t dst = smb + OFF_B + buf * 8704;
#pragma unroll
    for (int jj = 0; jj < 2; jj++) {
        int e8 = tid * 2 + jj;
        int plane = e8 >> 8;
        int ge = e8 & 255;
        int k = ge >> 4, n = (ge & 15) * 8;
        cp16(dst + plane * 4352 + k * 272 + n * 2, img + e8 * 8);
    }
}

__device__ __forceinline__ void stageA_cp(uint32_t smb, int buf, int row, int half,
                                          const __nv_bfloat16* __restrict__ nodeimg,
                                          int kseg) {
    const __nv_bfloat16* src = nodeimg + kseg * 16 + half * 8;
    uint32_t dst = smb + OFF_A + buf * 12288 + row * 48 + half * 16;
    cp16(dst, src);
    cp16(dst + 6144, src + 128);
}

__device__ __forceinline__ void a2_write(char* sm, int row, int col,
                                         float v0, float v1) {
    float h0 = bf16f(v0), h1 = bf16f(v1);
    int off = row * 272 + col * 2;
    *(uint32_t*)(sm + OFF_A2 + off)         = pack_bf2(v0, v1);
    *(uint32_t*)(sm + OFF_A2 + A2_LO + off) = pack_bf2(v0 - h0, v1 - h1);
}

// Cross-warp LN: thread holds C[2][8][4] (4 rows x 16 vals over 64 cols).
// Produces sMV[row] = {mean, rstd}. Uses sRed[128][4], sMV[128][2].
__device__ __forceinline__ void ln_reduce(char* sm, float C[2][8][4],
                                          const int R[4], int l, int wn, int tid) {
    float s[4] = {0.f, 0.f, 0.f, 0.f}, s2[4] = {0.f, 0.f, 0.f, 0.f};
#pragma unroll
    for (int mt = 0; mt < 2; mt++)
#pragma unroll
        for (int nn = 0; nn < 8; nn++) {
#pragma unroll
            for (int j = 0; j < 4; j++) {
                int t = mt * 2 + (j >> 1);
                float v = C[mt][nn][j];
                s[t] += v; s2[t] += v * v;
            }
        }
#pragma unroll
    for (int t = 0; t < 4; t++) {
        s[t]  += __shfl_xor_sync(0xffffffffu, s[t], 1);
        s[t]  += __shfl_xor_sync(0xffffffffu, s[t], 2);
        s2[t] += __shfl_xor_sync(0xffffffffu, s2[t], 1);
        s2[t] += __shfl_xor_sync(0xffffffffu, s2[t], 2);
    }
    float* sRed = (float*)(sm + OFF_RED);
    if ((l & 3) == 0) {
#pragma unroll
        for (int t = 0; t < 4; t++) {
            sRed[R[t] * 4 + wn * 2]     = s[t];
            sRed[R[t] * 4 + wn * 2 + 1] = s2[t];
        }
    }
    __syncthreads();
    float* sMV = (float*)(sm + OFF_MV);
    if (tid < 128) {
        float ss  = sRed[tid * 4] + sRed[tid * 4 + 2];
        float ss2 = sRed[tid * 4 + 1] + sRed[tid * 4 + 3];
        float mean = ss * (1.f / 128.f);
        float var = fmaxf(ss2 * (1.f / 128.f) - mean * mean, 0.f);
        sMV[tid * 2] = mean;
        sMV[tid * 2 + 1] = rsqrtf(var + 1e-5f);
    }
    __syncthreads();
}

// ------------------------------ msg_mma kernel -----------------------------
// 128 edges/block, 256 threads. Warp tiling 4(M) x 2(N):
// warp w: wm = w&3 -> rows 32wm..+31 (2 m-tiles), wn = w>>2 -> cols 64wn..+63.
__global__ void __launch_bounds__(256, 2) msg_mma(
    const int* __restrict__ ei,
    const __nv_bfloat16* __restrict__ B1, const __nv_bfloat16* __restrict__ B2,
    const float* __restrict__ W1d,
    const float* __restrict__ b1, const float* __restrict__ g1, const float* __restrict__ be1,
    const float* __restrict__ b2, const float* __restrict__ g2, const float* __restrict__ be2) {
    extern __shared__ char sm[];
    uint32_t smb = smem_u32(sm);
    int tid = threadIdx.x;
    int w = tid >> 5, l = tid & 31;
    int wm = w & 3, wn = w >> 2;
    int rowbase = 32 * wm, colbase = 64 * wn;
    int e0 = blockIdx.x * 128;

    int* sDst = (int*)(sm + OFF_DST);
    int* sSrc = (int*)(sm + OFF_SRC);
    float* sDist = (float*)(sm + OFF_DIST);
    float* sPar = (float*)(sm + OFF_PAR);
    if (tid < 128) {
        sPar[tid]       = b1[tid];
        sPar[128 + tid] = g1[tid];
        sPar[256 + tid] = be1[tid];
        sPar[384 + tid] = b2[tid];
        sPar[512 + tid] = g2[tid];
        sPar[640 + tid] = be2[tid];
        sPar[768 + tid] = W1d[tid];
        int ec = min(e0 + tid, N_EDGES - 1);
        sSrc[tid] = ei[ec];
        sDst[tid] = ei[N_EDGES + ec];
        sDist[tid] = g_dist[ec];
    }
    __syncthreads();

    int rowS = tid >> 1, halfS = tid & 1;
    auto stageA = [&](int kc, int buf) {
        int node = (kc < 8 ? sDst : sSrc)[rowS];
        stageA_cp(smb, buf, rowS, halfS, g_hbf + (size_t)node * 256, kc & 7);
    };

    float C[2][8][4];
#pragma unroll
    for (int mt = 0; mt < 2; mt++)
#pragma unroll
        for (int nn = 0; nn < 8; nn++)
#pragma unroll
            for (int j = 0; j < 4; j++) C[mt][nn][j] = 0.f;

    stageA(0, 0);
    stageB_cp(smb, tid, B1, 0);
    CP_COMMIT();
    CP_WAIT0();
    __syncthreads();
    uint32_t aoff0 = ((rowbase + (l & 15)) * 24 + (l >> 4) * 8) * 2;
    uint32_t aoff1 = ((rowbase + 16 + (l & 15)) * 24 + (l >> 4) * 8) * 2;
    uint32_t boff = (((l & 7) + 8 * ((l >> 3) & 1)) * 136 + 8 * (l >> 4)) * 2;

#pragma unroll 1
    for (int kc = 0; kc < 16; kc++) {
        int buf = kc & 1;
        if (kc + 1 < 16) {
            stageA(kc + 1, buf ^ 1);
            stageB_cp(smb, tid, B1 + (kc + 1) * 4096, buf ^ 1);
            CP_COMMIT();
        }
        uint32_t Ah[2][4], Al[2][4];
        uint32_t abase = smb + OFF_A + buf * 12288;
        ldmA(Ah[0], abase + aoff0);
        ldmA(Ah[1], abase + aoff1);
        ldmA(Al[0], abase + aoff0 + 6144);
        ldmA(Al[1], abase + aoff1 + 6144);
        uint32_t bbase = smb + OFF_B + buf * 8704 + boff + wn * 128;
#pragma unroll
        for (int i = 0; i < 4; i++) {
            uint32_t Bh[4], Bl[4];
            uint32_t ba = bbase + i * 32;
            ldmBT(Bh, ba);
            ldmBT(Bl, ba + 4352);
#pragma unroll
            for (int mt = 0; mt < 2; mt++) {
                mma16816(C[mt][2 * i],     Ah[mt], Bh[0], Bh[1]);
                mma16816(C[mt][2 * i],     Ah[mt], Bl[0], Bl[1]);
                mma16816(C[mt][2 * i],     Al[mt], Bh[0], Bh[1]);
                mma16816(C[mt][2 * i + 1], Ah[mt], Bh[2], Bh[3]);
                mma16816(C[mt][2 * i + 1], Ah[mt], Bl[2], Bl[3]);
                mma16816(C[mt][2 * i + 1], Al[mt], Bh[2], Bh[3]);
            }
        }
        CP_WAIT0();
        __syncthreads();
    }

    // ---- epilogue1: dist rank-1 + bias + LN + ReLU -> A2 SMEM image ----
    int rq = l >> 2, q2 = 2 * (l & 3);
    int R[4] = {rowbase + rq, rowbase + 8 + rq, rowbase + 16 + rq, rowbase + 24 + rq};
    float dR[4] = {sDist[R[0]], sDist[R[1]], sDist[R[2]], sDist[R[3]]};
#pragma unroll
    for (int mt = 0; mt < 2; mt++)
#pragma unroll
        for (int nn = 0; nn < 8; nn++) {
            int col = colbase + nn * 8 + q2;
            float wd0 = sPar[768 + col], wd1 = sPar[768 + col + 1];
            float bb0 = sPar[col], bb1 = sPar[col + 1];
            C[mt][nn][0] += dR[mt * 2] * wd0 + bb0;
            C[mt][nn][1] += dR[mt * 2] * wd1 + bb1;
            C[mt][nn][2] += dR[mt * 2 + 1] * wd0 + bb0;
            C[mt][nn][3] += dR[mt * 2 + 1] * wd1 + bb1;
        }
    ln_reduce(sm, C, R, l, wn, tid);
    {
        float* sMV = (float*)(sm + OFF_MV);
#pragma unroll
        for (int mt = 0; mt < 2; mt++)
#pragma unroll
            for (int nn = 0; nn < 8; nn++) {
                int col = colbase + nn * 8 + q2;
                float ga = sPar[128 + col], gb = sPar[128 + col + 1];
                float ba = sPar[256 + col], bb = sPar[256 + col + 1];
                int ra = R[mt * 2], rb = R[mt * 2 + 1];
                a2_write(sm, ra, col,
                    fmaxf(fmaf((C[mt][nn][0] - sMV[ra * 2]) * sMV[ra * 2 + 1], ga, ba), 0.f),
                    fmaxf(fmaf((C[mt][nn][1] - sMV[ra * 2]) * sMV[ra * 2 + 1], gb, bb), 0.f));
                a2_write(sm, rb, col,
                    fmaxf(fmaf((C[mt][nn][2] - sMV[rb * 2]) * sMV[rb * 2 + 1], ga, ba), 0.f),
                    fmaxf(fmaf((C[mt][nn][3] - sMV[rb * 2]) * sMV[rb * 2 + 1], gb, bb), 0.f));
            }
    }

    // ---- GEMM2 ----
    float (*C2)[8][4] = C;
#pragma unroll
    for (int mt = 0; mt < 2; mt++)
#pragma unroll
        for (int nn = 0; nn < 8; nn++)
#pragma unroll
            for (int j = 0; j < 4; j++) C2[mt][nn][j] = 0.f;

    stageB_cp(smb, tid, B2, 0);
    CP_COMMIT();
    CP_WAIT0();
    __syncthreads();
    uint32_t a2r0 = smb + OFF_A2 + (rowbase + (l & 15)) * 272 + (l >> 4) * 16;
    uint32_t a2r1 = smb + OFF_A2 + (rowbase + 16 + (l & 15)) * 272 + (l >> 4) * 16;
#pragma unroll
    for (int kc = 0; kc < 8; kc++) {
        int buf = kc & 1;
        if (kc + 1 < 8) { stageB_cp(smb, tid, B2 + (kc + 1) * 4096, buf ^ 1); CP_COMMIT(); }
        uint32_t Ah[2][4], Al[2][4];
        ldmA(Ah[0], a2r0 + kc * 32);
        ldmA(Ah[1], a2r1 + kc * 32);
        ldmA(Al[0], a2r0 + kc * 32 + A2_LO);
        ldmA(Al[1], a2r1 + kc * 32 + A2_LO);
        uint32_t bbase = smb + OFF_B + buf * 8704 + boff + wn * 128;
#pragma unroll
        for (int i = 0; i < 4; i++) {
            uint32_t Bh[4], Bl[4];
            uint32_t ba = bbase + i * 32;
            ldmBT(Bh, ba);
            ldmBT(Bl, ba + 4352);
#pragma unroll
            for (int mt = 0; mt < 2; mt++) {
                mma16816(C2[mt][2 * i],     Ah[mt], Bh[0], Bh[1]);
                mma16816(C2[mt][2 * i],     Ah[mt], Bl[0], Bl[1]);
                mma16816(C2[mt][2 * i],     Al[mt], Bh[0], Bh[1]);
                mma16816(C2[mt][2 * i + 1], Ah[mt], Bh[2], Bh[3]);
                mma16816(C2[mt][2 * i + 1], Ah[mt], Bl[2], Bl[3]);
                mma16816(C2[mt][2 * i + 1], Al[mt], Bh[2], Bh[3]);
            }
        }
        CP_WAIT0();
        __syncthreads();
    }

    // ---- epilogue2: bias + LN + ReLU -> sOut -> coalesced atomic scatter ----
#pragma unroll
    for (int mt = 0; mt < 2; mt++)
#pragma unroll
        for (int nn = 0; nn < 8; nn++) {
            int col = colbase + nn * 8 + q2;
            float bb0 = sPar[384 + col], bb1 = sPar[384 + col + 1];
            C2[mt][nn][0] += bb0; C2[mt][nn][1] += bb1;
            C2[mt][nn][2] += bb0; C2[mt][nn][3] += bb1;
        }
    ln_reduce(sm, C2, R, l, wn, tid);
    {
        float* sMV = (float*)(sm + OFF_MV);
        float* sOut = (float*)(sm + OFF_OUT);
#pragma unroll
        for (int mt = 0; mt < 2; mt++)
#pragma unroll
            for (int nn = 0; nn < 8; nn++) {
                int col = colbase + nn * 8 + q2;
                float ga = sPar[512 + col], gb = sPar[512 + col + 1];
                float ba = sPar[640 + col], bb = sPar[640 + col + 1];
                int ra = R[mt * 2], rb = R[mt * 2 + 1];
                float v0 = fmaxf(fmaf((C2[mt][nn][0] - sMV[ra * 2]) * sMV[ra * 2 + 1], ga, ba), 0.f);
                float v1 = fmaxf(fmaf((C2[mt][nn][1] - sMV[ra * 2]) * sMV[ra * 2 + 1], gb, bb), 0.f);
                float v2 = fmaxf(fmaf((C2[mt][nn][2] - sMV[rb * 2]) * sMV[rb * 2 + 1], ga, ba), 0.f);
                float v3 = fmaxf(fmaf((C2[mt][nn][3] - sMV[rb * 2]) * sMV[rb * 2 + 1], gb, bb), 0.f);
                *(float2*)&sOut[ra * 132 + col] = make_float2(v0, v1);
                *(float2*)&sOut[rb * 132 + col] = make_float2(v2, v3);
            }
    }
    __syncthreads();

    int col = tid & 127;
    int half = tid >> 7;
    float* sOut = (float*)(sm + OFF_OUT);
#pragma unroll 4
    for (int i = 0; i < 64; i++) {
        int row = half * 64 + i;
        if (e0 + row < N_EDGES)
            atomicAdd(&g_agg[sDst[row] * HID + col], sOut[row * 132 + col]);
    }
}

// ------------------------------ upd_mma kernel -----------------------------
__global__ void __launch_bounds__(256, 2) upd_mma(
    const __nv_bfloat16* __restrict__ B1, const __nv_bfloat16* __restrict__ B2,
    const float* __restrict__ b1, const float* __restrict__ g1, const float* __restrict__ be1,
    const float* __restrict__ b2, const float* __restrict__ g2, const float* __restrict__ be2) {
    extern __shared__ char sm[];
    uint32_t smb = smem_u32(sm);
    int tid = threadIdx.x;
    int w = tid >> 5, l = tid & 31;
    int wm = w & 3, wn = w >> 2;
    int rowbase = 32 * wm, colbase = 64 * wn;
    int n0 = blockIdx.x * 128;

    float* sPar = (float*)(sm + OFF_PAR);
    if (tid < 128) {
        sPar[tid]       = b1[tid];
        sPar[128 + tid] = g1[tid];
        sPar[256 + tid] = be1[tid];
        sPar[384 + tid] = b2[tid];
        sPar[512 + tid] = g2[tid];
        sPar[640 + tid] = be2[tid];
    }
    __syncthreads();

    int rowS = tid >> 1, halfS = tid & 1;
    int nodeS = min(n0 + rowS, N_NODES - 1);
    auto stageA = [&](int kc, int buf) {
        const __nv_bfloat16* base = (kc < 8) ? g_hbf : g_aggbf;
        stageA_cp(smb, buf, rowS, halfS, base + (size_t)nodeS * 256, kc & 7);
    };

    float C[2][8][4];
#pragma unroll
    for (int mt = 0; mt < 2; mt++)
#pragma unroll
        for (int nn = 0; nn < 8; nn++)
#pragma unroll
            for (int j = 0; j < 4; j++) C[mt][nn][j] = 0.f;

    stageA(0, 0);
    stageB_cp(smb, tid, B1, 0);
    CP_COMMIT();
    CP_WAIT0();
    __syncthreads();
    uint32_t aoff0 = ((rowbase + (l & 15)) * 24 + (l >> 4) * 8) * 2;
    uint32_t aoff1 = ((rowbase + 16 + (l & 15)) * 24 + (l >> 4) * 8) * 2;
    uint32_t boff = (((l & 7) + 8 * ((l >> 3) & 1)) * 136 + 8 * (l >> 4)) * 2;

#pragma unroll 1
    for (int kc = 0; kc < 16; kc++) {
        int buf = kc & 1;
        if (kc + 1 < 16) {
            stageA(kc + 1, buf ^ 1);
            stageB_cp(smb, tid, B1 + (kc + 1) * 4096, buf ^ 1);
            CP_COMMIT();
        }
        uint32_t Ah[2][4], Al[2][4];
        uint32_t abase = smb + OFF_A + buf * 12288;
        ldmA(Ah[0], abase + aoff0);
        ldmA(Ah[1], abase + aoff1);
        ldmA(Al[0], abase + aoff0 + 6144);
        ldmA(Al[1], abase + aoff1 + 6144);
        uint32_t bbase = smb + OFF_B + buf * 8704 + boff + wn * 128;
#pragma unroll
        for (int i = 0; i < 4; i++) {
            uint32_t Bh[4], Bl[4];
            uint32_t ba = bbase + i * 32;
            ldmBT(Bh, ba);
            ldmBT(Bl, ba + 4352);
#pragma unroll
            for (int mt = 0; mt < 2; mt++) {
                mma16816(C[mt][2 * i],     Ah[mt], Bh[0], Bh[1]);
                mma16816(C[mt][2 * i],     Ah[mt], Bl[0], Bl[1]);
                mma16816(C[mt][2 * i],     Al[mt], Bh[0], Bh[1]);
                mma16816(C[mt][2 * i + 1], Ah[mt], Bh[2], Bh[3]);
                mma16816(C[mt][2 * i + 1], Ah[mt], Bl[2], Bl[3]);
                mma16816(C[mt][2 * i + 1], Al[mt], Bh[2], Bh[3]);
            }
        }
        CP_WAIT0();
        __syncthreads();
    }

    // ---- epilogue1: bias + LN + ReLU -> A2 ----
    int rq = l >> 2, q2 = 2 * (l & 3);
    int R[4] = {rowbase + rq, rowbase + 8 + rq, rowbase + 16 + rq, rowbase + 24 + rq};
#pragma unroll
    for (int mt = 0; mt < 2; mt++)
#pragma unroll
        for (int nn = 0; nn < 8; nn++) {
            int col = colbase + nn * 8 + q2;
            float bb0 = sPar[col], bb1 = sPar[col + 1];
            C[mt][nn][0] += bb0; C[mt][nn][1] += bb1;
            C[mt][nn][2] += bb0; C[mt][nn][3] += bb1;
        }
    ln_reduce(sm, C, R, l, wn, tid);
    {
        float* sMV = (float*)(sm + OFF_MV);
#pragma unroll
        for (int mt = 0; mt < 2; mt++)
#pragma unroll
            for (int nn = 0; nn < 8; nn++) {
                int col = colbase + nn * 8 + q2;
                float ga = sPar[128 + col], gb = sPar[128 + col + 1];
                float ba = sPar[256 + col], bb = sPar[256 + col + 1];
                int ra = R[mt * 2], rb = R[mt * 2 + 1];
                a2_write(sm, ra, col,
                    fmaxf(fmaf((C[mt][nn][0] - sMV[ra * 2]) * sMV[ra * 2 + 1], ga, ba), 0.f),
                    fmaxf(fmaf((C[mt][nn][1] - sMV[ra * 2]) * sMV[ra * 2 + 1], gb, bb), 0.f));
                a2_write(sm, rb, col,
                    fmaxf(fmaf((C[mt][nn][2] - sMV[rb * 2]) * sMV[rb * 2 + 1], ga, ba), 0.f),
                    fmaxf(fmaf((C[mt][nn][3] - sMV[rb * 2]) * sMV[rb * 2 + 1], gb, bb), 0.f));
            }
    }

    // ---- GEMM2 ----
    float (*C2)[8][4] = C;
#pragma unroll
    for (int mt = 0; mt < 2; mt++)
#pragma unroll
        for (int nn = 0; nn < 8; nn++)
#pragma unroll
            for (int j = 0; j < 4; j++) C2[mt][nn][j] = 0.f;

    stageB_cp(smb, tid, B2, 0);
    CP_COMMIT();
    CP_WAIT0();
    __syncthreads();
    uint32_t a2r0 = smb + OFF_A2 + (rowbase + (l & 15)) * 272 + (l >> 4) * 16;
    uint32_t a2r1 = smb + OFF_A2 + (rowbase + 16 + (l & 15)) * 272 + (l >> 4) * 16;
#pragma unroll
    for (int kc = 0; kc < 8; kc++) {
        int buf = kc & 1;
        if (kc + 1 < 8) { stageB_cp(smb, tid, B2 + (kc + 1) * 4096, buf ^ 1); CP_COMMIT(); }
        uint32_t Ah[2][4], Al[2][4];
        ldmA(Ah[0], a2r0 + kc * 32);
        ldmA(Ah[1], a2r1 + kc * 32);
        ldmA(Al[0], a2r0 + kc * 32 + A2_LO);
        ldmA(Al[1], a2r1 + kc * 32 + A2_LO);
        uint32_t bbase = smb + OFF_B + buf * 8704 + boff + wn * 128;
#pragma unroll
        for (int i = 0; i < 4; i++) {
            uint32_t Bh[4], Bl[4];
            uint32_t ba = bbase + i * 32;
            ldmBT(Bh, ba);
            ldmBT(Bl, ba + 4352);
#pragma unroll
            for (int mt = 0; mt < 2; mt++) {
                mma16816(C2[mt][2 * i],     Ah[mt], Bh[0], Bh[1]);
                mma16816(C2[mt][2 * i],     Ah[mt], Bl[0], Bl[1]);
                mma16816(C2[mt][2 * i],     Al[mt], Bh[0], Bh[1]);
                mma16816(C2[mt][2 * i + 1], Ah[mt], Bh[2], Bh[3]);
                mma16816(C2[mt][2 * i + 1], Ah[mt], Bl[2], Bl[3]);
                mma16816(C2[mt][2 * i + 1], Al[mt], Bh[2], Bh[3]);
            }
        }
        CP_WAIT0();
        __syncthreads();
    }

    // ---- epilogue2: bias + LN + ReLU + residual -> g_h ----
#pragma unroll
    for (int mt = 0; mt < 2; mt++)
#pragma unroll
        for (int nn = 0; nn < 8; nn++) {
            int col = colbase + nn * 8 + q2;
            float bb0 = sPar[384 + col], bb1 = sPar[384 + col + 1];
            C2[mt][nn][0] += bb0; C2[mt][nn][1] += bb1;
            C2[mt][nn][2] += bb0; C2[mt][nn][3] += bb1;
        }
    ln_reduce(sm, C2, R, l, wn, tid);
    {
        float* sMV = (float*)(sm + OFF_MV);
#pragma unroll
        for (int mt = 0; mt < 2; mt++)
#pragma unroll
            for (int nn = 0; nn < 8; nn++) {
                int col = colbase + nn * 8 + q2;
                float ga = sPar[512 + col], gb = sPar[512 + col + 1];
                float ba = sPar[640 + col], bb = sPar[640 + col + 1];
                int ra = R[mt * 2], rb = R[mt * 2 + 1];
                int na = n0 + ra, nb = n0 + rb;
                if (na < N_NODES) {
                    float v0 = fmaxf(fmaf((C2[mt][nn][0] - sMV[ra * 2]) * sMV[ra * 2 + 1], ga, ba), 0.f);
                    float v1 = fmaxf(fmaf((C2[mt][nn][1] - sMV[ra * 2]) * sMV[ra * 2 + 1], gb, bb), 0.f);
                    float2 old = *(float2*)&g_h[(size_t)na * HID + col];
                    *(float2*)&g_h[(size_t)na * HID + col] = make_float2(old.x + v0, old.y + v1);
                }
                if (nb < N_NODES) {
                    float v2 = fmaxf(fmaf((C2[mt][nn][2] - sMV[rb * 2]) * sMV[rb * 2 + 1], ga, ba), 0.f);
                    float v3 = fmaxf(fmaf((C2[mt][nn][3] - sMV[rb * 2]) * sMV[rb * 2 + 1], gb, bb), 0.f);
                    float2 old = *(float2*)&g_h[(size_t)nb * HID + col];
                    *(float2*)&g_h[(size_t)nb * HID + col] = make_float2(old.x + v2, old.y + v3);
                }
            }
    }
}

// ------------------------------ pool / pred --------------------------------
__global__ void pool_kernel(const int* __restrict__ batch) {
    int n = blockIdx.x;
    int t = threadIdx.x;
    atomicAdd(&g_pool[batch[n] * HID + t], g_h[n * HID + t]);
}

__global__ void pred_kernel(const float* __restrict__ W1, const float* __restrict__ b1,
                            const float* __restrict__ W2, const float* __restrict__ b2,
                            float* __restrict__ out) {
    __shared__ float sred[128];
    int g = blockIdx.x;
    int t = threadIdx.x;
    float acc = b1[t];
    for (int k = 0; k < HID; k++)
        acc = fmaf(g_pool[g * HID + k], W1[k * HID + t], acc);
    acc = fmaxf(acc, 0.f) * W2[t];
    sred[t] = acc;
    __syncthreads();
    for (int o = 64; o > 0; o >>= 1) {
        if (t < o) sred[t] += sred[t + o];
        __syncthreads();
    }
    if (t == 0) out[g] = sred[0] + b2[0];
}

// ------------------------------ launch -------------------------------------
extern "C" void kernel_launch(void* const* d_in, const int* in_sizes, int n_in,
                              void* d_out, int out_size) {
    const float* x     = (const float*)d_in[0];
    const float* pos   = (const float*)d_in[1];
    const int*   ei    = (const int*)d_in[2];
    const int*   batch = (const int*)d_in[3];
    const float* emb_W = (const float*)d_in[4];
    const float* emb_b = (const float*)d_in[5];

    const float *mW1, *mb1, *mg1, *mbe1, *mW2, *mb2, *mg2, *mbe2;
    const float *uW1, *ub1, *ug1, *ube1, *uW2, *ub2, *ug2, *ube2;

    if (in_sizes[8] == 81920) {
        mW1  = (const float*)d_in[6];  mb1  = (const float*)d_in[7];
        mW2  = (const float*)d_in[8];  mb2  = (const float*)d_in[9];
        uW1  = (const float*)d_in[10]; ub1  = (const float*)d_in[11];
        uW2  = (const float*)d_in[12]; ub2  = (const float*)d_in[13];
        mg1  = (const float*)d_in[14]; mbe1 = (const float*)d_in[15];
        mg2  = (const float*)d_in[16]; mbe2 = (const float*)d_in[17];
        ug1  = (const float*)d_in[18]; ube1 = (const float*)d_in[19];
        ug2  = (const float*)d_in[20]; ube2 = (const float*)d_in[21];
    } else {
        mW1  = (const float*)d_in[6];  mb1  = (const float*)d_in[7];
        mg1  = (const float*)d_in[8];  mbe1 = (const float*)d_in[9];
        mW2  = (const float*)d_in[10]; mb2  = (const float*)d_in[11];
        mg2  = (const float*)d_in[12]; mbe2 = (const float*)d_in[13];
        uW1  = (const float*)d_in[14]; ub1  = (const float*)d_in[15];
        ug1  = (const float*)d_in[16]; ube1 = (const float*)d_in[17];
        uW2  = (const float*)d_in[18]; ub2  = (const float*)d_in[19];
        ug2  = (const float*)d_in[20]; ube2 = (const float*)d_in[21];
    }
    const float* pW1 = (const float*)d_in[22];
    const float* pb1 = (const float*)d_in[23];
    const float* pW2 = (const float*)d_in[24];
    const float* pb2 = (const float*)d_in[25];
    float* out = (float*)d_out;

    __nv_bfloat16 *bm1, *bm2, *bu1, *bu2, *hbf, *aggbf;
    float *gh, *gagg;
    cudaGetSymbolAddress((void**)&bm1, g_B1);
    cudaGetSymbolAddress((void**)&bm2, g_B2);
    cudaGetSymbolAddress((void**)&bu1, g_BU1);
    cudaGetSymbolAddress((void**)&bu2, g_BU2);
    cudaGetSymbolAddress((void**)&hbf, g_hbf);
    cudaGetSymbolAddress((void**)&aggbf, g_aggbf);
    cudaGetSymbolAddress((void**)&gh, g_h);
    cudaGetSymbolAddress((void**)&gagg, g_agg);

    cudaFuncSetAttribute(msg_mma, cudaFuncAttributeMaxDynamicSharedMemorySize, SMEM_MSG);
    cudaFuncSetAttribute(upd_mma, cudaFuncAttributeMaxDynamicSharedMemorySize, SMEM_MSG);

    pack_all<<<(2 * (PK16 + PK8) + 255) / 256, 256>>>(mW1, mW2, uW1, uW2,
                                                      bm1, bm2, bu1, bu2);
    dist_kernel<<<(N_EDGES + 255) / 256, 256>>>(pos, ei);
    embed_kernel<<<N_NODES, 128>>>(x, emb_W, emb_b);
    zero_pool_kernel<<<(N_GRAPHS * HID + 255) / 256, 256>>>();

    int msg_blocks = (N_EDGES + 127) / 128;
    int upd_blocks = (N_NODES + 127) / 128;
    int conv_blocks = (N_NODES * HID + 255) / 256;
    for (int l = 0; l < DEPTH; l++) {
        tobf_kernel<<<conv_blocks, 256>>>(gh, hbf, gagg);  // also zeroes g_agg
        msg_mma<<<msg_blocks, 256, SMEM_MSG>>>(
            ei,
            bm1 + l * 16 * 4096, bm2 + l * 8 * 4096,
            mW1 + l * 257 * HID + 256 * HID,
            mb1 + l * HID, mg1 + l * HID, mbe1 + l * HID,
            mb2 + l * HID, mg2 + l * HID, mbe2 + l * HID);
        tobf_kernel<<<conv_blocks, 256>>>(gagg, aggbf, nullptr);
        upd_mma<<<upd_blocks, 256, SMEM_MSG>>>(
            bu1 + l * 16 * 4096, bu2 + l * 8 * 4096,
            ub1 + l * HID, ug1 + l * HID, ube1 + l * HID,
            ub2 + l * HID, ug2 + l * HID, ube2 + l * HID);
    }

    pool_kernel<<<N_NODES, 128>>>(batch);
    pred_kernel<<<N_GRAPHS, 128>>>(pW1, pb1, pW2, pb2, out);
}

// round 17
// speedup vs baseline: 3.3938x; 1.0849x over previous
#include <cuda_runtime.h>
#include <cuda_bf16.h>
#include <math.h>
#include <stdint.h>

#define N_NODES 25000
#define N_EDGES 200000
#define HID     128
#define N_GRAPHS 64
#define DEPTH   5
#define NODE_F  16

// ------------------------------ scratch globals ----------------------------
__device__ float g_h[N_NODES * HID];
__device__ float g_agg[N_NODES * HID];
__device__ float g_dist[N_EDGES];
__device__ float g_pool[N_GRAPHS * HID];
__device__ __nv_bfloat16 g_hbf[N_NODES * 256];
__device__ __nv_bfloat16 g_aggbf[N_NODES * 256];
__device__ __nv_bfloat16 g_B1[DEPTH * 16 * 4096];
__device__ __nv_bfloat16 g_B2[DEPTH * 8 * 4096];
__device__ __nv_bfloat16 g_BU1[DEPTH * 16 * 4096];
__device__ __nv_bfloat16 g_BU2[DEPTH * 8 * 4096];

// ------------------------------ SMEM layout (bytes) ------------------------
// A stage: 2 bufs x (hi 10240 + lo 10240) = 40960 (rows 128 x 80B, 64B data)
// A2 image (after GEMM1, aliases A): hi 34816 + lo 34816 = 69632
// sOut (after GEMM2, aliases A): 128 x 132 fp32 = 67584
#define OFF_A    0
#define OFF_A2   0
#define OFF_OUT  0
#define A_PLANE  10240
#define A_BUFSZ  20480
#define A2_LO    34816
#define OFF_B    69632      // 2 bufs x (hi 8704 + lo 8704) = 34816
#define B_PLANE  8704
#define B_BUFSZ  17408
#define OFF_PAR  104448     // 7 x 128 fp32 = 3584
#define OFF_DST  108032
#define OFF_SRC  108544
#define OFF_DIST 109056
#define OFF_RED  109568     // 128 x 4 fp32
#define OFF_MV   111616     // 128 x 2 fp32
#define SMEM_MSG 112640     // 110 KB; 2 CTAs/SM = 220 KB <= 227 KB

// ------------------------------ helpers ------------------------------------
__device__ __forceinline__ uint32_t smem_u32(const void* p) {
    uint32_t a;
    asm("{ .reg .u64 t; cvta.to.shared.u64 t, %1; cvt.u32.u64 %0, t; }" : "=r"(a) : "l"(p));
    return a;
}
__device__ __forceinline__ void ldmA(uint32_t a[4], uint32_t addr) {
    asm volatile("ldmatrix.sync.aligned.m8n8.x4.shared.b16 {%0,%1,%2,%3}, [%4];"
                 : "=r"(a[0]), "=r"(a[1]), "=r"(a[2]), "=r"(a[3]) : "r"(addr));
}
__device__ __forceinline__ void ldmBT(uint32_t b[4], uint32_t addr) {
    asm volatile("ldmatrix.sync.aligned.m8n8.x4.trans.shared.b16 {%0,%1,%2,%3}, [%4];"
                 : "=r"(b[0]), "=r"(b[1]), "=r"(b[2]), "=r"(b[3]) : "r"(addr));
}
__device__ __forceinline__ void mma16816(float c[4], const uint32_t a[4],
                                         uint32_t b0, uint32_t b1) {
    asm volatile("mma.sync.aligned.m16n8k16.row.col.f32.bf16.bf16.f32 "
                 "{%0,%1,%2,%3}, {%4,%5,%6,%7}, {%8,%9}, {%0,%1,%2,%3};"
                 : "+f"(c[0]), "+f"(c[1]), "+f"(c[2]), "+f"(c[3])
                 : "r"(a[0]), "r"(a[1]), "r"(a[2]), "r"(a[3]), "r"(b0), "r"(b1));
}
__device__ __forceinline__ uint32_t pack_bf2(float a, float b) {
    __nv_bfloat162 h = __floats2bfloat162_rn(a, b);
    return *reinterpret_cast<uint32_t*>(&h);
}
__device__ __forceinline__ float bf16f(float v) {
    return __bfloat162float(__float2bfloat16(v));
}
__device__ __forceinline__ void cp16(uint32_t dst, const void* src) {
    asm volatile("cp.async.cg.shared.global [%0], [%1], 16;" :: "r"(dst), "l"(src) : "memory");
}
#define CP_COMMIT() asm volatile("cp.async.commit_group;" ::: "memory")
#define CP_WAIT0()  asm volatile("cp.async.wait_group 0;" ::: "memory")
__device__ __forceinline__ void red4(float* gaddr, float4 v) {
    asm volatile("red.global.add.v4.f32 [%0], {%1,%2,%3,%4};"
                 :: "l"(gaddr), "f"(v.x), "f"(v.y), "f"(v.z), "f"(v.w) : "memory");
}

// ------------------------------ pack kernel (merged) -----------------------
__device__ __forceinline__ void pack_one(const float* __restrict__ W,
                                         __nv_bfloat16* __restrict__ B,
                                         int idx, int rowStride, int Kuse, int nch) {
    int per = nch * 4096;
    int lay = idx / per;
    int rem = idx - lay * per;
    int chunk = rem >> 12;
    int e = rem & 4095;
    int plane = e >> 11;
    int ke = e & 2047;
    int k = ke >> 7, n = ke & 127;
    int kg = chunk * 16 + k;
    float w = (kg < Kuse) ? W[lay * rowStride * HID + kg * HID + n] : 0.f;
    __nv_bfloat16 hi = __float2bfloat16(w);
    B[idx] = plane ? __float2bfloat16(w - __bfloat162float(hi)) : hi;
}

#define PK16 (DEPTH * 16 * 4096)
#define PK8  (DEPTH * 8 * 4096)

__global__ void pack_all(const float* __restrict__ mW1, const float* __restrict__ mW2,
                         const float* __restrict__ uW1, const float* __restrict__ uW2,
                         __nv_bfloat16* __restrict__ B1, __nv_bfloat16* __restrict__ B2,
                         __nv_bfloat16* __restrict__ BU1, __nv_bfloat16* __restrict__ BU2) {
    int idx = blockIdx.x * blockDim.x + threadIdx.x;
    if (idx < PK16) { pack_one(mW1, B1, idx, 257, 256, 16); return; }
    idx -= PK16;
    if (idx < PK8)  { pack_one(mW2, B2, idx, 128, 128, 8); return; }
    idx -= PK8;
    if (idx < PK16) { pack_one(uW1, BU1, idx, 256, 256, 16); return; }
    idx -= PK16;
    if (idx < PK8)  { pack_one(uW2, BU2, idx, 128, 128, 8); }
}

// fp32 -> hi/lo bf16 image; optionally zero a second array (fused zero_agg).
__global__ void tobf_kernel(const float* __restrict__ src,
                            __nv_bfloat16* __restrict__ dst,
                            float* __restrict__ zeroarr) {
    int i = blockIdx.x * blockDim.x + threadIdx.x;
    if (i >= N_NODES * HID) return;
    int node = i >> 7, c = i & 127;
    float v = src[i];
    __nv_bfloat16 hi = __float2bfloat16(v);
    dst[node * 256 + c]       = hi;
    dst[node * 256 + 128 + c] = __float2bfloat16(v - __bfloat162float(hi));
    if (zeroarr) zeroarr[i] = 0.f;
}

// ------------------------------ misc kernels -------------------------------
__global__ void dist_kernel(const float* __restrict__ pos, const int* __restrict__ ei) {
    int e = blockIdx.x * blockDim.x + threadIdx.x;
    if (e >= N_EDGES) return;
    int s = ei[e];
    int d = ei[N_EDGES + e];
    float dx = pos[d * 3 + 0] - pos[s * 3 + 0];
    float dy = pos[d * 3 + 1] - pos[s * 3 + 1];
    float dz = pos[d * 3 + 2] - pos[s * 3 + 2];
    g_dist[e] = sqrtf(dx * dx + dy * dy + dz * dz);
}

__global__ void embed_kernel(const float* __restrict__ x,
                             const float* __restrict__ W,
                             const float* __restrict__ b) {
    int n = blockIdx.x;
    int t = threadIdx.x;
    float acc = b[t];
#pragma unroll
    for (int k = 0; k < NODE_F; k++)
        acc = fmaf(x[n * NODE_F + k], W[k * HID + t], acc);
    g_h[n * HID + t] = acc;
}

__global__ void zero_pool_kernel() {
    int i = blockIdx.x * blockDim.x + threadIdx.x;
    if (i < N_GRAPHS * HID) g_pool[i] = 0.f;
}

// ---------------------- async staging device fns ---------------------------
// Stage one 16-k weight image (4096 bf16) into rows [half*16, half*16+16)
// of a 32-row B buffer (row stride 272B, hi/lo planes).
__device__ __forceinline__ void stageB_half(uint32_t smb, int tid,
                                            const __nv_bfloat16* __restrict__ img,
                                            int buf, int half) {
    uint32_t dst = smb + OFF_B + buf * B_BUFSZ + half * 16 * 272;
#pragma unroll
    for (int jj = 0; jj < 2; jj++) {
        int e8 = tid * 2 + jj;
        int plane = e8 >> 8;
        int ge = e8 & 255;
        int k = ge >> 4, n = (ge & 15) * 8;
        cp16(dst + plane * B_PLANE + k * 272 + n * 2, img + e8 * 8);
    }
}
__device__ __forceinline__ void stageB32(uint32_t smb, int tid,
                                         const __nv_bfloat16* __restrict__ img, int buf) {
    stageB_half(smb, tid, img, buf, 0);
    stageB_half(smb, tid, img + 4096, buf, 1);
}

// A chunk: 32 bf16 cols per row (row stride 80B). Thread: row=tid>>1, half=tid&1
// copies 16 cols (32B = 2x cp16) per plane.
__device__ __forceinline__ void stageA_cp(uint32_t smb, int buf, int row, int half,
                                          const __nv_bfloat16* __restrict__ nodeimg,
                                          int kseg) {
    const __nv_bfloat16* src = nodeimg + kseg * 32 + half * 16;
    uint32_t dst = smb + OFF_A + buf * A_BUFSZ + row * 80 + half * 32;
    cp16(dst, src);
    cp16(dst + 16, src + 8);
    cp16(dst + A_PLANE, src + 128);
    cp16(dst + A_PLANE + 16, src + 136);
}

__device__ __forceinline__ void a2_write(char* sm, int row, int col,
                                         float v0, float v1) {
    float h0 = bf16f(v0), h1 = bf16f(v1);
    int off = row * 272 + col * 2;
    *(uint32_t*)(sm + OFF_A2 + off)         = pack_bf2(v0, v1);
    *(uint32_t*)(sm + OFF_A2 + A2_LO + off) = pack_bf2(v0 - h0, v1 - h1);
}

// Cross-warp LN (4x2 warp tiling): produces sMV[row] = {mean, rstd}.
__device__ __forceinline__ void ln_reduce(char* sm, float C[2][8][4],
                                          const int R[4], int l, int wn, int tid) {
    float s[4] = {0.f, 0.f, 0.f, 0.f}, s2[4] = {0.f, 0.f, 0.f, 0.f};
#pragma unroll
    for (int mt = 0; mt < 2; mt++)
#pragma unroll
        for (int nn = 0; nn < 8; nn++) {
#pragma unroll
            for (int j = 0; j < 4; j++) {
                int t = mt * 2 + (j >> 1);
                float v = C[mt][nn][j];
                s[t] += v; s2[t] += v * v;
            }
        }
#pragma unroll
    for (int t = 0; t < 4; t++) {
        s[t]  += __shfl_xor_sync(0xffffffffu, s[t], 1);
        s[t]  += __shfl_xor_sync(0xffffffffu, s[t], 2);
        s2[t] += __shfl_xor_sync(0xffffffffu, s2[t], 1);
        s2[t] += __shfl_xor_sync(0xffffffffu, s2[t], 2);
    }
    float* sRed = (float*)(sm + OFF_RED);
    if ((l & 3) == 0) {
#pragma unroll
        for (int t = 0; t < 4; t++) {
            sRed[R[t] * 4 + wn * 2]     = s[t];
            sRed[R[t] * 4 + wn * 2 + 1] = s2[t];
        }
    }
    __syncthreads();
    float* sMV = (float*)(sm + OFF_MV);
    if (tid < 128) {
        float ss  = sRed[tid * 4] + sRed[tid * 4 + 2];
        float ss2 = sRed[tid * 4 + 1] + sRed[tid * 4 + 3];
        float mean = ss * (1.f / 128.f);
        float var = fmaxf(ss2 * (1.f / 128.f) - mean * mean, 0.f);
        sMV[tid * 2] = mean;
        sMV[tid * 2 + 1] = rsqrtf(var + 1e-5f);
    }
    __syncthreads();
}

// One 32-k pipeline chunk of MMAs (both kernels share this shape).
__device__ __forceinline__ void mma_chunk32(uint32_t smb, int buf,
                                            uint32_t aoff0, uint32_t aoff1,
                                            uint32_t boff, int wn,
                                            float C[2][8][4]) {
#pragma unroll
    for (int ks = 0; ks < 2; ks++) {
        uint32_t Ah[2][4], Al[2][4];
        uint32_t abase = smb + OFF_A + buf * A_BUFSZ + ks * 32;
        ldmA(Ah[0], abase + aoff0);
        ldmA(Ah[1], abase + aoff1);
        ldmA(Al[0], abase + aoff0 + A_PLANE);
        ldmA(Al[1], abase + aoff1 + A_PLANE);
        uint32_t bbase = smb + OFF_B + buf * B_BUFSZ + boff + wn * 128 + ks * 4352;
#pragma unroll
        for (int i = 0; i < 4; i++) {
            uint32_t Bh[4], Bl[4];
            uint32_t ba = bbase + i * 32;
            ldmBT(Bh, ba);
            ldmBT(Bl, ba + B_PLANE);
#pragma unroll
            for (int mt = 0; mt < 2; mt++) {
                mma16816(C[mt][2 * i],     Ah[mt], Bh[0], Bh[1]);
                mma16816(C[mt][2 * i],     Ah[mt], Bl[0], Bl[1]);
                mma16816(C[mt][2 * i],     Al[mt], Bh[0], Bh[1]);
                mma16816(C[mt][2 * i + 1], Ah[mt], Bh[2], Bh[3]);
                mma16816(C[mt][2 * i + 1], Ah[mt], Bl[2], Bl[3]);
                mma16816(C[mt][2 * i + 1], Al[mt], Bh[2], Bh[3]);
            }
        }
    }
}

// GEMM2: A2 from SMEM image (row stride 272B), 4 chunks of 32 k.
__device__ __forceinline__ void mma2_chunk32(uint32_t smb, int buf, int cb,
                                             uint32_t a2r0, uint32_t a2r1,
                                             uint32_t boff, int wn,
                                             float C[2][8][4]) {
#pragma unroll
    for (int ks = 0; ks < 2; ks++) {
        uint32_t Ah[2][4], Al[2][4];
        uint32_t ao = (cb * 2 + ks) * 32;
        ldmA(Ah[0], a2r0 + ao);
        ldmA(Ah[1], a2r1 + ao);
        ldmA(Al[0], a2r0 + ao + A2_LO);
        ldmA(Al[1], a2r1 + ao + A2_LO);
        uint32_t bbase = smb + OFF_B + buf * B_BUFSZ + boff + wn * 128 + ks * 4352;
#pragma unroll
        for (int i = 0; i < 4; i++) {
            uint32_t Bh[4], Bl[4];
            uint32_t ba = bbase + i * 32;
            ldmBT(Bh, ba);
            ldmBT(Bl, ba + B_PLANE);
#pragma unroll
            for (int mt = 0; mt < 2; mt++) {
                mma16816(C[mt][2 * i],     Ah[mt], Bh[0], Bh[1]);
                mma16816(C[mt][2 * i],     Ah[mt], Bl[0], Bl[1]);
                mma16816(C[mt][2 * i],     Al[mt], Bh[0], Bh[1]);
                mma16816(C[mt][2 * i + 1], Ah[mt], Bh[2], Bh[3]);
                mma16816(C[mt][2 * i + 1], Ah[mt], Bl[2], Bl[3]);
                mma16816(C[mt][2 * i + 1], Al[mt], Bh[2], Bh[3]);
            }
        }
    }
}

// ------------------------------ msg_mma kernel -----------------------------
// 128 edges/block, 256 threads, warp tiling 4(M) x 2(N), 32-k pipeline chunks.
__global__ void __launch_bounds__(256, 2) msg_mma(
    const int* __restrict__ ei,
    const __nv_bfloat16* __restrict__ B1, const __nv_bfloat16* __restrict__ B2,
    const float* __restrict__ W1d,
    const float* __restrict__ b1, const float* __restrict__ g1, const float* __restrict__ be1,
    const float* __restrict__ b2, const float* __restrict__ g2, const float* __restrict__ be2) {
    extern __shared__ char sm[];
    uint32_t smb = smem_u32(sm);
    int tid = threadIdx.x;
    int w = tid >> 5, l = tid & 31;
    int wm = w & 3, wn = w >> 2;
    int rowbase = 32 * wm, colbase = 64 * wn;
    int e0 = blockIdx.x * 128;

    int* sDst = (int*)(sm + OFF_DST);
    int* sSrc = (int*)(sm + OFF_SRC);
    float* sDist = (float*)(sm + OFF_DIST);
    float* sPar = (float*)(sm + OFF_PAR);
    if (tid < 128) {
        sPar[tid]       = b1[tid];
        sPar[128 + tid] = g1[tid];
        sPar[256 + tid] = be1[tid];
        sPar[384 + tid] = b2[tid];
        sPar[512 + tid] = g2[tid];
        sPar[640 + tid] = be2[tid];
        sPar[768 + tid] = W1d[tid];
        int ec = min(e0 + tid, N_EDGES - 1);
        sSrc[tid] = ei[ec];
        sDst[tid] = ei[N_EDGES + ec];
        sDist[tid] = g_dist[ec];
    }
    __syncthreads();

    int rowS = tid >> 1, halfS = tid & 1;
    auto stageA = [&](int kc, int buf) {
        int node = (kc < 4 ? sDst : sSrc)[rowS];
        stageA_cp(smb, buf, rowS, halfS, g_hbf + (size_t)node * 256, kc & 3);
    };

    float C[2][8][4];
#pragma unroll
    for (int mt = 0; mt < 2; mt++)
#pragma unroll
        for (int nn = 0; nn < 8; nn++)
#pragma unroll
            for (int j = 0; j < 4; j++) C[mt][nn][j] = 0.f;

    stageA(0, 0);
    stageB32(smb, tid, B1, 0);
    CP_COMMIT();
    CP_WAIT0();
    __syncthreads();
    uint32_t aoff0 = (rowbase + (l & 15)) * 80 + (l >> 4) * 16;
    uint32_t aoff1 = aoff0 + 16 * 80;
    uint32_t boff = ((l & 7) + 8 * ((l >> 3) & 1)) * 272 + (l >> 4) * 16;

#pragma unroll 1
    for (int kc = 0; kc < 8; kc++) {
        int buf = kc & 1;
        if (kc + 1 < 8) {
            stageA(kc + 1, buf ^ 1);
            stageB32(smb, tid, B1 + (kc + 1) * 8192, buf ^ 1);
            CP_COMMIT();
        }
        mma_chunk32(smb, buf, aoff0, aoff1, boff, wn, C);
        CP_WAIT0();
        __syncthreads();
    }

    // ---- epilogue1: dist rank-1 + bias + LN + ReLU -> A2 SMEM image ----
    int rq = l >> 2, q2 = 2 * (l & 3);
    int R[4] = {rowbase + rq, rowbase + 8 + rq, rowbase + 16 + rq, rowbase + 24 + rq};
    float dR[4] = {sDist[R[0]], sDist[R[1]], sDist[R[2]], sDist[R[3]]};
#pragma unroll
    for (int mt = 0; mt < 2; mt++)
#pragma unroll
        for (int nn = 0; nn < 8; nn++) {
            int col = colbase + nn * 8 + q2;
            float wd0 = sPar[768 + col], wd1 = sPar[768 + col + 1];
            float bb0 = sPar[col], bb1 = sPar[col + 1];
            C[mt][nn][0] += dR[mt * 2] * wd0 + bb0;
            C[mt][nn][1] += dR[mt * 2] * wd1 + bb1;
            C[mt][nn][2] += dR[mt * 2 + 1] * wd0 + bb0;
            C[mt][nn][3] += dR[mt * 2 + 1] * wd1 + bb1;
        }
    ln_reduce(sm, C, R, l, wn, tid);
    {
        float* sMV = (float*)(sm + OFF_MV);
#pragma unroll
        for (int mt = 0; mt < 2; mt++)
#pragma unroll
            for (int nn = 0; nn < 8; nn++) {
                int col = colbase + nn * 8 + q2;
                float ga = sPar[128 + col], gb = sPar[128 + col + 1];
                float ba = sPar[256 + col], bb = sPar[256 + col + 1];
                int ra = R[mt * 2], rb = R[mt * 2 + 1];
                a2_write(sm, ra, col,
                    fmaxf(fmaf((C[mt][nn][0] - sMV[ra * 2]) * sMV[ra * 2 + 1], ga, ba), 0.f),
                    fmaxf(fmaf((C[mt][nn][1] - sMV[ra * 2]) * sMV[ra * 2 + 1], gb, bb), 0.f));
                a2_write(sm, rb, col,
                    fmaxf(fmaf((C[mt][nn][2] - sMV[rb * 2]) * sMV[rb * 2 + 1], ga, ba), 0.f),
                    fmaxf(fmaf((C[mt][nn][3] - sMV[rb * 2]) * sMV[rb * 2 + 1], gb, bb), 0.f));
            }
    }

    // ---- GEMM2: 4 chunks of 32 k, A2 from SMEM ----
    float (*C2)[8][4] = C;
#pragma unroll
    for (int mt = 0; mt < 2; mt++)
#pragma unroll
        for (int nn = 0; nn < 8; nn++)
#pragma unroll
            for (int j = 0; j < 4; j++) C2[mt][nn][j] = 0.f;

    stageB32(smb, tid, B2, 0);
    CP_COMMIT();
    CP_WAIT0();
    __syncthreads();
    uint32_t a2r0 = smb + OFF_A2 + (rowbase + (l & 15)) * 272 + (l >> 4) * 16;
    uint32_t a2r1 = a2r0 + 16 * 272;
#pragma unroll
    for (int cb = 0; cb < 4; cb++) {
        int buf = cb & 1;
        if (cb + 1 < 4) { stageB32(smb, tid, B2 + (cb + 1) * 8192, buf ^ 1); CP_COMMIT(); }
        mma2_chunk32(smb, buf, cb, a2r0, a2r1, boff, wn, C2);
        CP_WAIT0();
        __syncthreads();
    }

    // ---- epilogue2: bias + LN + ReLU -> sOut -> red.v4 scatter ----
#pragma unroll
    for (int mt = 0; mt < 2; mt++)
#pragma unroll
        for (int nn = 0; nn < 8; nn++) {
            int col = colbase + nn * 8 + q2;
            float bb0 = sPar[384 + col], bb1 = sPar[384 + col + 1];
            C2[mt][nn][0] += bb0; C2[mt][nn][1] += bb1;
            C2[mt][nn][2] += bb0; C2[mt][nn][3] += bb1;
        }
    ln_reduce(sm, C2, R, l, wn, tid);
    {
        float* sMV = (float*)(sm + OFF_MV);
        float* sOut = (float*)(sm + OFF_OUT);
#pragma unroll
        for (int mt = 0; mt < 2; mt++)
#pragma unroll
            for (int nn = 0; nn < 8; nn++) {
                int col = colbase + nn * 8 + q2;
                float ga = sPar[512 + col], gb = sPar[512 + col + 1];
                float ba = sPar[640 + col], bb = sPar[640 + col + 1];
                int ra = R[mt * 2], rb = R[mt * 2 + 1];
                float v0 = fmaxf(fmaf((C2[mt][nn][0] - sMV[ra * 2]) * sMV[ra * 2 + 1], ga, ba), 0.f);
                float v1 = fmaxf(fmaf((C2[mt][nn][1] - sMV[ra * 2]) * sMV[ra * 2 + 1], gb, bb), 0.f);
                float v2 = fmaxf(fmaf((C2[mt][nn][2] - sMV[rb * 2]) * sMV[rb * 2 + 1], ga, ba), 0.f);
                float v3 = fmaxf(fmaf((C2[mt][nn][3] - sMV[rb * 2]) * sMV[rb * 2 + 1], gb, bb), 0.f);
                *(float2*)&sOut[ra * 132 + col] = make_float2(v0, v1);
                *(float2*)&sOut[rb * 132 + col] = make_float2(v2, v3);
            }
    }
    __syncthreads();

    {
        int c4 = (tid & 31) * 4;
        int rg = tid >> 5;
        float* sOut = (float*)(sm + OFF_OUT);
#pragma unroll 4
        for (int i = 0; i < 16; i++) {
            int row = i * 8 + rg;
            if (e0 + row < N_EDGES) {
                float4 v = *(float4*)&sOut[row * 132 + c4];
                red4(&g_agg[(size_t)sDst[row] * HID + c4], v);
            }
        }
    }
}

// ------------------------------ upd_mma kernel -----------------------------
__global__ void __launch_bounds__(256, 2) upd_mma(
    const __nv_bfloat16* __restrict__ B1, const __nv_bfloat16* __restrict__ B2,
    const float* __restrict__ b1, const float* __restrict__ g1, const float* __restrict__ be1,
    const float* __restrict__ b2, const float* __restrict__ g2, const float* __restrict__ be2) {
    extern __shared__ char sm[];
    uint32_t smb = smem_u32(sm);
    int tid = threadIdx.x;
    int w = tid >> 5, l = tid & 31;
    int wm = w & 3, wn = w >> 2;
    int rowbase = 32 * wm, colbase = 64 * wn;
    int n0 = blockIdx.x * 128;

    float* sPar = (float*)(sm + OFF_PAR);
    if (tid < 128) {
        sPar[tid]       = b1[tid];
        sPar[128 + tid] = g1[tid];
        sPar[256 + tid] = be1[tid];
        sPar[384 + tid] = b2[tid];
        sPar[512 + tid] = g2[tid];
        sPar[640 + tid] = be2[tid];
    }
    __syncthreads();

    int rowS = tid >> 1, halfS = tid & 1;
    int nodeS = min(n0 + rowS, N_NODES - 1);
    auto stageA = [&](int kc, int buf) {
        const __nv_bfloat16* base = (kc < 4) ? g_hbf : g_aggbf;
        stageA_cp(smb, buf, rowS, halfS, base + (size_t)nodeS * 256, kc & 3);
    };

    float C[2][8][4];
#pragma unroll
    for (int mt = 0; mt < 2; mt++)
#pragma unroll
        for (int nn = 0; nn < 8; nn++)
#pragma unroll
            for (int j = 0; j < 4; j++) C[mt][nn][j] = 0.f;

    stageA(0, 0);
    stageB32(smb, tid, B1, 0);
    CP_COMMIT();
    CP_WAIT0();
    __syncthreads();
    uint32_t aoff0 = (rowbase + (l & 15)) * 80 + (l >> 4) * 16;
    uint32_t aoff1 = aoff0 + 16 * 80;
    uint32_t boff = ((l & 7) + 8 * ((l >> 3) & 1)) * 272 + (l >> 4) * 16;

#pragma unroll 1
    for (int kc = 0; kc < 8; kc++) {
        int buf = kc & 1;
        if (kc + 1 < 8) {
            stageA(kc + 1, buf ^ 1);
            stageB32(smb, tid, B1 + (kc + 1) * 8192, buf ^ 1);
            CP_COMMIT();
        }
        mma_chunk32(smb, buf, aoff0, aoff1, boff, wn, C);
        CP_WAIT0();
        __syncthreads();
    }

    // ---- epilogue1: bias + LN + ReLU -> A2 ----
    int rq = l >> 2, q2 = 2 * (l & 3);
    int R[4] = {rowbase + rq, rowbase + 8 + rq, rowbase + 16 + rq, rowbase + 24 + rq};
#pragma unroll
    for (int mt = 0; mt < 2; mt++)
#pragma unroll
        for (int nn = 0; nn < 8; nn++) {
            int col = colbase + nn * 8 + q2;
            float bb0 = sPar[col], bb1 = sPar[col + 1];
            C[mt][nn][0] += bb0; C[mt][nn][1] += bb1;
            C[mt][nn][2] += bb0; C[mt][nn][3] += bb1;
        }
    ln_reduce(sm, C, R, l, wn, tid);
    {
        float* sMV = (float*)(sm + OFF_MV);
#pragma unroll
        for (int mt = 0; mt < 2; mt++)
#pragma unroll
            for (int nn = 0; nn < 8; nn++) {
                int col = colbase + nn * 8 + q2;
                float ga = sPar[128 + col], gb = sPar[128 + col + 1];
                float ba = sPar[256 + col], bb = sPar[256 + col + 1];
                int ra = R[mt * 2], rb = R[mt * 2 + 1];
                a2_write(sm, ra, col,
                    fmaxf(fmaf((C[mt][nn][0] - sMV[ra * 2]) * sMV[ra * 2 + 1], ga, ba), 0.f),
                    fmaxf(fmaf((C[mt][nn][1] - sMV[ra * 2]) * sMV[ra * 2 + 1], gb, bb), 0.f));
                a2_write(sm, rb, col,
                    fmaxf(fmaf((C[mt][nn][2] - sMV[rb * 2]) * sMV[rb * 2 + 1], ga, ba), 0.f),
                    fmaxf(fmaf((C[mt][nn][3] - sMV[rb * 2]) * sMV[rb * 2 + 1], gb, bb), 0.f));
            }
    }

    // ---- GEMM2 ----
    float (*C2)[8][4] = C;
#pragma unroll
    for (int mt = 0; mt < 2; mt++)
#pragma unroll
        for (int nn = 0; nn < 8; nn++)
#pragma unroll
            for (int j = 0; j < 4; j++) C2[mt][nn][j] = 0.f;

    stageB32(smb, tid, B2, 0);
    CP_COMMIT();
    CP_WAIT0();
    __syncthreads();
    uint32_t a2r0 = smb + OFF_A2 + (rowbase + (l & 15)) * 272 + (l >> 4) * 16;
    uint32_t a2r1 = a2r0 + 16 * 272;
#pragma unroll
    for (int cb = 0; cb < 4; cb++) {
        int buf = cb & 1;
        if (cb + 1 < 4) { stageB32(smb, tid, B2 + (cb + 1) * 8192, buf ^ 1); CP_COMMIT(); }
        mma2_chunk32(smb, buf, cb, a2r0, a2r1, boff, wn, C2);
        CP_WAIT0();
        __syncthreads();
    }

    // ---- epilogue2: bias + LN + ReLU + residual -> g_h ----
#pragma unroll
    for (int mt = 0; mt < 2; mt++)
#pragma unroll
        for (int nn = 0; nn < 8; nn++) {
            int col = colbase + nn * 8 + q2;
            float bb0 = sPar[384 + col], bb1 = sPar[384 + col + 1];
            C2[mt][nn][0] += bb0; C2[mt][nn][1] += bb1;
            C2[mt][nn][2] += bb0; C2[mt][nn][3] += bb1;
        }
    ln_reduce(sm, C2, R, l, wn, tid);
    {
        float* sMV = (float*)(sm + OFF_MV);
#pragma unroll
        for (int mt = 0; mt < 2; mt++)
#pragma unroll
            for (int nn = 0; nn < 8; nn++) {
                int col = colbase + nn * 8 + q2;
                float ga = sPar[512 + col], gb = sPar[512 + col + 1];
                float ba = sPar[640 + col], bb = sPar[640 + col + 1];
                int ra = R[mt * 2], rb = R[mt * 2 + 1];
                int na = n0 + ra, nb = n0 + rb;
                if (na < N_NODES) {
                    float v0 = fmaxf(fmaf((C2[mt][nn][0] - sMV[ra * 2]) * sMV[ra * 2 + 1], ga, ba), 0.f);
                    float v1 = fmaxf(fmaf((C2[mt][nn][1] - sMV[ra * 2]) * sMV[ra * 2 + 1], gb, bb), 0.f);
                    float2 old = *(float2*)&g_h[(size_t)na * HID + col];
                    *(float2*)&g_h[(size_t)na * HID + col] = make_float2(old.x + v0, old.y + v1);
                }
                if (nb < N_NODES) {
                    float v2 = fmaxf(fmaf((C2[mt][nn][2] - sMV[rb * 2]) * sMV[rb * 2 + 1], ga, ba), 0.f);
                    float v3 = fmaxf(fmaf((C2[mt][nn][3] - sMV[rb * 2]) * sMV[rb * 2 + 1], gb, bb), 0.f);
                    float2 old = *(float2*)&g_h[(size_t)nb * HID + col];
                    *(float2*)&g_h[(size_t)nb * HID + col] = make_float2(old.x + v2, old.y + v3);
                }
            }
    }
}

// ------------------------------ pool / pred --------------------------------
__global__ void pool_kernel(const int* __restrict__ batch) {
    int idx = blockIdx.x * blockDim.x + threadIdx.x;
    int node = idx >> 5;
    if (node >= N_NODES) return;
    int c4 = (idx & 31) * 4;
    float4 v = *(const float4*)&g_h[(size_t)node * HID + c4];
    red4(&g_pool[(size_t)batch[node] * HID + c4], v);
}

__global__ void pred_kernel(const float* __restrict__ W1, const float* __restrict__ b1,
                            const float* __restrict__ W2, const float* __restrict__ b2,
                            float* __restrict__ out) {
    __shared__ float sred[128];
    int g = blockIdx.x;
    int t = threadIdx.x;
    float acc = b1[t];
    for (int k = 0; k < HID; k++)
        acc = fmaf(g_pool[g * HID + k], W1[k * HID + t], acc);
    acc = fmaxf(acc, 0.f) * W2[t];
    sred[t] = acc;
    __syncthreads();
    for (int o = 64; o > 0; o >>= 1) {
        if (t < o) sred[t] += sred[t + o];
        __syncthreads();
    }
    if (t == 0) out[g] = sred[0] + b2[0];
}

// ------------------------------ launch -------------------------------------
extern "C" void kernel_launch(void* const* d_in, const int* in_sizes, int n_in,
                              void* d_out, int out_size) {
    const float* x     = (const float*)d_in[0];
    const float* pos   = (const float*)d_in[1];
    const int*   ei    = (const int*)d_in[2];
    const int*   batch = (const int*)d_in[3];
    const float* emb_W = (const float*)d_in[4];
    const float* emb_b = (const float*)d_in[5];

    const float *mW1, *mb1, *mg1, *mbe1, *mW2, *mb2, *mg2, *mbe2;
    const float *uW1, *ub1, *ug1, *ube1, *uW2, *ub2, *ug2, *ube2;

    if (in_sizes[8] == 81920) {
        mW1  = (const float*)d_in[6];  mb1  = (const float*)d_in[7];
        mW2  = (const float*)d_in[8];  mb2  = (const float*)d_in[9];
        uW1  = (const float*)d_in[10]; ub1  = (const float*)d_in[11];
        uW2  = (const float*)d_in[12]; ub2  = (const float*)d_in[13];
        mg1  = (const float*)d_in[14]; mbe1 = (const float*)d_in[15];
        mg2  = (const float*)d_in[16]; mbe2 = (const float*)d_in[17];
        ug1  = (const float*)d_in[18]; ube1 = (const float*)d_in[19];
        ug2  = (const float*)d_in[20]; ube2 = (const float*)d_in[21];
    } else {
        mW1  = (const float*)d_in[6];  mb1  = (const float*)d_in[7];
        mg1  = (const float*)d_in[8];  mbe1 = (const float*)d_in[9];
        mW2  = (const float*)d_in[10]; mb2  = (const float*)d_in[11];
        mg2  = (const float*)d_in[12]; mbe2 = (const float*)d_in[13];
        uW1  = (const float*)d_in[14]; ub1  = (const float*)d_in[15];
        ug1  = (const float*)d_in[16]; ube1 = (const float*)d_in[17];
        uW2  = (const float*)d_in[18]; ub2  = (const float*)d_in[19];
        ug2  = (const float*)d_in[20]; ube2 = (const float*)d_in[21];
    }
    const float* pW1 = (const float*)d_in[22];
    const float* pb1 = (const float*)d_in[23];
    const float* pW2 = (const float*)d_in[24];
    const float* pb2 = (const float*)d_in[25];
    float* out = (float*)d_out;

    __nv_bfloat16 *bm1, *bm2, *bu1, *bu2, *hbf, *aggbf;
    float *gh, *gagg;
    cudaGetSymbolAddress((void**)&bm1, g_B1);
    cudaGetSymbolAddress((void**)&bm2, g_B2);
    cudaGetSymbolAddress((void**)&bu1, g_BU1);
    cudaGetSymbolAddress((void**)&bu2, g_BU2);
    cudaGetSymbolAddress((void**)&hbf, g_hbf);
    cudaGetSymbolAddress((void**)&aggbf, g_aggbf);
    cudaGetSymbolAddress((void**)&gh, g_h);
    cudaGetSymbolAddress((void**)&gagg, g_agg);

    cudaFuncSetAttribute(msg_mma, cudaFuncAttributeMaxDynamicSharedMemorySize, SMEM_MSG);
    cudaFuncSetAttribute(upd_mma, cudaFuncAttributeMaxDynamicSharedMemorySize, SMEM_MSG);

    pack_all<<<(2 * (PK16 + PK8) + 255) / 256, 256>>>(mW1, mW2, uW1, uW2,
                                                      bm1, bm2, bu1, bu2);
    dist_kernel<<<(N_EDGES + 255) / 256, 256>>>(pos, ei);
    embed_kernel<<<N_NODES, 128>>>(x, emb_W, emb_b);
    zero_pool_kernel<<<(N_GRAPHS * HID + 255) / 256, 256>>>();

    int msg_blocks = (N_EDGES + 127) / 128;
    int upd_blocks = (N_NODES + 127) / 128;
    int conv_blocks = (N_NODES * HID + 255) / 256;
    for (int l = 0; l < DEPTH; l++) {
        tobf_kernel<<<conv_blocks, 256>>>(gh, hbf, gagg);  // also zeroes g_agg
        msg_mma<<<msg_blocks, 256, SMEM_MSG>>>(
            ei,
            bm1 + l * 16 * 4096, bm2 + l * 8 * 4096,
            mW1 + l * 257 * HID + 256 * HID,
            mb1 + l * HID, mg1 + l * HID, mbe1 + l * HID,
            mb2 + l * HID, mg2 + l * HID, mbe2 + l * HID);
        tobf_kernel<<<conv_blocks, 256>>>(gagg, aggbf, nullptr);
        upd_mma<<<upd_blocks, 256, SMEM_MSG>>>(
            bu1 + l * 16 * 4096, bu2 + l * 8 * 4096,
            ub1 + l * HID, ug1 + l * HID, ube1 + l * HID,
            ub2 + l * HID, ug2 + l * HID, ube2 + l * HID);
    }

    pool_kernel<<<(N_NODES * 32 + 127) / 128, 128>>>(batch);
    pred_kernel<<<N_GRAPHS, 128>>>(pW1, pb1, pW2, pb2, out);
}